// round 1
// baseline (speedup 1.0000x reference)
#include <cuda_runtime.h>
#include <cuda_bf16.h>
#include <cstdint>

#define NU_MAX 200000
#define NI_MAX 20000
#define NE_MAX 1000000

// ---------------- scratch (device globals; no allocation allowed) -------------
__device__ float  g_user_x[NU_MAX * 32];
__device__ float  g_item_x[NI_MAX * 32];
__device__ float  g_xl1[NU_MAX * 128];
__device__ float  g_xr1[NI_MAX * 128];
__device__ float  g_xr2[NU_MAX * 128];
__device__ float  g_item2[NI_MAX * 128];
__device__ float  g_xl2[NI_MAX * 128];
__device__ float  g_hid[NU_MAX * 128];
__device__ float4 g_logits[NE_MAX];
__device__ int    g_cnt1[NI_MAX];
__device__ int    g_off1[NI_MAX];
__device__ int    g_cur1[NI_MAX];
__device__ int    g_eidx1[NE_MAX];
__device__ int    g_cnt2[NU_MAX];
__device__ int    g_off2[NU_MAX];
__device__ int    g_cur2[NU_MAX];
__device__ int    g_eidx2[NE_MAX];

// ---------------- generic tiled fp32 GEMM: out[N, NOUT] = in[N,K] @ W[K,NOUT] + b
// thread mapping: cg = tid/RG (warp-uniform -> W LDS broadcast),
// rows interleaved by RG with odd smem pitch KP -> conflict-free x LDS.
template<int K, int NOUT, int CPT, int RPT>
__global__ void __launch_bounds__(256, 1) gemm_kernel(
    const float* __restrict__ in, const float* __restrict__ W,
    const float* __restrict__ bias, float* __restrict__ out,
    int nrows, int do_relu)
{
    constexpr int CG = NOUT / CPT;       // 4
    constexpr int RG = 256 / CG;         // 64
    constexpr int RB = RG * RPT;         // rows per block
    constexpr int KP = (K & 1) ? K : (K + 1);

    extern __shared__ float sm[];
    float* s_in = sm;                    // RB * KP
    float* s_w  = sm + RB * KP;          // K * NOUT
    __shared__ float s_b[NOUT];

    const int tid = threadIdx.x;
    const int rowbase = blockIdx.x * RB;

    for (int i = tid; i < K * NOUT; i += 256) s_w[i] = W[i];
    if (tid < NOUT) s_b[tid] = bias[tid];

    int nrow_blk = nrows - rowbase; if (nrow_blk > RB) nrow_blk = RB;
    const float* gin = in + (size_t)rowbase * K;
    for (int i = tid; i < nrow_blk * K; i += 256) {
        int r = i / K;
        int k = i - r * K;
        s_in[r * KP + k] = gin[i];
    }
    __syncthreads();

    const int cg = tid / RG;
    const int rg = tid - cg * RG;

    float acc[RPT][CPT];
#pragma unroll
    for (int j = 0; j < RPT; j++)
#pragma unroll
        for (int c = 0; c < CPT; c++) acc[j][c] = 0.f;

    const float* wbase = s_w + cg * CPT;
    const float* xbase = s_in + rg * KP;

    for (int k = 0; k < K; k++) {
        float xv[RPT];
#pragma unroll
        for (int j = 0; j < RPT; j++) xv[j] = xbase[j * RG * KP + k];
#pragma unroll
        for (int c = 0; c < CPT; c++) {
            float wv = wbase[k * NOUT + c];
#pragma unroll
            for (int j = 0; j < RPT; j++) acc[j][c] = fmaf(xv[j], wv, acc[j][c]);
        }
    }

#pragma unroll
    for (int j = 0; j < RPT; j++) {
        int row = rowbase + rg + j * RG;
        if (row < nrows) {
            float* orow = out + (size_t)row * NOUT + cg * CPT;
#pragma unroll
            for (int c = 0; c < CPT; c++) {
                float v = acc[j][c] + s_b[cg * CPT + c];
                if (do_relu) v = fmaxf(v, 0.f);
                orow[c] = v;
            }
        }
    }
}

// ---------------- trivial item linear: [Ni,1] @ [1,32] + b
__global__ void item_lin_kernel(const float* __restrict__ fx, const float* __restrict__ w,
                                const float* __restrict__ b, float* __restrict__ out, int ni)
{
    int i = blockIdx.x * blockDim.x + threadIdx.x;
    if (i < ni * 32) {
        int r = i >> 5, c = i & 31;
        out[i] = fmaf(fx[r], w[c], b[c]);
    }
}

// ---------------- CSR build ----------------
__global__ void count_kernel(const int* __restrict__ src, const int* __restrict__ dst,
                             int* __restrict__ c1, int* __restrict__ c2, int E)
{
    int i = blockIdx.x * blockDim.x + threadIdx.x;
    if (i < E) {
        atomicAdd(&c1[dst[i]], 1);
        atomicAdd(&c2[src[i]], 1);
    }
}

__global__ void scan_kernel(const int* __restrict__ cnt, int* __restrict__ off,
                            int* __restrict__ cur, int n)
{
    __shared__ int wsum[32];
    __shared__ int carry;
    int tid = threadIdx.x;
    if (tid == 0) carry = 0;
    __syncthreads();
    for (int base = 0; base < n; base += 1024) {
        int i = base + tid;
        int v = (i < n) ? cnt[i] : 0;
        int x = v;
#pragma unroll
        for (int d = 1; d < 32; d <<= 1) {
            int y = __shfl_up_sync(0xffffffffu, x, d);
            if ((tid & 31) >= d) x += y;
        }
        if ((tid & 31) == 31) wsum[tid >> 5] = x;
        __syncthreads();
        if (tid < 32) {
            int w = wsum[tid];
#pragma unroll
            for (int d = 1; d < 32; d <<= 1) {
                int y = __shfl_up_sync(0xffffffffu, w, d);
                if (tid >= d) w += y;
            }
            wsum[tid] = w;
        }
        __syncthreads();
        int wo = (tid >= 32) ? wsum[(tid >> 5) - 1] : 0;
        int excl = carry + wo + x - v;
        if (i < n) { off[i] = excl; cur[i] = excl; }
        __syncthreads();
        if (tid == 0) carry += wsum[31];
        __syncthreads();
    }
}

__global__ void scatter_kernel(const int* __restrict__ src, const int* __restrict__ dst,
                               int* __restrict__ cur1, int* __restrict__ cur2,
                               int* __restrict__ e1, int* __restrict__ e2, int E)
{
    int i = blockIdx.x * blockDim.x + threadIdx.x;
    if (i < E) {
        e1[atomicAdd(&cur1[dst[i]], 1)] = i;
        e2[atomicAdd(&cur2[src[i]], 1)] = i;
    }
}

// ---------------- edge logits: warp per edge ----------------
// logit[e,h] = sum_c leaky( xl[srcIdx[e],h*32+c] + xr[dstIdx[e],h*32+c] + eattr[e,:]@we[:,h*32+c] ) * att[h,c]
__global__ void logits_kernel(const float* __restrict__ xl, const float* __restrict__ xr,
                              const int* __restrict__ srcIdx, const int* __restrict__ dstIdx,
                              const float* __restrict__ eattr, const float* __restrict__ we,
                              const float* __restrict__ att, float4* __restrict__ logits, int E)
{
    const int lane = threadIdx.x & 31;
    const int warp = (blockIdx.x * blockDim.x + threadIdx.x) >> 5;
    const int nwarp = (gridDim.x * blockDim.x) >> 5;

    float attv[4], we0[4], we1[4], we2[4];
#pragma unroll
    for (int h = 0; h < 4; h++) {
        int c = h * 32 + lane;
        attv[h] = att[c];
        if (we) { we0[h] = we[c]; we1[h] = we[128 + c]; we2[h] = we[256 + c]; }
        else    { we0[h] = we1[h] = we2[h] = 0.f; }
    }

    for (int e = warp; e < E; e += nwarp) {
        int s = __ldg(srcIdx + e);
        int d = __ldg(dstIdx + e);
        float a0 = 0.f, a1 = 0.f, a2 = 0.f;
        if (eattr) {
            a0 = __ldg(eattr + (size_t)e * 3);
            a1 = __ldg(eattr + (size_t)e * 3 + 1);
            a2 = __ldg(eattr + (size_t)e * 3 + 2);
        }
        const float* xls = xl + (size_t)s * 128;
        const float* xrd = xr + (size_t)d * 128;
        float lg[4];
#pragma unroll
        for (int h = 0; h < 4; h++) {
            int c = h * 32 + lane;
            float m = xls[c] + xrd[c];
            m = fmaf(a0, we0[h], m);
            m = fmaf(a1, we1[h], m);
            m = fmaf(a2, we2[h], m);
            float g = fmaxf(m, 0.2f * m);   // leaky_relu, slope 0.2
            lg[h] = g * attv[h];
        }
#pragma unroll
        for (int off = 16; off; off >>= 1) {
#pragma unroll
            for (int h = 0; h < 4; h++) lg[h] += __shfl_xor_sync(0xffffffffu, lg[h], off);
        }
        if (lane == 0) logits[e] = make_float4(lg[0], lg[1], lg[2], lg[3]);
    }
}

// ---------------- per-node softmax + weighted aggregation: warp per node -------
__global__ void node_agg_kernel(const float* __restrict__ xl, const float4* __restrict__ logits,
                                const int* __restrict__ off, const int* __restrict__ cnt,
                                const int* __restrict__ eidx, const int* __restrict__ srcarr,
                                const float* __restrict__ bias, float* __restrict__ out,
                                int n, int do_relu)
{
    const int lane = threadIdx.x & 31;
    const int node = (blockIdx.x * blockDim.x + threadIdx.x) >> 5;
    if (node >= n) return;

    const int start = off[node];
    const int m = cnt[node];
    const float NEGINF = __int_as_float(0xff800000u);

    float mx0 = NEGINF, mx1 = NEGINF, mx2 = NEGINF, mx3 = NEGINF;
    for (int i = lane; i < m; i += 32) {
        float4 lg = logits[eidx[start + i]];
        mx0 = fmaxf(mx0, lg.x); mx1 = fmaxf(mx1, lg.y);
        mx2 = fmaxf(mx2, lg.z); mx3 = fmaxf(mx3, lg.w);
    }
#pragma unroll
    for (int o = 16; o; o >>= 1) {
        mx0 = fmaxf(mx0, __shfl_xor_sync(0xffffffffu, mx0, o));
        mx1 = fmaxf(mx1, __shfl_xor_sync(0xffffffffu, mx1, o));
        mx2 = fmaxf(mx2, __shfl_xor_sync(0xffffffffu, mx2, o));
        mx3 = fmaxf(mx3, __shfl_xor_sync(0xffffffffu, mx3, o));
    }

    float s0 = 0.f, s1 = 0.f, s2 = 0.f, s3 = 0.f;
    for (int i = lane; i < m; i += 32) {
        float4 lg = logits[eidx[start + i]];
        s0 += __expf(lg.x - mx0); s1 += __expf(lg.y - mx1);
        s2 += __expf(lg.z - mx2); s3 += __expf(lg.w - mx3);
    }
#pragma unroll
    for (int o = 16; o; o >>= 1) {
        s0 += __shfl_xor_sync(0xffffffffu, s0, o);
        s1 += __shfl_xor_sync(0xffffffffu, s1, o);
        s2 += __shfl_xor_sync(0xffffffffu, s2, o);
        s3 += __shfl_xor_sync(0xffffffffu, s3, o);
    }
    const float i0 = 1.f / (s0 + 1e-16f);
    const float i1 = 1.f / (s1 + 1e-16f);
    const float i2 = 1.f / (s2 + 1e-16f);
    const float i3 = 1.f / (s3 + 1e-16f);

    float a0 = 0.f, a1 = 0.f, a2 = 0.f, a3 = 0.f;
    for (int i = 0; i < m; i++) {
        int e = eidx[start + i];
        int s = srcarr[e];
        float4 lg = logits[e];
        const float* row = xl + (size_t)s * 128;
        a0 = fmaf(__expf(lg.x - mx0) * i0, row[lane],      a0);
        a1 = fmaf(__expf(lg.y - mx1) * i1, row[32 + lane], a1);
        a2 = fmaf(__expf(lg.z - mx2) * i2, row[64 + lane], a2);
        a3 = fmaf(__expf(lg.w - mx3) * i3, row[96 + lane], a3);
    }

    float o0 = a0 + bias[lane];
    float o1 = a1 + bias[32 + lane];
    float o2 = a2 + bias[64 + lane];
    float o3 = a3 + bias[96 + lane];
    if (do_relu) {
        o0 = fmaxf(o0, 0.f); o1 = fmaxf(o1, 0.f);
        o2 = fmaxf(o2, 0.f); o3 = fmaxf(o3, 0.f);
    }
    float* orow = out + (size_t)node * 128;
    orow[lane] = o0; orow[32 + lane] = o1; orow[64 + lane] = o2; orow[96 + lane] = o3;
}

// ---------------- host launch ----------------
extern "C" void kernel_launch(void* const* d_in, const int* in_sizes, int n_in,
                              void* d_out, int out_size)
{
    (void)n_in; (void)out_size;
    const float* customer_x = (const float*)d_in[0];
    const float* fund_x     = (const float*)d_in[1];
    const float* edge_attr  = (const float*)d_in[2];
    const float* user_lin_w = (const float*)d_in[3];
    const float* user_lin_b = (const float*)d_in[4];
    const float* item_lin_w = (const float*)d_in[5];
    const float* item_lin_b = (const float*)d_in[6];
    const float* conv1_wl   = (const float*)d_in[7];
    const float* conv1_bl   = (const float*)d_in[8];
    const float* conv1_wr   = (const float*)d_in[9];
    const float* conv1_br   = (const float*)d_in[10];
    const float* conv1_we   = (const float*)d_in[11];
    const float* conv1_att  = (const float*)d_in[12];
    const float* conv1_bias = (const float*)d_in[13];
    const float* conv2_wl   = (const float*)d_in[14];
    const float* conv2_bl   = (const float*)d_in[15];
    const float* conv2_wr   = (const float*)d_in[16];
    const float* conv2_br   = (const float*)d_in[17];
    const float* conv2_att  = (const float*)d_in[18];
    const float* conv2_bias = (const float*)d_in[19];
    const float* proj_w1    = (const float*)d_in[20];
    const float* proj_b1    = (const float*)d_in[21];
    const float* proj_w2    = (const float*)d_in[22];
    const float* proj_b2    = (const float*)d_in[23];
    const int*   edge_src   = (const int*)d_in[24];
    const int*   edge_dst   = (const int*)d_in[25];

    const int Nu = in_sizes[0] / 101;
    const int Ni = in_sizes[1];
    const int E  = in_sizes[24];

    float *user_x, *item_x, *xl1, *xr1, *xr2, *item2, *xl2, *hid;
    float4* logits;
    int *cnt1, *off1, *cur1, *eidx1, *cnt2, *off2, *cur2, *eidx2;
    cudaGetSymbolAddress((void**)&user_x, g_user_x);
    cudaGetSymbolAddress((void**)&item_x, g_item_x);
    cudaGetSymbolAddress((void**)&xl1,    g_xl1);
    cudaGetSymbolAddress((void**)&xr1,    g_xr1);
    cudaGetSymbolAddress((void**)&xr2,    g_xr2);
    cudaGetSymbolAddress((void**)&item2,  g_item2);
    cudaGetSymbolAddress((void**)&xl2,    g_xl2);
    cudaGetSymbolAddress((void**)&hid,    g_hid);
    cudaGetSymbolAddress((void**)&logits, g_logits);
    cudaGetSymbolAddress((void**)&cnt1,   g_cnt1);
    cudaGetSymbolAddress((void**)&off1,   g_off1);
    cudaGetSymbolAddress((void**)&cur1,   g_cur1);
    cudaGetSymbolAddress((void**)&eidx1,  g_eidx1);
    cudaGetSymbolAddress((void**)&cnt2,   g_cnt2);
    cudaGetSymbolAddress((void**)&off2,   g_off2);
    cudaGetSymbolAddress((void**)&cur2,   g_cur2);
    cudaGetSymbolAddress((void**)&eidx2,  g_eidx2);

    // dynamic smem sizes (match template internals)
    const int smemUser   = (128 * 101 + 101 * 32) * 4;   // K=101,RPT=2
    const int smemG32    = (128 * 33  + 32 * 128) * 4;   // K=32, RPT=2
    const int smemG128   = (256 * 129 + 128 * 128) * 4;  // K=128,RPT=4
    cudaFuncSetAttribute(gemm_kernel<101, 32, 8, 2>,  cudaFuncAttributeMaxDynamicSharedMemorySize, smemUser);
    cudaFuncSetAttribute(gemm_kernel<32, 128, 32, 2>, cudaFuncAttributeMaxDynamicSharedMemorySize, smemG32);
    cudaFuncSetAttribute(gemm_kernel<128, 128, 32, 4>,cudaFuncAttributeMaxDynamicSharedMemorySize, smemG128);

    float* user_out = (float*)d_out;             // [Nu,128]
    float* z        = user_out + (size_t)Nu * 128;

    // ---- CSR build (both directions) ----
    cudaMemsetAsync(cnt1, 0, Ni * sizeof(int));
    cudaMemsetAsync(cnt2, 0, Nu * sizeof(int));
    count_kernel<<<(E + 255) / 256, 256>>>(edge_src, edge_dst, cnt1, cnt2, E);
    scan_kernel<<<1, 1024>>>(cnt1, off1, cur1, Ni);
    scan_kernel<<<1, 1024>>>(cnt2, off2, cur2, Nu);
    scatter_kernel<<<(E + 255) / 256, 256>>>(edge_src, edge_dst, cur1, cur2, eidx1, eidx2, E);

    // ---- input linears ----
    gemm_kernel<101, 32, 8, 2><<<(Nu + 127) / 128, 256, smemUser>>>(customer_x, user_lin_w, user_lin_b, user_x, Nu, 0);
    item_lin_kernel<<<(Ni * 32 + 255) / 256, 256>>>(fund_x, item_lin_w, item_lin_b, item_x, Ni);

    // ---- conv1 / conv2 projections ----
    gemm_kernel<32, 128, 32, 2><<<(Nu + 127) / 128, 256, smemG32>>>(user_x, conv1_wl, conv1_bl, xl1, Nu, 0);
    gemm_kernel<32, 128, 32, 2><<<(Nu + 127) / 128, 256, smemG32>>>(user_x, conv2_wr, conv2_br, xr2, Nu, 0);
    gemm_kernel<32, 128, 32, 2><<<(Ni + 127) / 128, 256, smemG32>>>(item_x, conv1_wr, conv1_br, xr1, Ni, 0);

    // ---- conv1: user -> item ----
    logits_kernel<<<2048, 256>>>(xl1, xr1, edge_src, edge_dst, edge_attr, conv1_we, conv1_att, logits, E);
    node_agg_kernel<<<(Ni * 32 + 255) / 256, 256>>>(xl1, logits, off1, cnt1, eidx1, edge_src, conv1_bias, item2, Ni, 1);

    // ---- conv2: item -> user (flipped edges) ----
    gemm_kernel<128, 128, 32, 4><<<(Ni + 255) / 256, 256, smemG128>>>(item2, conv2_wl, conv2_bl, xl2, Ni, 0);
    logits_kernel<<<2048, 256>>>(xl2, xr2, edge_dst, edge_src, nullptr, nullptr, conv2_att, logits, E);
    node_agg_kernel<<<(Nu * 32 + 255) / 256, 256>>>(xl2, logits, off2, cnt2, eidx2, edge_dst, conv2_bias, user_out, Nu, 0);

    // ---- final MLP: z = relu(user_out@W1+b1)@W2+b2 ----
    gemm_kernel<128, 128, 32, 4><<<(Nu + 255) / 256, 256, smemG128>>>(user_out, proj_w1, proj_b1, hid, Nu, 1);
    gemm_kernel<128, 128, 32, 4><<<(Nu + 255) / 256, 256, smemG128>>>(hid, proj_w2, proj_b2, z, Nu, 0);
}

// round 2
// speedup vs baseline: 1.2160x; 1.2160x over previous
#include <cuda_runtime.h>
#include <cuda_bf16.h>
#include <cstdint>

#define NU_MAX 200000
#define NI_MAX 20000
#define NE_MAX 1000000

// ---------------- scratch (device globals; no allocation allowed) -------------
__device__ float  g_user_x[NU_MAX * 32];
__device__ float  g_item_x[NI_MAX * 32];
__device__ float  g_xl1[NU_MAX * 128];
__device__ float  g_xr1[NI_MAX * 128];
__device__ float  g_xr2[NU_MAX * 128];
__device__ float  g_item2[NI_MAX * 128];
__device__ float  g_xl2[NI_MAX * 128];
__device__ float  g_hid[NU_MAX * 128];
__device__ float4 g_logits[NE_MAX];       // CSR-ordered logits
__device__ int    g_cnt1[NI_MAX];
__device__ int    g_off1[NI_MAX];
__device__ int    g_cur1[NI_MAX];
__device__ int    g_cnt2[NU_MAX];
__device__ int    g_off2[NU_MAX];
__device__ int    g_cur2[NU_MAX];
__device__ int    g_pos1[NE_MAX];         // edge -> CSR slot (dst grouping)
__device__ int    g_pos2[NE_MAX];         // edge -> CSR slot (src grouping)
__device__ int    g_oth1[NE_MAX];         // CSR-ordered "other endpoint" (src) for conv1
__device__ int    g_oth2[NE_MAX];         // CSR-ordered "other endpoint" (dst) for conv2

// ---------------- f32x2 helpers (Blackwell packed fp32 FMA) -------------------
__device__ __forceinline__ unsigned long long dup2(float x) {
    unsigned long long r;
    unsigned int xi = __float_as_uint(x);
    asm("mov.b64 %0, {%1, %1};" : "=l"(r) : "r"(xi));
    return r;
}
__device__ __forceinline__ void ffma2(unsigned long long& d, unsigned long long a,
                                      unsigned long long b) {
    asm("fma.rn.f32x2 %0, %1, %2, %0;" : "+l"(d) : "l"(a), "l"(b));
}
__device__ __forceinline__ float2 u2f2(unsigned long long v) {
    float2 f;
    unsigned int lo, hi;
    asm("mov.b64 {%0, %1}, %2;" : "=r"(lo), "=r"(hi) : "l"(v));
    f.x = __uint_as_float(lo); f.y = __uint_as_float(hi);
    return f;
}

// ---------------- tiled fp32 GEMM with f32x2: out = in[N,K]@W[K,NOUT] + b -----
// cg warp-uniform -> W LDS.64 broadcast; rows interleaved (odd pitch KP) ->
// conflict-free x LDS. Columns packed in pairs for fma.rn.f32x2.
template<int K, int NOUT, int CPT, int RPT>
__global__ void __launch_bounds__(256, 1) gemm_kernel(
    const float* __restrict__ in, const float* __restrict__ W,
    const float* __restrict__ bias, float* __restrict__ out,
    int nrows, int do_relu)
{
    constexpr int CG = NOUT / CPT;
    constexpr int RG = 256 / CG;         // >= 32 so cg is warp-uniform
    constexpr int RB = RG * RPT;
    constexpr int KP = (K & 1) ? K : (K + 1);
    constexpr int CP2 = CPT / 2;

    extern __shared__ float sm[];
    float* s_in = sm;                    // RB * KP
    float* s_w  = sm + RB * KP;          // K * NOUT (8B-aligned: RB even)
    __shared__ float s_b[NOUT];

    const int tid = threadIdx.x;
    const int rowbase = blockIdx.x * RB;

    for (int i = tid; i < K * NOUT; i += 256) s_w[i] = W[i];
    if (tid < NOUT) s_b[tid] = bias[tid];

    int nrow_blk = nrows - rowbase; if (nrow_blk > RB) nrow_blk = RB;
    const float* gin = in + (size_t)rowbase * K;
    for (int i = tid; i < nrow_blk * K; i += 256) {
        int r = i / K;
        int k = i - r * K;
        s_in[r * KP + k] = gin[i];
    }
    __syncthreads();

    const int cg = tid / RG;
    const int rg = tid - cg * RG;

    unsigned long long acc[RPT][CP2];
#pragma unroll
    for (int j = 0; j < RPT; j++)
#pragma unroll
        for (int c = 0; c < CP2; c++) acc[j][c] = 0ULL;

    const float* xbase = s_in + rg * KP;
    const float* wbase = s_w + cg * CPT;

#pragma unroll 8
    for (int k = 0; k < K; k++) {
        unsigned long long xd[RPT];
#pragma unroll
        for (int j = 0; j < RPT; j++) xd[j] = dup2(xbase[j * RG * KP + k]);
        const unsigned long long* wrow =
            (const unsigned long long*)(wbase + k * NOUT);
#pragma unroll
        for (int c = 0; c < CP2; c++) {
            unsigned long long wv = wrow[c];
#pragma unroll
            for (int j = 0; j < RPT; j++) ffma2(acc[j][c], xd[j], wv);
        }
    }

#pragma unroll
    for (int j = 0; j < RPT; j++) {
        int row = rowbase + rg + j * RG;
        if (row < nrows) {
            float* orow = out + (size_t)row * NOUT + cg * CPT;
#pragma unroll
            for (int c = 0; c < CP2; c++) {
                float2 f = u2f2(acc[j][c]);
                float v0 = f.x + s_b[cg * CPT + 2 * c];
                float v1 = f.y + s_b[cg * CPT + 2 * c + 1];
                if (do_relu) { v0 = fmaxf(v0, 0.f); v1 = fmaxf(v1, 0.f); }
                float2 o; o.x = v0; o.y = v1;
                ((float2*)orow)[c] = o;
            }
        }
    }
}

// ---------------- trivial item linear: [Ni,1] @ [1,32] + b
__global__ void item_lin_kernel(const float* __restrict__ fx, const float* __restrict__ w,
                                const float* __restrict__ b, float* __restrict__ out, int ni)
{
    int i = blockIdx.x * blockDim.x + threadIdx.x;
    if (i < ni * 32) {
        int r = i >> 5, c = i & 31;
        out[i] = fmaf(fx[r], w[c], b[c]);
    }
}

// ---------------- CSR build ----------------
__global__ void count_kernel(const int* __restrict__ src, const int* __restrict__ dst,
                             int* __restrict__ c1, int* __restrict__ c2, int E)
{
    int i = blockIdx.x * blockDim.x + threadIdx.x;
    if (i < E) {
        atomicAdd(&c1[dst[i]], 1);
        atomicAdd(&c2[src[i]], 1);
    }
}

// single-block exclusive scan, 4 elems/thread/iter (int4)
__global__ void scan_kernel(const int* __restrict__ cnt, int* __restrict__ off,
                            int* __restrict__ cur, int n)
{
    __shared__ int wsum[32];
    __shared__ int s_carry;
    int tid = threadIdx.x;
    if (tid == 0) s_carry = 0;
    __syncthreads();
    int nquad = (n + 3) >> 2;
    for (int base = 0; base < nquad; base += 1024) {
        int qi = base + tid;
        int4 v = make_int4(0, 0, 0, 0);
        if (qi < nquad) {
            int i0 = qi << 2;
            if (i0 + 3 < n) v = ((const int4*)cnt)[qi];
            else {
                v.x = cnt[i0];
                if (i0 + 1 < n) v.y = cnt[i0 + 1];
                if (i0 + 2 < n) v.z = cnt[i0 + 2];
            }
        }
        int tsum = v.x + v.y + v.z + v.w;
        int x = tsum;
#pragma unroll
        for (int d = 1; d < 32; d <<= 1) {
            int y = __shfl_up_sync(0xffffffffu, x, d);
            if ((tid & 31) >= d) x += y;
        }
        if ((tid & 31) == 31) wsum[tid >> 5] = x;
        __syncthreads();
        if (tid < 32) {
            int w = wsum[tid];
#pragma unroll
            for (int d = 1; d < 32; d <<= 1) {
                int y = __shfl_up_sync(0xffffffffu, w, d);
                if (tid >= d) w += y;
            }
            wsum[tid] = w;
        }
        __syncthreads();
        int wo = (tid >= 32) ? wsum[(tid >> 5) - 1] : 0;
        int excl = s_carry + wo + x - tsum;
        if (qi < nquad) {
            int i0 = qi << 2;
            int e0 = excl, e1 = e0 + v.x, e2 = e1 + v.y, e3 = e2 + v.z;
            off[i0] = e0; cur[i0] = e0;
            if (i0 + 1 < n) { off[i0 + 1] = e1; cur[i0 + 1] = e1; }
            if (i0 + 2 < n) { off[i0 + 2] = e2; cur[i0 + 2] = e2; }
            if (i0 + 3 < n) { off[i0 + 3] = e3; cur[i0 + 3] = e3; }
        }
        __syncthreads();
        if (tid == 0) s_carry += wsum[31];
        __syncthreads();
    }
}

// scatter: assign CSR slots, record per-edge slot and CSR-ordered other-endpoint
__global__ void scatter_kernel(const int* __restrict__ src, const int* __restrict__ dst,
                               int* __restrict__ cur1, int* __restrict__ cur2,
                               int* __restrict__ pos1, int* __restrict__ pos2,
                               int* __restrict__ oth1, int* __restrict__ oth2, int E)
{
    int i = blockIdx.x * blockDim.x + threadIdx.x;
    if (i < E) {
        int s = src[i], d = dst[i];
        int p1 = atomicAdd(&cur1[d], 1);
        pos1[i] = p1; oth1[p1] = s;
        int p2 = atomicAdd(&cur2[s], 1);
        pos2[i] = p2; oth2[p2] = d;
    }
}

// ---------------- edge logits: warp per edge, float4 rows, write CSR slot -----
__global__ void logits_kernel(const float* __restrict__ xl, const float* __restrict__ xr,
                              const int* __restrict__ srcIdx, const int* __restrict__ dstIdx,
                              const int* __restrict__ pos,
                              const float* __restrict__ eattr, const float* __restrict__ we,
                              const float* __restrict__ att, float* __restrict__ logits_csr,
                              int E)
{
    const int lane = threadIdx.x & 31;
    const int h = lane >> 3;                 // head owning my 4 channels
    const int warp = (blockIdx.x * blockDim.x + threadIdx.x) >> 5;
    const int nwarp = (gridDim.x * blockDim.x) >> 5;

    float4 att4 = ((const float4*)att)[lane];
    float4 we0 = make_float4(0, 0, 0, 0), we1 = we0, we2 = we0;
    if (we) {
        we0 = ((const float4*)we)[lane];
        we1 = ((const float4*)(we + 128))[lane];
        we2 = ((const float4*)(we + 256))[lane];
    }

    for (int e = warp; e < E; e += nwarp) {
        int s = __ldg(srcIdx + e);
        int d = __ldg(dstIdx + e);
        int p = __ldg(pos + e);
        float4 xs = __ldg((const float4*)(xl + (size_t)s * 128) + lane);
        float4 xd = __ldg((const float4*)(xr + (size_t)d * 128) + lane);
        float4 m4;
        m4.x = xs.x + xd.x; m4.y = xs.y + xd.y;
        m4.z = xs.z + xd.z; m4.w = xs.w + xd.w;
        if (eattr) {
            float a0 = __ldg(eattr + (size_t)e * 3);
            float a1 = __ldg(eattr + (size_t)e * 3 + 1);
            float a2 = __ldg(eattr + (size_t)e * 3 + 2);
            m4.x = fmaf(a0, we0.x, fmaf(a1, we1.x, fmaf(a2, we2.x, m4.x)));
            m4.y = fmaf(a0, we0.y, fmaf(a1, we1.y, fmaf(a2, we2.y, m4.y)));
            m4.z = fmaf(a0, we0.z, fmaf(a1, we1.z, fmaf(a2, we2.z, m4.z)));
            m4.w = fmaf(a0, we0.w, fmaf(a1, we1.w, fmaf(a2, we2.w, m4.w)));
        }
        float g0 = fmaxf(m4.x, 0.2f * m4.x);
        float g1 = fmaxf(m4.y, 0.2f * m4.y);
        float g2 = fmaxf(m4.z, 0.2f * m4.z);
        float g3 = fmaxf(m4.w, 0.2f * m4.w);
        float t = g0 * att4.x + g1 * att4.y + g2 * att4.z + g3 * att4.w;
        // reduce within 8-lane head group
        t += __shfl_xor_sync(0xffffffffu, t, 1);
        t += __shfl_xor_sync(0xffffffffu, t, 2);
        t += __shfl_xor_sync(0xffffffffu, t, 4);
        if ((lane & 7) == 0) logits_csr[(size_t)p * 4 + h] = t;
    }
}

// ---------------- per-node softmax + aggregation: warp per node, CSR order ----
__global__ void node_agg_kernel(const float* __restrict__ xl, const float4* __restrict__ lcsr,
                                const int* __restrict__ off, const int* __restrict__ cnt,
                                const int* __restrict__ other,
                                const float* __restrict__ bias, float* __restrict__ out,
                                int n, int do_relu)
{
    __shared__ float4 s_w4[8][32];
    __shared__ int    s_s[8][32];

    const int lane = threadIdx.x & 31;
    const int wrp = threadIdx.x >> 5;
    const int node = blockIdx.x * 8 + wrp;
    if (node >= n) return;

    const int h = lane >> 3;
    float4 bias4 = ((const float4*)bias)[lane];
    const int start = off[node];
    const int m = cnt[node];

    if (m == 0) {
        float4 o = bias4;
        if (do_relu) {
            o.x = fmaxf(o.x, 0.f); o.y = fmaxf(o.y, 0.f);
            o.z = fmaxf(o.z, 0.f); o.w = fmaxf(o.w, 0.f);
        }
        ((float4*)(out + (size_t)node * 128))[lane] = o;
        return;
    }

    const float NEGINF = __int_as_float(0xff800000u);
    float mx0 = NEGINF, mx1 = NEGINF, mx2 = NEGINF, mx3 = NEGINF;
    for (int i = lane; i < m; i += 32) {
        float4 lg = __ldg(lcsr + start + i);
        mx0 = fmaxf(mx0, lg.x); mx1 = fmaxf(mx1, lg.y);
        mx2 = fmaxf(mx2, lg.z); mx3 = fmaxf(mx3, lg.w);
    }
#pragma unroll
    for (int o = 16; o; o >>= 1) {
        mx0 = fmaxf(mx0, __shfl_xor_sync(0xffffffffu, mx0, o));
        mx1 = fmaxf(mx1, __shfl_xor_sync(0xffffffffu, mx1, o));
        mx2 = fmaxf(mx2, __shfl_xor_sync(0xffffffffu, mx2, o));
        mx3 = fmaxf(mx3, __shfl_xor_sync(0xffffffffu, mx3, o));
    }

    float s0 = 0.f, s1 = 0.f, s2 = 0.f, s3 = 0.f;
    for (int i = lane; i < m; i += 32) {
        float4 lg = __ldg(lcsr + start + i);
        s0 += __expf(lg.x - mx0); s1 += __expf(lg.y - mx1);
        s2 += __expf(lg.z - mx2); s3 += __expf(lg.w - mx3);
    }
#pragma unroll
    for (int o = 16; o; o >>= 1) {
        s0 += __shfl_xor_sync(0xffffffffu, s0, o);
        s1 += __shfl_xor_sync(0xffffffffu, s1, o);
        s2 += __shfl_xor_sync(0xffffffffu, s2, o);
        s3 += __shfl_xor_sync(0xffffffffu, s3, o);
    }
    const float i0 = 1.f / (s0 + 1e-16f);
    const float i1 = 1.f / (s1 + 1e-16f);
    const float i2 = 1.f / (s2 + 1e-16f);
    const float i3 = 1.f / (s3 + 1e-16f);

    float4 a = make_float4(0.f, 0.f, 0.f, 0.f);
    for (int base = 0; base < m; base += 32) {
        int i = base + lane;
        if (i < m) {
            float4 lg = __ldg(lcsr + start + i);
            float4 w;
            w.x = __expf(lg.x - mx0) * i0;
            w.y = __expf(lg.y - mx1) * i1;
            w.z = __expf(lg.z - mx2) * i2;
            w.w = __expf(lg.w - mx3) * i3;
            s_w4[wrp][lane] = w;
            s_s[wrp][lane] = __ldg(other + start + i);
        }
        __syncwarp();
        int lim = m - base; if (lim > 32) lim = 32;
        for (int j = 0; j < lim; j++) {
            int sj = s_s[wrp][j];
            float wh = ((const float*)&s_w4[wrp][j])[h];   // broadcast per head group
            float4 r = __ldg((const float4*)(xl + (size_t)sj * 128) + lane);
            a.x = fmaf(wh, r.x, a.x);
            a.y = fmaf(wh, r.y, a.y);
            a.z = fmaf(wh, r.z, a.z);
            a.w = fmaf(wh, r.w, a.w);
        }
        __syncwarp();
    }

    float4 o;
    o.x = a.x + bias4.x; o.y = a.y + bias4.y;
    o.z = a.z + bias4.z; o.w = a.w + bias4.w;
    if (do_relu) {
        o.x = fmaxf(o.x, 0.f); o.y = fmaxf(o.y, 0.f);
        o.z = fmaxf(o.z, 0.f); o.w = fmaxf(o.w, 0.f);
    }
    ((float4*)(out + (size_t)node * 128))[lane] = o;
}

// ---------------- host launch ----------------
extern "C" void kernel_launch(void* const* d_in, const int* in_sizes, int n_in,
                              void* d_out, int out_size)
{
    (void)n_in; (void)out_size;
    const float* customer_x = (const float*)d_in[0];
    const float* fund_x     = (const float*)d_in[1];
    const float* edge_attr  = (const float*)d_in[2];
    const float* user_lin_w = (const float*)d_in[3];
    const float* user_lin_b = (const float*)d_in[4];
    const float* item_lin_w = (const float*)d_in[5];
    const float* item_lin_b = (const float*)d_in[6];
    const float* conv1_wl   = (const float*)d_in[7];
    const float* conv1_bl   = (const float*)d_in[8];
    const float* conv1_wr   = (const float*)d_in[9];
    const float* conv1_br   = (const float*)d_in[10];
    const float* conv1_we   = (const float*)d_in[11];
    const float* conv1_att  = (const float*)d_in[12];
    const float* conv1_bias = (const float*)d_in[13];
    const float* conv2_wl   = (const float*)d_in[14];
    const float* conv2_bl   = (const float*)d_in[15];
    const float* conv2_wr   = (const float*)d_in[16];
    const float* conv2_br   = (const float*)d_in[17];
    const float* conv2_att  = (const float*)d_in[18];
    const float* conv2_bias = (const float*)d_in[19];
    const float* proj_w1    = (const float*)d_in[20];
    const float* proj_b1    = (const float*)d_in[21];
    const float* proj_w2    = (const float*)d_in[22];
    const float* proj_b2    = (const float*)d_in[23];
    const int*   edge_src   = (const int*)d_in[24];
    const int*   edge_dst   = (const int*)d_in[25];

    const int Nu = in_sizes[0] / 101;
    const int Ni = in_sizes[1];
    const int E  = in_sizes[24];

    float *user_x, *item_x, *xl1, *xr1, *xr2, *item2, *xl2, *hid;
    float4* logits;
    int *cnt1, *off1, *cur1, *cnt2, *off2, *cur2, *pos1, *pos2, *oth1, *oth2;
    cudaGetSymbolAddress((void**)&user_x, g_user_x);
    cudaGetSymbolAddress((void**)&item_x, g_item_x);
    cudaGetSymbolAddress((void**)&xl1,    g_xl1);
    cudaGetSymbolAddress((void**)&xr1,    g_xr1);
    cudaGetSymbolAddress((void**)&xr2,    g_xr2);
    cudaGetSymbolAddress((void**)&item2,  g_item2);
    cudaGetSymbolAddress((void**)&xl2,    g_xl2);
    cudaGetSymbolAddress((void**)&hid,    g_hid);
    cudaGetSymbolAddress((void**)&logits, g_logits);
    cudaGetSymbolAddress((void**)&cnt1,   g_cnt1);
    cudaGetSymbolAddress((void**)&off1,   g_off1);
    cudaGetSymbolAddress((void**)&cur1,   g_cur1);
    cudaGetSymbolAddress((void**)&cnt2,   g_cnt2);
    cudaGetSymbolAddress((void**)&off2,   g_off2);
    cudaGetSymbolAddress((void**)&cur2,   g_cur2);
    cudaGetSymbolAddress((void**)&pos1,   g_pos1);
    cudaGetSymbolAddress((void**)&pos2,   g_pos2);
    cudaGetSymbolAddress((void**)&oth1,   g_oth1);
    cudaGetSymbolAddress((void**)&oth2,   g_oth2);

    // dynamic smem per instantiation: (RB*KP + K*NOUT)*4
    const int smemUser = (128 * 101 + 101 * 32) * 4;    // gemm<101,32,8,2>
    const int smemG32  = (128 * 33  + 32 * 128) * 4;    // gemm<32,128,16,4>
    const int smemG128 = (128 * 129 + 128 * 128) * 4;   // gemm<128,128,16,4>
    cudaFuncSetAttribute(gemm_kernel<101, 32, 8, 2>,   cudaFuncAttributeMaxDynamicSharedMemorySize, smemUser);
    cudaFuncSetAttribute(gemm_kernel<32, 128, 16, 4>,  cudaFuncAttributeMaxDynamicSharedMemorySize, smemG32);
    cudaFuncSetAttribute(gemm_kernel<128, 128, 16, 4>, cudaFuncAttributeMaxDynamicSharedMemorySize, smemG128);

    float* user_out = (float*)d_out;             // [Nu,128]
    float* z        = user_out + (size_t)Nu * 128;

    // ---- CSR build (both directions) ----
    cudaMemsetAsync(cnt1, 0, Ni * sizeof(int));
    cudaMemsetAsync(cnt2, 0, Nu * sizeof(int));
    count_kernel<<<(E + 255) / 256, 256>>>(edge_src, edge_dst, cnt1, cnt2, E);
    scan_kernel<<<1, 1024>>>(cnt1, off1, cur1, Ni);
    scan_kernel<<<1, 1024>>>(cnt2, off2, cur2, Nu);
    scatter_kernel<<<(E + 255) / 256, 256>>>(edge_src, edge_dst, cur1, cur2,
                                             pos1, pos2, oth1, oth2, E);

    // ---- input linears ----
    gemm_kernel<101, 32, 8, 2><<<(Nu + 127) / 128, 256, smemUser>>>(customer_x, user_lin_w, user_lin_b, user_x, Nu, 0);
    item_lin_kernel<<<(Ni * 32 + 255) / 256, 256>>>(fund_x, item_lin_w, item_lin_b, item_x, Ni);

    // ---- conv projections ----
    gemm_kernel<32, 128, 16, 4><<<(Nu + 127) / 128, 256, smemG32>>>(user_x, conv1_wl, conv1_bl, xl1, Nu, 0);
    gemm_kernel<32, 128, 16, 4><<<(Nu + 127) / 128, 256, smemG32>>>(user_x, conv2_wr, conv2_br, xr2, Nu, 0);
    gemm_kernel<32, 128, 16, 4><<<(Ni + 127) / 128, 256, smemG32>>>(item_x, conv1_wr, conv1_br, xr1, Ni, 0);

    // ---- conv1: user -> item ----
    logits_kernel<<<4096, 256>>>(xl1, xr1, edge_src, edge_dst, pos1, edge_attr, conv1_we,
                                 conv1_att, (float*)logits, E);
    node_agg_kernel<<<(Ni + 7) / 8, 256>>>(xl1, logits, off1, cnt1, oth1, conv1_bias, item2, Ni, 1);

    // ---- conv2: item -> user (flipped edges, no edge_attr) ----
    gemm_kernel<128, 128, 16, 4><<<(Ni + 127) / 128, 256, smemG128>>>(item2, conv2_wl, conv2_bl, xl2, Ni, 0);
    logits_kernel<<<4096, 256>>>(xl2, xr2, edge_dst, edge_src, pos2, nullptr, nullptr,
                                 conv2_att, (float*)logits, E);
    node_agg_kernel<<<(Nu + 7) / 8, 256>>>(xl2, logits, off2, cnt2, oth2, conv2_bias, user_out, Nu, 0);

    // ---- final MLP: z = relu(user_out@W1+b1)@W2+b2 ----
    gemm_kernel<128, 128, 16, 4><<<(Nu + 127) / 128, 256, smemG128>>>(user_out, proj_w1, proj_b1, hid, Nu, 1);
    gemm_kernel<128, 128, 16, 4><<<(Nu + 127) / 128, 256, smemG128>>>(hid, proj_w2, proj_b2, z, Nu, 0);
}

// round 4
// speedup vs baseline: 1.8035x; 1.4832x over previous
#include <cuda_runtime.h>
#include <cuda_bf16.h>
#include <cstdint>

#define NU_MAX 200000
#define NI_MAX 20000
#define NE_MAX 1000000

// ---------------- scratch (device globals; no allocation allowed) -------------
__device__ float  g_user_x[NU_MAX * 32];
__device__ float  g_item_x[NI_MAX * 32];
__device__ float  g_xl1[NU_MAX * 128];
__device__ float  g_xr1[NI_MAX * 128];
__device__ float  g_xr2[NU_MAX * 128];
__device__ float  g_item2[NI_MAX * 128];
__device__ float  g_xl2[NI_MAX * 128];
__device__ float  g_hid[NU_MAX * 128];
__device__ int    g_deg[NI_MAX + NU_MAX]; // cnt1 | cnt2 (one memset)
__device__ int    g_off[NI_MAX + NU_MAX];
__device__ int    g_cur[NI_MAX + NU_MAX];
__device__ int    g_oth1[NE_MAX];         // CSR(dst)-ordered src for conv1
__device__ int    g_oth2[NE_MAX];         // CSR(src)-ordered dst for conv2
__device__ float4 g_ea1[NE_MAX];          // CSR(dst)-ordered edge_attr (conv1)

// ================= helpers =================
__device__ __forceinline__ uint32_t smem_u32(const void* p) {
    uint32_t a;
    asm("{ .reg .u64 t; cvta.to.shared.u64 t, %1; cvt.u32.u64 %0, t; }" : "=r"(a) : "l"(p));
    return a;
}
__device__ __forceinline__ void ldm_x4(uint32_t* r, uint32_t addr) {
    asm volatile("ldmatrix.sync.aligned.m8n8.x4.shared.b16 {%0,%1,%2,%3}, [%4];"
                 : "=r"(r[0]), "=r"(r[1]), "=r"(r[2]), "=r"(r[3]) : "r"(addr));
}
__device__ __forceinline__ void mma_bf16(float* c, const uint32_t* a, uint32_t b0, uint32_t b1) {
    asm volatile("mma.sync.aligned.m16n8k16.row.col.f32.bf16.bf16.f32 "
                 "{%0,%1,%2,%3}, {%4,%5,%6,%7}, {%8,%9}, {%0,%1,%2,%3};"
                 : "+f"(c[0]), "+f"(c[1]), "+f"(c[2]), "+f"(c[3])
                 : "r"(a[0]), "r"(a[1]), "r"(a[2]), "r"(a[3]), "r"(b0), "r"(b1));
}

// ---------------- HMMA GEMM: out[nrows,128] = in[nrows,K] @ W[K,128] + b ------
// bf16 hi/lo split (3 terms), fp32 accumulate. Block = 128 rows x 128 cols,
// 8 warps, each warp 16 rows x 128 cols. Padded smem stride -> conflict-free
// ldmatrix (stride 4r mod 32 distinct).
template<int K>
__global__ void __launch_bounds__(256) mma_gemm(
    const float* __restrict__ in, const float* __restrict__ W,
    const float* __restrict__ bias, float* __restrict__ out,
    int nrows, int do_relu)
{
    constexpr int KP = K + 8;                // padded bf16 row stride
    constexpr int TILE = 128 * KP;           // elements per bf16 tile

    extern __shared__ __nv_bfloat16 smbf[];
    __nv_bfloat16* sAh = smbf;
    __nv_bfloat16* sAl = sAh + TILE;
    __nv_bfloat16* sBh = sAl + TILE;
    __nv_bfloat16* sBl = sBh + TILE;
    __shared__ float s_bias[128];

    const int tid = threadIdx.x;
    const int rowbase = blockIdx.x * 128;
    if (tid < 128) s_bias[tid] = bias[tid];

    int nrow_blk = nrows - rowbase; if (nrow_blk > 128) nrow_blk = 128;
    const float* gin = in + (size_t)rowbase * K;
    // A: full 128 rows (zero-fill tail)
    for (int i = tid; i < 128 * K; i += 256) {
        int r = i / K;
        int c = i - r * K;
        float x = (r < nrow_blk) ? gin[i] : 0.f;
        __nv_bfloat16 hi = __float2bfloat16(x);
        __nv_bfloat16 lo = __float2bfloat16(x - __bfloat162float(hi));
        sAh[r * KP + c] = hi;
        sAl[r * KP + c] = lo;
    }
    // B = W^T : sB[n][k] = W[k][n]
    for (int i = tid; i < K * 128; i += 256) {
        int k = i >> 7;
        int n = i & 127;
        float x = W[i];
        __nv_bfloat16 hi = __float2bfloat16(x);
        __nv_bfloat16 lo = __float2bfloat16(x - __bfloat162float(hi));
        sBh[n * KP + k] = hi;
        sBl[n * KP + k] = lo;
    }
    __syncthreads();

    const int wid = tid >> 5;
    const int lane = tid & 31;
    const int m0 = wid * 16;

    float c[16][4];
#pragma unroll
    for (int nb = 0; nb < 16; nb++)
#pragma unroll
        for (int q = 0; q < 4; q++) c[nb][q] = 0.f;

    const uint32_t sAh0 = smem_u32(sAh), sAl0 = smem_u32(sAl);
    const uint32_t sBh0 = smem_u32(sBh), sBl0 = smem_u32(sBl);
    const int lrow = lane & 15;
    const int lcol = (lane >> 4) << 3;
    const uint32_t offA = (uint32_t)((m0 + lrow) * KP + lcol) * 2;

#pragma unroll 2
    for (int s = 0; s < K / 16; s++) {
        uint32_t ah[4], al[4];
        ldm_x4(ah, sAh0 + offA + s * 32);
        ldm_x4(al, sAl0 + offA + s * 32);
#pragma unroll
        for (int nbp = 0; nbp < 8; nbp++) {
            uint32_t offB = (uint32_t)((nbp * 16 + lrow) * KP + lcol) * 2 + s * 32;
            uint32_t bh[4], bl[4];
            ldm_x4(bh, sBh0 + offB);
            ldm_x4(bl, sBl0 + offB);
            mma_bf16(c[2 * nbp],     ah, bh[0], bh[2]);
            mma_bf16(c[2 * nbp],     ah, bl[0], bl[2]);
            mma_bf16(c[2 * nbp],     al, bh[0], bh[2]);
            mma_bf16(c[2 * nbp + 1], ah, bh[1], bh[3]);
            mma_bf16(c[2 * nbp + 1], ah, bl[1], bl[3]);
            mma_bf16(c[2 * nbp + 1], al, bh[1], bh[3]);
        }
    }

    // epilogue: thread t -> rows m0 + t/4 (+8), col pair nb*8 + 2*(t%4)
    const int r0 = rowbase + m0 + (lane >> 2);
    const int r1 = r0 + 8;
    const int cb = (lane & 3) * 2;
#pragma unroll
    for (int nb = 0; nb < 16; nb++) {
        int col = nb * 8 + cb;
        float2 v0, v1;
        v0.x = c[nb][0] + s_bias[col];
        v0.y = c[nb][1] + s_bias[col + 1];
        v1.x = c[nb][2] + s_bias[col];
        v1.y = c[nb][3] + s_bias[col + 1];
        if (do_relu) {
            v0.x = fmaxf(v0.x, 0.f); v0.y = fmaxf(v0.y, 0.f);
            v1.x = fmaxf(v1.x, 0.f); v1.y = fmaxf(v1.y, 0.f);
        }
        if (r0 < nrows) *(float2*)(out + (size_t)r0 * 128 + col) = v0;
        if (r1 < nrows) *(float2*)(out + (size_t)r1 * 128 + col) = v1;
    }
}

// ================= f32x2 FFMA2 GEMM (K=101 user linear) ======================
__device__ __forceinline__ unsigned long long dup2(float x) {
    unsigned long long r;
    unsigned int xi = __float_as_uint(x);
    asm("mov.b64 %0, {%1, %1};" : "=l"(r) : "r"(xi));
    return r;
}
__device__ __forceinline__ void ffma2(unsigned long long& d, unsigned long long a,
                                      unsigned long long b) {
    asm("fma.rn.f32x2 %0, %1, %2, %0;" : "+l"(d) : "l"(a), "l"(b));
}
__device__ __forceinline__ float2 u2f2(unsigned long long v) {
    float2 f;
    unsigned int lo, hi;
    asm("mov.b64 {%0, %1}, %2;" : "=r"(lo), "=r"(hi) : "l"(v));
    f.x = __uint_as_float(lo); f.y = __uint_as_float(hi);
    return f;
}

template<int K, int NOUT, int CPT, int RPT>
__global__ void __launch_bounds__(256, 1) gemm_kernel(
    const float* __restrict__ in, const float* __restrict__ W,
    const float* __restrict__ bias, float* __restrict__ out,
    int nrows, int do_relu)
{
    constexpr int CG = NOUT / CPT;
    constexpr int RG = 256 / CG;
    constexpr int RB = RG * RPT;
    constexpr int KP = (K & 1) ? K : (K + 1);
    constexpr int CP2 = CPT / 2;

    extern __shared__ float sm[];
    float* s_in = sm;
    float* s_w  = sm + RB * KP;
    __shared__ float s_b[NOUT];

    const int tid = threadIdx.x;
    const int rowbase = blockIdx.x * RB;

    for (int i = tid; i < K * NOUT; i += 256) s_w[i] = W[i];
    if (tid < NOUT) s_b[tid] = bias[tid];

    int nrow_blk = nrows - rowbase; if (nrow_blk > RB) nrow_blk = RB;
    const float* gin = in + (size_t)rowbase * K;
    for (int i = tid; i < nrow_blk * K; i += 256) {
        int r = i / K;
        int k = i - r * K;
        s_in[r * KP + k] = gin[i];
    }
    __syncthreads();

    const int cg = tid / RG;
    const int rg = tid - cg * RG;

    unsigned long long acc[RPT][CP2];
#pragma unroll
    for (int j = 0; j < RPT; j++)
#pragma unroll
        for (int c = 0; c < CP2; c++) acc[j][c] = 0ULL;

    const float* xbase = s_in + rg * KP;
    const float* wbase = s_w + cg * CPT;

#pragma unroll 8
    for (int k = 0; k < K; k++) {
        unsigned long long xd[RPT];
#pragma unroll
        for (int j = 0; j < RPT; j++) xd[j] = dup2(xbase[j * RG * KP + k]);
        const unsigned long long* wrow = (const unsigned long long*)(wbase + k * NOUT);
#pragma unroll
        for (int c = 0; c < CP2; c++) {
            unsigned long long wv = wrow[c];
#pragma unroll
            for (int j = 0; j < RPT; j++) ffma2(acc[j][c], xd[j], wv);
        }
    }

#pragma unroll
    for (int j = 0; j < RPT; j++) {
        int row = rowbase + rg + j * RG;
        if (row < nrows) {
            float* orow = out + (size_t)row * NOUT + cg * CPT;
#pragma unroll
            for (int c = 0; c < CP2; c++) {
                float2 f = u2f2(acc[j][c]);
                float v0 = f.x + s_b[cg * CPT + 2 * c];
                float v1 = f.y + s_b[cg * CPT + 2 * c + 1];
                if (do_relu) { v0 = fmaxf(v0, 0.f); v1 = fmaxf(v1, 0.f); }
                float2 o; o.x = v0; o.y = v1;
                ((float2*)orow)[c] = o;
            }
        }
    }
}

// ---------------- trivial item linear ----------------
__global__ void item_lin_kernel(const float* __restrict__ fx, const float* __restrict__ w,
                                const float* __restrict__ b, float* __restrict__ out, int ni)
{
    int i = blockIdx.x * blockDim.x + threadIdx.x;
    if (i < ni * 32) {
        int r = i >> 5, c = i & 31;
        out[i] = fmaf(fx[r], w[c], b[c]);
    }
}

// ---------------- CSR build ----------------
__global__ void count_kernel(const int* __restrict__ src, const int* __restrict__ dst,
                             int* __restrict__ c1, int* __restrict__ c2, int E)
{
    int i = blockIdx.x * blockDim.x + threadIdx.x;
    if (i < E) {
        atomicAdd(&c1[dst[i]], 1);
        atomicAdd(&c2[src[i]], 1);
    }
}

// two exclusive scans in one launch (single block)
__global__ void scan2_kernel(const int* __restrict__ cA, int* __restrict__ oA, int* __restrict__ uA, int nA,
                             const int* __restrict__ cB, int* __restrict__ oB, int* __restrict__ uB, int nB)
{
    __shared__ int wsum[32];
    __shared__ int s_carry;
    int tid = threadIdx.x;
    for (int seg = 0; seg < 2; seg++) {
        const int* cnt = seg ? cB : cA;
        int* off = seg ? oB : oA;
        int* cur = seg ? uB : uA;
        int n = seg ? nB : nA;
        if (tid == 0) s_carry = 0;
        __syncthreads();
        int nquad = (n + 3) >> 2;
        for (int base = 0; base < nquad; base += 1024) {
            int qi = base + tid;
            int4 v = make_int4(0, 0, 0, 0);
            if (qi < nquad) {
                int i0 = qi << 2;
                if (i0 + 3 < n) v = ((const int4*)cnt)[qi];
                else {
                    v.x = cnt[i0];
                    if (i0 + 1 < n) v.y = cnt[i0 + 1];
                    if (i0 + 2 < n) v.z = cnt[i0 + 2];
                }
            }
            int tsum = v.x + v.y + v.z + v.w;
            int x = tsum;
#pragma unroll
            for (int d = 1; d < 32; d <<= 1) {
                int y = __shfl_up_sync(0xffffffffu, x, d);
                if ((tid & 31) >= d) x += y;
            }
            if ((tid & 31) == 31) wsum[tid >> 5] = x;
            __syncthreads();
            if (tid < 32) {
                int w = wsum[tid];
#pragma unroll
                for (int d = 1; d < 32; d <<= 1) {
                    int y = __shfl_up_sync(0xffffffffu, w, d);
                    if (tid >= d) w += y;
                }
                wsum[tid] = w;
            }
            __syncthreads();
            int wo = (tid >= 32) ? wsum[(tid >> 5) - 1] : 0;
            int excl = s_carry + wo + x - tsum;
            if (qi < nquad) {
                int i0 = qi << 2;
                int e0 = excl, e1 = e0 + v.x, e2 = e1 + v.y, e3 = e2 + v.z;
                off[i0] = e0; cur[i0] = e0;
                if (i0 + 1 < n) { off[i0 + 1] = e1; cur[i0 + 1] = e1; }
                if (i0 + 2 < n) { off[i0 + 2] = e2; cur[i0 + 2] = e2; }
                if (i0 + 3 < n) { off[i0 + 3] = e3; cur[i0 + 3] = e3; }
            }
            __syncthreads();
            if (tid == 0) s_carry += wsum[31];
            __syncthreads();
        }
    }
}

// scatter: CSR slots + CSR-ordered other-endpoint + CSR-ordered edge attrs
__global__ void scatter_kernel(const int* __restrict__ src, const int* __restrict__ dst,
                               const float* __restrict__ eattr,
                               int* __restrict__ cur1, int* __restrict__ cur2,
                               int* __restrict__ oth1, int* __restrict__ oth2,
                               float4* __restrict__ ea1, int E)
{
    int i = blockIdx.x * blockDim.x + threadIdx.x;
    if (i < E) {
        int s = src[i], d = dst[i];
        int p1 = atomicAdd(&cur1[d], 1);
        oth1[p1] = s;
        float a0 = eattr[(size_t)i * 3];
        float a1 = eattr[(size_t)i * 3 + 1];
        float a2 = eattr[(size_t)i * 3 + 2];
        ea1[p1] = make_float4(a0, a1, a2, 0.f);
        int p2 = atomicAdd(&cur2[s], 1);
        oth2[p2] = d;
    }
}

// ---------------- fused GATv2 conv: online softmax + aggregation --------------
// warp per destination node; lane owns 4 channels (head = lane>>3).
// Single pass over edges: logit -> running max/sum/accumulator (flash-style).
__global__ void gat_conv_kernel(
    const float* __restrict__ xl,      // [n_src,128] source-side projections
    const float* __restrict__ xr,      // [n_dst,128] dest-side projections
    const int* __restrict__ off, const int* __restrict__ cnt,
    const int* __restrict__ other,     // CSR-ordered source indices
    const float4* __restrict__ ea,     // CSR-ordered edge attrs or null
    const float* __restrict__ we,      // [3,128] or null
    const float* __restrict__ att,     // [4,32] flattened
    const float* __restrict__ bias, float* __restrict__ out,
    int n, int do_relu)
{
    __shared__ int    s_o[8][32];
    __shared__ float4 s_ea[8][32];

    const int lane = threadIdx.x & 31;
    const int wrp = threadIdx.x >> 5;
    const int node = blockIdx.x * 8 + wrp;
    if (node >= n) return;

    float4 att4 = ((const float4*)att)[lane];
    float4 bias4 = ((const float4*)bias)[lane];
    const int start = off[node];
    const int m = cnt[node];

    if (m == 0) {
        float4 o = bias4;
        if (do_relu) {
            o.x = fmaxf(o.x, 0.f); o.y = fmaxf(o.y, 0.f);
            o.z = fmaxf(o.z, 0.f); o.w = fmaxf(o.w, 0.f);
        }
        ((float4*)(out + (size_t)node * 128))[lane] = o;
        return;
    }

    float4 we0 = make_float4(0, 0, 0, 0), we1 = we0, we2 = we0;
    if (we) {
        we0 = ((const float4*)we)[lane];
        we1 = ((const float4*)(we + 128))[lane];
        we2 = ((const float4*)(we + 256))[lane];
    }
    float4 xr4 = __ldg((const float4*)(xr + (size_t)node * 128) + lane);

    float M = __int_as_float(0xff800000u);   // -inf
    float ssum = 0.f;
    float4 a = make_float4(0.f, 0.f, 0.f, 0.f);

    for (int base = 0; base < m; base += 32) {
        int i = base + lane;
        if (i < m) {
            s_o[wrp][lane] = __ldg(other + start + i);
            if (ea) s_ea[wrp][lane] = __ldg(ea + start + i);
        }
        __syncwarp();
        int lim = m - base; if (lim > 32) lim = 32;
        for (int j = 0; j < lim; j++) {
            int srcn = s_o[wrp][j];
            float4 xs = __ldg((const float4*)(xl + (size_t)srcn * 128) + lane);
            float4 m4;
            m4.x = xs.x + xr4.x; m4.y = xs.y + xr4.y;
            m4.z = xs.z + xr4.z; m4.w = xs.w + xr4.w;
            if (ea) {
                float4 e = s_ea[wrp][j];
                m4.x = fmaf(e.x, we0.x, fmaf(e.y, we1.x, fmaf(e.z, we2.x, m4.x)));
                m4.y = fmaf(e.x, we0.y, fmaf(e.y, we1.y, fmaf(e.z, we2.y, m4.y)));
                m4.z = fmaf(e.x, we0.z, fmaf(e.y, we1.z, fmaf(e.z, we2.z, m4.z)));
                m4.w = fmaf(e.x, we0.w, fmaf(e.y, we1.w, fmaf(e.z, we2.w, m4.w)));
            }
            float g0 = fmaxf(m4.x, 0.2f * m4.x);
            float g1 = fmaxf(m4.y, 0.2f * m4.y);
            float g2 = fmaxf(m4.z, 0.2f * m4.z);
            float g3 = fmaxf(m4.w, 0.2f * m4.w);
            float t = g0 * att4.x + g1 * att4.y + g2 * att4.z + g3 * att4.w;
            // head logit: reduce across 8-lane group
            t += __shfl_xor_sync(0xffffffffu, t, 1);
            t += __shfl_xor_sync(0xffffffffu, t, 2);
            t += __shfl_xor_sync(0xffffffffu, t, 4);
            // online softmax update (per head; all lanes of group identical state)
            float Mn = fmaxf(M, t);
            float corr = __expf(M - Mn);       // first iter: exp(-inf)=0
            float p = __expf(t - Mn);
            ssum = ssum * corr + p;
            a.x = fmaf(a.x, corr, p * xs.x);
            a.y = fmaf(a.y, corr, p * xs.y);
            a.z = fmaf(a.z, corr, p * xs.z);
            a.w = fmaf(a.w, corr, p * xs.w);
            M = Mn;
        }
        __syncwarp();
    }

    float inv = 1.f / (ssum + 1e-16f);
    float4 o;
    o.x = fmaf(a.x, inv, bias4.x);
    o.y = fmaf(a.y, inv, bias4.y);
    o.z = fmaf(a.z, inv, bias4.z);
    o.w = fmaf(a.w, inv, bias4.w);
    if (do_relu) {
        o.x = fmaxf(o.x, 0.f); o.y = fmaxf(o.y, 0.f);
        o.z = fmaxf(o.z, 0.f); o.w = fmaxf(o.w, 0.f);
    }
    ((float4*)(out + (size_t)node * 128))[lane] = o;
}

// ---------------- host launch ----------------
extern "C" void kernel_launch(void* const* d_in, const int* in_sizes, int n_in,
                              void* d_out, int out_size)
{
    (void)n_in; (void)out_size;
    const float* customer_x = (const float*)d_in[0];
    const float* fund_x     = (const float*)d_in[1];
    const float* edge_attr  = (const float*)d_in[2];
    const float* user_lin_w = (const float*)d_in[3];
    const float* user_lin_b = (const float*)d_in[4];
    const float* item_lin_w = (const float*)d_in[5];
    const float* item_lin_b = (const float*)d_in[6];
    const float* conv1_wl   = (const float*)d_in[7];
    const float* conv1_bl   = (const float*)d_in[8];
    const float* conv1_wr   = (const float*)d_in[9];
    const float* conv1_br   = (const float*)d_in[10];
    const float* conv1_we   = (const float*)d_in[11];
    const float* conv1_att  = (const float*)d_in[12];
    const float* conv1_bias = (const float*)d_in[13];
    const float* conv2_wl   = (const float*)d_in[14];
    const float* conv2_bl   = (const float*)d_in[15];
    const float* conv2_wr   = (const float*)d_in[16];
    const float* conv2_br   = (const float*)d_in[17];
    const float* conv2_att  = (const float*)d_in[18];
    const float* conv2_bias = (const float*)d_in[19];
    const float* proj_w1    = (const float*)d_in[20];
    const float* proj_b1    = (const float*)d_in[21];
    const float* proj_w2    = (const float*)d_in[22];
    const float* proj_b2    = (const float*)d_in[23];
    const int*   edge_src   = (const int*)d_in[24];
    const int*   edge_dst   = (const int*)d_in[25];

    const int Nu = in_sizes[0] / 101;
    const int Ni = in_sizes[1];
    const int E  = in_sizes[24];

    float *user_x, *item_x, *xl1, *xr1, *xr2, *item2, *xl2, *hid;
    int *deg, *off, *cur, *oth1, *oth2;
    float4* ea1;
    cudaGetSymbolAddress((void**)&user_x, g_user_x);
    cudaGetSymbolAddress((void**)&item_x, g_item_x);
    cudaGetSymbolAddress((void**)&xl1,    g_xl1);
    cudaGetSymbolAddress((void**)&xr1,    g_xr1);
    cudaGetSymbolAddress((void**)&xr2,    g_xr2);
    cudaGetSymbolAddress((void**)&item2,  g_item2);
    cudaGetSymbolAddress((void**)&xl2,    g_xl2);
    cudaGetSymbolAddress((void**)&hid,    g_hid);
    cudaGetSymbolAddress((void**)&deg,    g_deg);
    cudaGetSymbolAddress((void**)&off,    g_off);
    cudaGetSymbolAddress((void**)&cur,    g_cur);
    cudaGetSymbolAddress((void**)&oth1,   g_oth1);
    cudaGetSymbolAddress((void**)&oth2,   g_oth2);
    cudaGetSymbolAddress((void**)&ea1,    g_ea1);

    int *cnt1 = deg, *cnt2 = deg + NI_MAX;
    int *off1 = off, *off2 = off + NI_MAX;
    int *cur1 = cur, *cur2 = cur + NI_MAX;

    const int smemUser  = (128 * 101 + 101 * 32) * 4;            // gemm<101,32,8,2>
    const int smemMM32  = 4 * 128 * (32 + 8) * 2;                // mma_gemm<32>   (40960)
    const int smemMM128 = 4 * 128 * (128 + 8) * 2;               // mma_gemm<128> (139264)
    cudaFuncSetAttribute(gemm_kernel<101, 32, 8, 2>, cudaFuncAttributeMaxDynamicSharedMemorySize, smemUser);
    cudaFuncSetAttribute(mma_gemm<32>,  cudaFuncAttributeMaxDynamicSharedMemorySize, smemMM32);
    cudaFuncSetAttribute(mma_gemm<128>, cudaFuncAttributeMaxDynamicSharedMemorySize, smemMM128);

    float* user_out = (float*)d_out;             // [Nu,128]
    float* z        = user_out + (size_t)Nu * 128;

    // 1: memset combined degree array
    cudaMemsetAsync(deg, 0, (NI_MAX + Nu) * sizeof(int));
    // 2-4: CSR build
    count_kernel<<<(E + 255) / 256, 256>>>(edge_src, edge_dst, cnt1, cnt2, E);
    scan2_kernel<<<1, 1024>>>(cnt1, off1, cur1, Ni, cnt2, off2, cur2, Nu);
    scatter_kernel<<<(E + 255) / 256, 256>>>(edge_src, edge_dst, edge_attr,
                                             cur1, cur2, oth1, oth2, ea1, E);
    // 5: user linear (K=101, FFMA2)
    gemm_kernel<101, 32, 8, 2><<<(Nu + 127) / 128, 256, smemUser>>>(customer_x, user_lin_w, user_lin_b, user_x, Nu, 0);
    // 6: mma_gemm<32> xl1  (ncu capture lands here)
    mma_gemm<32><<<(Nu + 127) / 128, 256, smemMM32>>>(user_x, conv1_wl, conv1_bl, xl1, Nu, 0);
    // 7: item linear
    item_lin_kernel<<<(Ni * 32 + 255) / 256, 256>>>(fund_x, item_lin_w, item_lin_b, item_x, Ni);
    // 8-9: remaining projections
    mma_gemm<32><<<(Nu + 127) / 128, 256, smemMM32>>>(user_x, conv2_wr, conv2_br, xr2, Nu, 0);
    mma_gemm<32><<<(Ni + 127) / 128, 256, smemMM32>>>(item_x, conv1_wr, conv1_br, xr1, Ni, 0);

    // conv1: user -> item (fused logits+softmax+aggregate, online)
    gat_conv_kernel<<<(Ni + 7) / 8, 256>>>(xl1, xr1, off1, cnt1, oth1, ea1, conv1_we,
                                           conv1_att, conv1_bias, item2, Ni, 1);

    // conv2: item -> user (flipped edges, no edge_attr)
    mma_gemm<128><<<(Ni + 127) / 128, 256, smemMM128>>>(item2, conv2_wl, conv2_bl, xl2, Ni, 0);
    gat_conv_kernel<<<(Nu + 7) / 8, 256>>>(xl2, xr2, off2, cnt2, oth2, nullptr, nullptr,
                                           conv2_att, conv2_bias, user_out, Nu, 0);

    // final MLP
    mma_gemm<128><<<(Nu + 127) / 128, 256, smemMM128>>>(user_out, proj_w1, proj_b1, hid, Nu, 1);
    mma_gemm<128><<<(Nu + 127) / 128, 256, smemMM128>>>(hid, proj_w2, proj_b2, z, Nu, 0);
}

// round 5
// speedup vs baseline: 1.8054x; 1.0011x over previous
#include <cuda_runtime.h>
#include <cuda_bf16.h>
#include <cstdint>

#define NU_MAX 200000
#define NI_MAX 20000
#define NE_MAX 1000000

// ---------------- scratch (device globals; no allocation allowed) -------------
__device__ float  g_user_x[NU_MAX * 32];
__device__ float  g_item_x[NI_MAX * 32];
__device__ float  g_xl1[NU_MAX * 128];
__device__ float  g_xr1[NI_MAX * 128];
__device__ float  g_xr2[NU_MAX * 128];
__device__ float  g_item2[NI_MAX * 128];
__device__ float  g_xl2[NI_MAX * 128];
__device__ float  g_hid[NU_MAX * 128];
__device__ int    g_deg[NI_MAX + NU_MAX]; // cnt1 | cnt2 (one memset)
__device__ int    g_off[NI_MAX + NU_MAX];
__device__ int    g_cur[NI_MAX + NU_MAX];
__device__ int    g_oth1[NE_MAX];         // CSR(dst)-ordered src for conv1
__device__ int    g_oth2[NE_MAX];         // CSR(src)-ordered dst for conv2
__device__ float4 g_ea1[NE_MAX];          // CSR(dst)-ordered edge_attr (conv1)

// ================= helpers =================
__device__ __forceinline__ uint32_t smem_u32(const void* p) {
    uint32_t a;
    asm("{ .reg .u64 t; cvta.to.shared.u64 t, %1; cvt.u32.u64 %0, t; }" : "=r"(a) : "l"(p));
    return a;
}
__device__ __forceinline__ void ldm_x4(uint32_t* r, uint32_t addr) {
    asm volatile("ldmatrix.sync.aligned.m8n8.x4.shared.b16 {%0,%1,%2,%3}, [%4];"
                 : "=r"(r[0]), "=r"(r[1]), "=r"(r[2]), "=r"(r[3]) : "r"(addr));
}
__device__ __forceinline__ void mma_bf16(float* c, const uint32_t* a, uint32_t b0, uint32_t b1) {
    asm volatile("mma.sync.aligned.m16n8k16.row.col.f32.bf16.bf16.f32 "
                 "{%0,%1,%2,%3}, {%4,%5,%6,%7}, {%8,%9}, {%0,%1,%2,%3};"
                 : "+f"(c[0]), "+f"(c[1]), "+f"(c[2]), "+f"(c[3])
                 : "r"(a[0]), "r"(a[1]), "r"(a[2]), "r"(a[3]), "r"(b0), "r"(b1));
}

// ---------------- HMMA GEMM: out[nrows,128] = in[nrows,K] @ W[K,128] + b ------
// bf16 hi/lo split (3 terms), fp32 accumulate. Block = 128 rows x 128 cols,
// 8 warps, each warp 16 rows x 128 cols. Padded smem stride -> conflict-free
// ldmatrix (stride 4r mod 32 distinct).
template<int K>
__global__ void __launch_bounds__(256) mma_gemm(
    const float* __restrict__ in, const float* __restrict__ W,
    const float* __restrict__ bias, float* __restrict__ out,
    int nrows, int do_relu)
{
    constexpr int KP = K + 8;                // padded bf16 row stride
    constexpr int TILE = 128 * KP;           // elements per bf16 tile

    extern __shared__ __nv_bfloat16 smbf[];
    __nv_bfloat16* sAh = smbf;
    __nv_bfloat16* sAl = sAh + TILE;
    __nv_bfloat16* sBh = sAl + TILE;
    __nv_bfloat16* sBl = sBh + TILE;
    __shared__ float s_bias[128];

    const int tid = threadIdx.x;
    const int rowbase = blockIdx.x * 128;
    if (tid < 128) s_bias[tid] = bias[tid];

    int nrow_blk = nrows - rowbase; if (nrow_blk > 128) nrow_blk = 128;
    const float* gin = in + (size_t)rowbase * K;
    // A: full 128 rows (zero-fill tail)
    for (int i = tid; i < 128 * K; i += 256) {
        int r = i / K;
        int c = i - r * K;
        float x = (r < nrow_blk) ? gin[i] : 0.f;
        __nv_bfloat16 hi = __float2bfloat16(x);
        __nv_bfloat16 lo = __float2bfloat16(x - __bfloat162float(hi));
        sAh[r * KP + c] = hi;
        sAl[r * KP + c] = lo;
    }
    // B = W^T : sB[n][k] = W[k][n]
    for (int i = tid; i < K * 128; i += 256) {
        int k = i >> 7;
        int n = i & 127;
        float x = W[i];
        __nv_bfloat16 hi = __float2bfloat16(x);
        __nv_bfloat16 lo = __float2bfloat16(x - __bfloat162float(hi));
        sBh[n * KP + k] = hi;
        sBl[n * KP + k] = lo;
    }
    __syncthreads();

    const int wid = tid >> 5;
    const int lane = tid & 31;
    const int m0 = wid * 16;

    float c[16][4];
#pragma unroll
    for (int nb = 0; nb < 16; nb++)
#pragma unroll
        for (int q = 0; q < 4; q++) c[nb][q] = 0.f;

    const uint32_t sAh0 = smem_u32(sAh), sAl0 = smem_u32(sAl);
    const uint32_t sBh0 = smem_u32(sBh), sBl0 = smem_u32(sBl);
    const int lrow = lane & 15;
    const int lcol = (lane >> 4) << 3;
    const uint32_t offA = (uint32_t)((m0 + lrow) * KP + lcol) * 2;

#pragma unroll 2
    for (int s = 0; s < K / 16; s++) {
        uint32_t ah[4], al[4];
        ldm_x4(ah, sAh0 + offA + s * 32);
        ldm_x4(al, sAl0 + offA + s * 32);
#pragma unroll
        for (int nbp = 0; nbp < 8; nbp++) {
            uint32_t offB = (uint32_t)((nbp * 16 + lrow) * KP + lcol) * 2 + s * 32;
            uint32_t bh[4], bl[4];
            ldm_x4(bh, sBh0 + offB);
            ldm_x4(bl, sBl0 + offB);
            mma_bf16(c[2 * nbp],     ah, bh[0], bh[2]);
            mma_bf16(c[2 * nbp],     ah, bl[0], bl[2]);
            mma_bf16(c[2 * nbp],     al, bh[0], bh[2]);
            mma_bf16(c[2 * nbp + 1], ah, bh[1], bh[3]);
            mma_bf16(c[2 * nbp + 1], ah, bl[1], bl[3]);
            mma_bf16(c[2 * nbp + 1], al, bh[1], bh[3]);
        }
    }

    // epilogue: thread t -> rows m0 + t/4 (+8), col pair nb*8 + 2*(t%4)
    const int r0 = rowbase + m0 + (lane >> 2);
    const int r1 = r0 + 8;
    const int cb = (lane & 3) * 2;
#pragma unroll
    for (int nb = 0; nb < 16; nb++) {
        int col = nb * 8 + cb;
        float2 v0, v1;
        v0.x = c[nb][0] + s_bias[col];
        v0.y = c[nb][1] + s_bias[col + 1];
        v1.x = c[nb][2] + s_bias[col];
        v1.y = c[nb][3] + s_bias[col + 1];
        if (do_relu) {
            v0.x = fmaxf(v0.x, 0.f); v0.y = fmaxf(v0.y, 0.f);
            v1.x = fmaxf(v1.x, 0.f); v1.y = fmaxf(v1.y, 0.f);
        }
        if (r0 < nrows) *(float2*)(out + (size_t)r0 * 128 + col) = v0;
        if (r1 < nrows) *(float2*)(out + (size_t)r1 * 128 + col) = v1;
    }
}

// ================= f32x2 FFMA2 GEMM (K=101 user linear) ======================
__device__ __forceinline__ unsigned long long dup2(float x) {
    unsigned long long r;
    unsigned int xi = __float_as_uint(x);
    asm("mov.b64 %0, {%1, %1};" : "=l"(r) : "r"(xi));
    return r;
}
__device__ __forceinline__ void ffma2(unsigned long long& d, unsigned long long a,
                                      unsigned long long b) {
    asm("fma.rn.f32x2 %0, %1, %2, %0;" : "+l"(d) : "l"(a), "l"(b));
}
__device__ __forceinline__ float2 u2f2(unsigned long long v) {
    float2 f;
    unsigned int lo, hi;
    asm("mov.b64 {%0, %1}, %2;" : "=r"(lo), "=r"(hi) : "l"(v));
    f.x = __uint_as_float(lo); f.y = __uint_as_float(hi);
    return f;
}

template<int K, int NOUT, int CPT, int RPT>
__global__ void __launch_bounds__(256, 1) gemm_kernel(
    const float* __restrict__ in, const float* __restrict__ W,
    const float* __restrict__ bias, float* __restrict__ out,
    int nrows, int do_relu)
{
    constexpr int CG = NOUT / CPT;
    constexpr int RG = 256 / CG;
    constexpr int RB = RG * RPT;
    constexpr int KP = (K & 1) ? K : (K + 1);
    constexpr int CP2 = CPT / 2;

    extern __shared__ float sm[];
    float* s_in = sm;
    float* s_w  = sm + RB * KP;
    __shared__ float s_b[NOUT];

    const int tid = threadIdx.x;
    const int rowbase = blockIdx.x * RB;

    for (int i = tid; i < K * NOUT; i += 256) s_w[i] = W[i];
    if (tid < NOUT) s_b[tid] = bias[tid];

    int nrow_blk = nrows - rowbase; if (nrow_blk > RB) nrow_blk = RB;
    const float* gin = in + (size_t)rowbase * K;
    for (int i = tid; i < nrow_blk * K; i += 256) {
        int r = i / K;
        int k = i - r * K;
        s_in[r * KP + k] = gin[i];
    }
    __syncthreads();

    const int cg = tid / RG;
    const int rg = tid - cg * RG;

    unsigned long long acc[RPT][CP2];
#pragma unroll
    for (int j = 0; j < RPT; j++)
#pragma unroll
        for (int c = 0; c < CP2; c++) acc[j][c] = 0ULL;

    const float* xbase = s_in + rg * KP;
    const float* wbase = s_w + cg * CPT;

#pragma unroll 8
    for (int k = 0; k < K; k++) {
        unsigned long long xd[RPT];
#pragma unroll
        for (int j = 0; j < RPT; j++) xd[j] = dup2(xbase[j * RG * KP + k]);
        const unsigned long long* wrow = (const unsigned long long*)(wbase + k * NOUT);
#pragma unroll
        for (int c = 0; c < CP2; c++) {
            unsigned long long wv = wrow[c];
#pragma unroll
            for (int j = 0; j < RPT; j++) ffma2(acc[j][c], xd[j], wv);
        }
    }

#pragma unroll
    for (int j = 0; j < RPT; j++) {
        int row = rowbase + rg + j * RG;
        if (row < nrows) {
            float* orow = out + (size_t)row * NOUT + cg * CPT;
#pragma unroll
            for (int c = 0; c < CP2; c++) {
                float2 f = u2f2(acc[j][c]);
                float v0 = f.x + s_b[cg * CPT + 2 * c];
                float v1 = f.y + s_b[cg * CPT + 2 * c + 1];
                if (do_relu) { v0 = fmaxf(v0, 0.f); v1 = fmaxf(v1, 0.f); }
                float2 o; o.x = v0; o.y = v1;
                ((float2*)orow)[c] = o;
            }
        }
    }
}

// ---------------- trivial item linear ----------------
__global__ void item_lin_kernel(const float* __restrict__ fx, const float* __restrict__ w,
                                const float* __restrict__ b, float* __restrict__ out, int ni)
{
    int i = blockIdx.x * blockDim.x + threadIdx.x;
    if (i < ni * 32) {
        int r = i >> 5, c = i & 31;
        out[i] = fmaf(fx[r], w[c], b[c]);
    }
}

// ---------------- CSR build ----------------
__global__ void count_kernel(const int* __restrict__ src, const int* __restrict__ dst,
                             int* __restrict__ c1, int* __restrict__ c2, int E)
{
    int i = blockIdx.x * blockDim.x + threadIdx.x;
    if (i < E) {
        atomicAdd(&c1[dst[i]], 1);
        atomicAdd(&c2[src[i]], 1);
    }
}

// two exclusive scans in one launch (single block)
__global__ void scan2_kernel(const int* __restrict__ cA, int* __restrict__ oA, int* __restrict__ uA, int nA,
                             const int* __restrict__ cB, int* __restrict__ oB, int* __restrict__ uB, int nB)
{
    __shared__ int wsum[32];
    __shared__ int s_carry;
    int tid = threadIdx.x;
    for (int seg = 0; seg < 2; seg++) {
        const int* cnt = seg ? cB : cA;
        int* off = seg ? oB : oA;
        int* cur = seg ? uB : uA;
        int n = seg ? nB : nA;
        if (tid == 0) s_carry = 0;
        __syncthreads();
        int nquad = (n + 3) >> 2;
        for (int base = 0; base < nquad; base += 1024) {
            int qi = base + tid;
            int4 v = make_int4(0, 0, 0, 0);
            if (qi < nquad) {
                int i0 = qi << 2;
                if (i0 + 3 < n) v = ((const int4*)cnt)[qi];
                else {
                    v.x = cnt[i0];
                    if (i0 + 1 < n) v.y = cnt[i0 + 1];
                    if (i0 + 2 < n) v.z = cnt[i0 + 2];
                }
            }
            int tsum = v.x + v.y + v.z + v.w;
            int x = tsum;
#pragma unroll
            for (int d = 1; d < 32; d <<= 1) {
                int y = __shfl_up_sync(0xffffffffu, x, d);
                if ((tid & 31) >= d) x += y;
            }
            if ((tid & 31) == 31) wsum[tid >> 5] = x;
            __syncthreads();
            if (tid < 32) {
                int w = wsum[tid];
#pragma unroll
                for (int d = 1; d < 32; d <<= 1) {
                    int y = __shfl_up_sync(0xffffffffu, w, d);
                    if (tid >= d) w += y;
                }
                wsum[tid] = w;
            }
            __syncthreads();
            int wo = (tid >= 32) ? wsum[(tid >> 5) - 1] : 0;
            int excl = s_carry + wo + x - tsum;
            if (qi < nquad) {
                int i0 = qi << 2;
                int e0 = excl, e1 = e0 + v.x, e2 = e1 + v.y, e3 = e2 + v.z;
                off[i0] = e0; cur[i0] = e0;
                if (i0 + 1 < n) { off[i0 + 1] = e1; cur[i0 + 1] = e1; }
                if (i0 + 2 < n) { off[i0 + 2] = e2; cur[i0 + 2] = e2; }
                if (i0 + 3 < n) { off[i0 + 3] = e3; cur[i0 + 3] = e3; }
            }
            __syncthreads();
            if (tid == 0) s_carry += wsum[31];
            __syncthreads();
        }
    }
}

// scatter: CSR slots + CSR-ordered other-endpoint + CSR-ordered edge attrs
__global__ void scatter_kernel(const int* __restrict__ src, const int* __restrict__ dst,
                               const float* __restrict__ eattr,
                               int* __restrict__ cur1, int* __restrict__ cur2,
                               int* __restrict__ oth1, int* __restrict__ oth2,
                               float4* __restrict__ ea1, int E)
{
    int i = blockIdx.x * blockDim.x + threadIdx.x;
    if (i < E) {
        int s = src[i], d = dst[i];
        int p1 = atomicAdd(&cur1[d], 1);
        oth1[p1] = s;
        float a0 = eattr[(size_t)i * 3];
        float a1 = eattr[(size_t)i * 3 + 1];
        float a2 = eattr[(size_t)i * 3 + 2];
        ea1[p1] = make_float4(a0, a1, a2, 0.f);
        int p2 = atomicAdd(&cur2[s], 1);
        oth2[p2] = d;
    }
}

// ---------------- fused GATv2 conv: online softmax + aggregation --------------
// warp per destination node; lane owns 4 channels (head = lane>>3).
// Single pass over edges: logit -> running max/sum/accumulator (flash-style).
__global__ void gat_conv_kernel(
    const float* __restrict__ xl,      // [n_src,128] source-side projections
    const float* __restrict__ xr,      // [n_dst,128] dest-side projections
    const int* __restrict__ off, const int* __restrict__ cnt,
    const int* __restrict__ other,     // CSR-ordered source indices
    const float4* __restrict__ ea,     // CSR-ordered edge attrs or null
    const float* __restrict__ we,      // [3,128] or null
    const float* __restrict__ att,     // [4,32] flattened
    const float* __restrict__ bias, float* __restrict__ out,
    int n, int do_relu)
{
    __shared__ int    s_o[8][32];
    __shared__ float4 s_ea[8][32];

    const int lane = threadIdx.x & 31;
    const int wrp = threadIdx.x >> 5;
    const int node = blockIdx.x * 8 + wrp;
    if (node >= n) return;

    float4 att4 = ((const float4*)att)[lane];
    float4 bias4 = ((const float4*)bias)[lane];
    const int start = off[node];
    const int m = cnt[node];

    if (m == 0) {
        float4 o = bias4;
        if (do_relu) {
            o.x = fmaxf(o.x, 0.f); o.y = fmaxf(o.y, 0.f);
            o.z = fmaxf(o.z, 0.f); o.w = fmaxf(o.w, 0.f);
        }
        ((float4*)(out + (size_t)node * 128))[lane] = o;
        return;
    }

    float4 we0 = make_float4(0, 0, 0, 0), we1 = we0, we2 = we0;
    if (we) {
        we0 = ((const float4*)we)[lane];
        we1 = ((const float4*)(we + 128))[lane];
        we2 = ((const float4*)(we + 256))[lane];
    }
    float4 xr4 = __ldg((const float4*)(xr + (size_t)node * 128) + lane);

    float M = __int_as_float(0xff800000u);   // -inf
    float ssum = 0.f;
    float4 a = make_float4(0.f, 0.f, 0.f, 0.f);

    for (int base = 0; base < m; base += 32) {
        int i = base + lane;
        if (i < m) {
            s_o[wrp][lane] = __ldg(other + start + i);
            if (ea) s_ea[wrp][lane] = __ldg(ea + start + i);
        }
        __syncwarp();
        int lim = m - base; if (lim > 32) lim = 32;
        for (int j = 0; j < lim; j++) {
            int srcn = s_o[wrp][j];
            float4 xs = __ldg((const float4*)(xl + (size_t)srcn * 128) + lane);
            float4 m4;
            m4.x = xs.x + xr4.x; m4.y = xs.y + xr4.y;
            m4.z = xs.z + xr4.z; m4.w = xs.w + xr4.w;
            if (ea) {
                float4 e = s_ea[wrp][j];
                m4.x = fmaf(e.x, we0.x, fmaf(e.y, we1.x, fmaf(e.z, we2.x, m4.x)));
                m4.y = fmaf(e.x, we0.y, fmaf(e.y, we1.y, fmaf(e.z, we2.y, m4.y)));
                m4.z = fmaf(e.x, we0.z, fmaf(e.y, we1.z, fmaf(e.z, we2.z, m4.z)));
                m4.w = fmaf(e.x, we0.w, fmaf(e.y, we1.w, fmaf(e.z, we2.w, m4.w)));
            }
            float g0 = fmaxf(m4.x, 0.2f * m4.x);
            float g1 = fmaxf(m4.y, 0.2f * m4.y);
            float g2 = fmaxf(m4.z, 0.2f * m4.z);
            float g3 = fmaxf(m4.w, 0.2f * m4.w);
            float t = g0 * att4.x + g1 * att4.y + g2 * att4.z + g3 * att4.w;
            // head logit: reduce across 8-lane group
            t += __shfl_xor_sync(0xffffffffu, t, 1);
            t += __shfl_xor_sync(0xffffffffu, t, 2);
            t += __shfl_xor_sync(0xffffffffu, t, 4);
            // online softmax update (per head; all lanes of group identical state)
            float Mn = fmaxf(M, t);
            float corr = __expf(M - Mn);       // first iter: exp(-inf)=0
            float p = __expf(t - Mn);
            ssum = ssum * corr + p;
            a.x = fmaf(a.x, corr, p * xs.x);
            a.y = fmaf(a.y, corr, p * xs.y);
            a.z = fmaf(a.z, corr, p * xs.z);
            a.w = fmaf(a.w, corr, p * xs.w);
            M = Mn;
        }
        __syncwarp();
    }

    float inv = 1.f / (ssum + 1e-16f);
    float4 o;
    o.x = fmaf(a.x, inv, bias4.x);
    o.y = fmaf(a.y, inv, bias4.y);
    o.z = fmaf(a.z, inv, bias4.z);
    o.w = fmaf(a.w, inv, bias4.w);
    if (do_relu) {
        o.x = fmaxf(o.x, 0.f); o.y = fmaxf(o.y, 0.f);
        o.z = fmaxf(o.z, 0.f); o.w = fmaxf(o.w, 0.f);
    }
    ((float4*)(out + (size_t)node * 128))[lane] = o;
}

// ---------------- host launch ----------------
extern "C" void kernel_launch(void* const* d_in, const int* in_sizes, int n_in,
                              void* d_out, int out_size)
{
    (void)n_in; (void)out_size;
    const float* customer_x = (const float*)d_in[0];
    const float* fund_x     = (const float*)d_in[1];
    const float* edge_attr  = (const float*)d_in[2];
    const float* user_lin_w = (const float*)d_in[3];
    const float* user_lin_b = (const float*)d_in[4];
    const float* item_lin_w = (const float*)d_in[5];
    const float* item_lin_b = (const float*)d_in[6];
    const float* conv1_wl   = (const float*)d_in[7];
    const float* conv1_bl   = (const float*)d_in[8];
    const float* conv1_wr   = (const float*)d_in[9];
    const float* conv1_br   = (const float*)d_in[10];
    const float* conv1_we   = (const float*)d_in[11];
    const float* conv1_att  = (const float*)d_in[12];
    const float* conv1_bias = (const float*)d_in[13];
    const float* conv2_wl   = (const float*)d_in[14];
    const float* conv2_bl   = (const float*)d_in[15];
    const float* conv2_wr   = (const float*)d_in[16];
    const float* conv2_br   = (const float*)d_in[17];
    const float* conv2_att  = (const float*)d_in[18];
    const float* conv2_bias = (const float*)d_in[19];
    const float* proj_w1    = (const float*)d_in[20];
    const float* proj_b1    = (const float*)d_in[21];
    const float* proj_w2    = (const float*)d_in[22];
    const float* proj_b2    = (const float*)d_in[23];
    const int*   edge_src   = (const int*)d_in[24];
    const int*   edge_dst   = (const int*)d_in[25];

    const int Nu = in_sizes[0] / 101;
    const int Ni = in_sizes[1];
    const int E  = in_sizes[24];

    float *user_x, *item_x, *xl1, *xr1, *xr2, *item2, *xl2, *hid;
    int *deg, *off, *cur, *oth1, *oth2;
    float4* ea1;
    cudaGetSymbolAddress((void**)&user_x, g_user_x);
    cudaGetSymbolAddress((void**)&item_x, g_item_x);
    cudaGetSymbolAddress((void**)&xl1,    g_xl1);
    cudaGetSymbolAddress((void**)&xr1,    g_xr1);
    cudaGetSymbolAddress((void**)&xr2,    g_xr2);
    cudaGetSymbolAddress((void**)&item2,  g_item2);
    cudaGetSymbolAddress((void**)&xl2,    g_xl2);
    cudaGetSymbolAddress((void**)&hid,    g_hid);
    cudaGetSymbolAddress((void**)&deg,    g_deg);
    cudaGetSymbolAddress((void**)&off,    g_off);
    cudaGetSymbolAddress((void**)&cur,    g_cur);
    cudaGetSymbolAddress((void**)&oth1,   g_oth1);
    cudaGetSymbolAddress((void**)&oth2,   g_oth2);
    cudaGetSymbolAddress((void**)&ea1,    g_ea1);

    int *cnt1 = deg, *cnt2 = deg + NI_MAX;
    int *off1 = off, *off2 = off + NI_MAX;
    int *cur1 = cur, *cur2 = cur + NI_MAX;

    const int smemUser  = (128 * 101 + 101 * 32) * 4;            // gemm<101,32,8,2>
    const int smemMM32  = 4 * 128 * (32 + 8) * 2;                // mma_gemm<32>   (40960)
    const int smemMM128 = 4 * 128 * (128 + 8) * 2;               // mma_gemm<128> (139264)
    cudaFuncSetAttribute(gemm_kernel<101, 32, 8, 2>, cudaFuncAttributeMaxDynamicSharedMemorySize, smemUser);
    cudaFuncSetAttribute(mma_gemm<32>,  cudaFuncAttributeMaxDynamicSharedMemorySize, smemMM32);
    cudaFuncSetAttribute(mma_gemm<128>, cudaFuncAttributeMaxDynamicSharedMemorySize, smemMM128);

    float* user_out = (float*)d_out;             // [Nu,128]
    float* z        = user_out + (size_t)Nu * 128;

    // 1: memset combined degree array
    cudaMemsetAsync(deg, 0, (NI_MAX + Nu) * sizeof(int));
    // 2-4: CSR build
    count_kernel<<<(E + 255) / 256, 256>>>(edge_src, edge_dst, cnt1, cnt2, E);
    scan2_kernel<<<1, 1024>>>(cnt1, off1, cur1, Ni, cnt2, off2, cur2, Nu);
    scatter_kernel<<<(E + 255) / 256, 256>>>(edge_src, edge_dst, edge_attr,
                                             cur1, cur2, oth1, oth2, ea1, E);
    // 5: user linear (K=101, FFMA2)
    gemm_kernel<101, 32, 8, 2><<<(Nu + 127) / 128, 256, smemUser>>>(customer_x, user_lin_w, user_lin_b, user_x, Nu, 0);
    // 6: mma_gemm<32> xl1  (ncu capture lands here)
    mma_gemm<32><<<(Nu + 127) / 128, 256, smemMM32>>>(user_x, conv1_wl, conv1_bl, xl1, Nu, 0);
    // 7: item linear
    item_lin_kernel<<<(Ni * 32 + 255) / 256, 256>>>(fund_x, item_lin_w, item_lin_b, item_x, Ni);
    // 8-9: remaining projections
    mma_gemm<32><<<(Nu + 127) / 128, 256, smemMM32>>>(user_x, conv2_wr, conv2_br, xr2, Nu, 0);
    mma_gemm<32><<<(Ni + 127) / 128, 256, smemMM32>>>(item_x, conv1_wr, conv1_br, xr1, Ni, 0);

    // conv1: user -> item (fused logits+softmax+aggregate, online)
    gat_conv_kernel<<<(Ni + 7) / 8, 256>>>(xl1, xr1, off1, cnt1, oth1, ea1, conv1_we,
                                           conv1_att, conv1_bias, item2, Ni, 1);

    // conv2: item -> user (flipped edges, no edge_attr)
    mma_gemm<128><<<(Ni + 127) / 128, 256, smemMM128>>>(item2, conv2_wl, conv2_bl, xl2, Ni, 0);
    gat_conv_kernel<<<(Nu + 7) / 8, 256>>>(xl2, xr2, off2, cnt2, oth2, nullptr, nullptr,
                                           conv2_att, conv2_bias, user_out, Nu, 0);

    // final MLP
    mma_gemm<128><<<(Nu + 127) / 128, 256, smemMM128>>>(user_out, proj_w1, proj_b1, hid, Nu, 1);
    mma_gemm<128><<<(Nu + 127) / 128, 256, smemMM128>>>(hid, proj_w2, proj_b2, z, Nu, 0);
}

// round 6
// speedup vs baseline: 1.8079x; 1.0014x over previous
#include <cuda_runtime.h>
#include <cuda_bf16.h>
#include <cstdint>

#define NU_MAX 200000
#define NI_MAX 20000
#define NE_MAX 1000000

// ---------------- scratch (device globals; no allocation allowed) -------------
__device__ float  g_user_x[NU_MAX * 32];
__device__ float  g_item_x[NI_MAX * 32];
__device__ float  g_xl1[NU_MAX * 128];
__device__ float  g_xr1[NI_MAX * 128];
__device__ float  g_xr2[NU_MAX * 128];
__device__ float  g_item2[NI_MAX * 128];
__device__ float  g_xl2[NI_MAX * 128];
__device__ float  g_hid[NU_MAX * 128];
__device__ int    g_deg[NI_MAX + NU_MAX]; // cnt1 | cnt2 (one memset)
__device__ int    g_off[NI_MAX + NU_MAX];
__device__ int    g_cur[NI_MAX + NU_MAX];
__device__ int    g_oth1[NE_MAX];         // CSR(dst)-ordered src for conv1
__device__ int    g_oth2[NE_MAX];         // CSR(src)-ordered dst for conv2
__device__ float4 g_ea1[NE_MAX];          // CSR(dst)-ordered edge_attr (conv1)

// ================= helpers =================
__device__ __forceinline__ uint32_t smem_u32(const void* p) {
    uint32_t a;
    asm("{ .reg .u64 t; cvta.to.shared.u64 t, %1; cvt.u32.u64 %0, t; }" : "=r"(a) : "l"(p));
    return a;
}
__device__ __forceinline__ void ldm_x4(uint32_t* r, uint32_t addr) {
    asm volatile("ldmatrix.sync.aligned.m8n8.x4.shared.b16 {%0,%1,%2,%3}, [%4];"
                 : "=r"(r[0]), "=r"(r[1]), "=r"(r[2]), "=r"(r[3]) : "r"(addr));
}
__device__ __forceinline__ void mma_bf16(float* c, const uint32_t* a, uint32_t b0, uint32_t b1) {
    asm volatile("mma.sync.aligned.m16n8k16.row.col.f32.bf16.bf16.f32 "
                 "{%0,%1,%2,%3}, {%4,%5,%6,%7}, {%8,%9}, {%0,%1,%2,%3};"
                 : "+f"(c[0]), "+f"(c[1]), "+f"(c[2]), "+f"(c[3])
                 : "r"(a[0]), "r"(a[1]), "r"(a[2]), "r"(a[3]), "r"(b0), "r"(b1));
}

// ---------------- HMMA GEMM: out[nrows,128] = in[nrows,K] @ W[K,128] + b ------
// bf16 hi/lo split (3 terms), fp32 accumulate. Block = 128 rows x 128 cols,
// 8 warps, each warp 16 rows x 128 cols. Padded smem stride -> conflict-free
// ldmatrix (stride 4r mod 32 distinct).
template<int K>
__global__ void __launch_bounds__(256) mma_gemm(
    const float* __restrict__ in, const float* __restrict__ W,
    const float* __restrict__ bias, float* __restrict__ out,
    int nrows, int do_relu)
{
    constexpr int KP = K + 8;                // padded bf16 row stride
    constexpr int TILE = 128 * KP;           // elements per bf16 tile

    extern __shared__ __nv_bfloat16 smbf[];
    __nv_bfloat16* sAh = smbf;
    __nv_bfloat16* sAl = sAh + TILE;
    __nv_bfloat16* sBh = sAl + TILE;
    __nv_bfloat16* sBl = sBh + TILE;
    __shared__ float s_bias[128];

    const int tid = threadIdx.x;
    const int rowbase = blockIdx.x * 128;
    if (tid < 128) s_bias[tid] = bias[tid];

    int nrow_blk = nrows - rowbase; if (nrow_blk > 128) nrow_blk = 128;
    const float* gin = in + (size_t)rowbase * K;
    // A: full 128 rows (zero-fill tail)
    for (int i = tid; i < 128 * K; i += 256) {
        int r = i / K;
        int c = i - r * K;
        float x = (r < nrow_blk) ? gin[i] : 0.f;
        __nv_bfloat16 hi = __float2bfloat16(x);
        __nv_bfloat16 lo = __float2bfloat16(x - __bfloat162float(hi));
        sAh[r * KP + c] = hi;
        sAl[r * KP + c] = lo;
    }
    // B = W^T : sB[n][k] = W[k][n]
    for (int i = tid; i < K * 128; i += 256) {
        int k = i >> 7;
        int n = i & 127;
        float x = W[i];
        __nv_bfloat16 hi = __float2bfloat16(x);
        __nv_bfloat16 lo = __float2bfloat16(x - __bfloat162float(hi));
        sBh[n * KP + k] = hi;
        sBl[n * KP + k] = lo;
    }
    __syncthreads();

    const int wid = tid >> 5;
    const int lane = tid & 31;
    const int m0 = wid * 16;

    float c[16][4];
#pragma unroll
    for (int nb = 0; nb < 16; nb++)
#pragma unroll
        for (int q = 0; q < 4; q++) c[nb][q] = 0.f;

    const uint32_t sAh0 = smem_u32(sAh), sAl0 = smem_u32(sAl);
    const uint32_t sBh0 = smem_u32(sBh), sBl0 = smem_u32(sBl);
    const int lrow = lane & 15;
    const int lcol = (lane >> 4) << 3;
    const uint32_t offA = (uint32_t)((m0 + lrow) * KP + lcol) * 2;

#pragma unroll 2
    for (int s = 0; s < K / 16; s++) {
        uint32_t ah[4], al[4];
        ldm_x4(ah, sAh0 + offA + s * 32);
        ldm_x4(al, sAl0 + offA + s * 32);
#pragma unroll
        for (int nbp = 0; nbp < 8; nbp++) {
            uint32_t offB = (uint32_t)((nbp * 16 + lrow) * KP + lcol) * 2 + s * 32;
            uint32_t bh[4], bl[4];
            ldm_x4(bh, sBh0 + offB);
            ldm_x4(bl, sBl0 + offB);
            mma_bf16(c[2 * nbp],     ah, bh[0], bh[2]);
            mma_bf16(c[2 * nbp],     ah, bl[0], bl[2]);
            mma_bf16(c[2 * nbp],     al, bh[0], bh[2]);
            mma_bf16(c[2 * nbp + 1], ah, bh[1], bh[3]);
            mma_bf16(c[2 * nbp + 1], ah, bl[1], bl[3]);
            mma_bf16(c[2 * nbp + 1], al, bh[1], bh[3]);
        }
    }

    // epilogue: thread t -> rows m0 + t/4 (+8), col pair nb*8 + 2*(t%4)
    const int r0 = rowbase + m0 + (lane >> 2);
    const int r1 = r0 + 8;
    const int cb = (lane & 3) * 2;
#pragma unroll
    for (int nb = 0; nb < 16; nb++) {
        int col = nb * 8 + cb;
        float2 v0, v1;
        v0.x = c[nb][0] + s_bias[col];
        v0.y = c[nb][1] + s_bias[col + 1];
        v1.x = c[nb][2] + s_bias[col];
        v1.y = c[nb][3] + s_bias[col + 1];
        if (do_relu) {
            v0.x = fmaxf(v0.x, 0.f); v0.y = fmaxf(v0.y, 0.f);
            v1.x = fmaxf(v1.x, 0.f); v1.y = fmaxf(v1.y, 0.f);
        }
        if (r0 < nrows) *(float2*)(out + (size_t)r0 * 128 + col) = v0;
        if (r1 < nrows) *(float2*)(out + (size_t)r1 * 128 + col) = v1;
    }
}

// ================= f32x2 FFMA2 GEMM (K=101 user linear) ======================
__device__ __forceinline__ unsigned long long dup2(float x) {
    unsigned long long r;
    unsigned int xi = __float_as_uint(x);
    asm("mov.b64 %0, {%1, %1};" : "=l"(r) : "r"(xi));
    return r;
}
__device__ __forceinline__ void ffma2(unsigned long long& d, unsigned long long a,
                                      unsigned long long b) {
    asm("fma.rn.f32x2 %0, %1, %2, %0;" : "+l"(d) : "l"(a), "l"(b));
}
__device__ __forceinline__ float2 u2f2(unsigned long long v) {
    float2 f;
    unsigned int lo, hi;
    asm("mov.b64 {%0, %1}, %2;" : "=r"(lo), "=r"(hi) : "l"(v));
    f.x = __uint_as_float(lo); f.y = __uint_as_float(hi);
    return f;
}

template<int K, int NOUT, int CPT, int RPT>
__global__ void __launch_bounds__(256, 1) gemm_kernel(
    const float* __restrict__ in, const float* __restrict__ W,
    const float* __restrict__ bias, float* __restrict__ out,
    int nrows, int do_relu)
{
    constexpr int CG = NOUT / CPT;
    constexpr int RG = 256 / CG;
    constexpr int RB = RG * RPT;
    constexpr int KP = (K & 1) ? K : (K + 1);
    constexpr int CP2 = CPT / 2;

    extern __shared__ float sm[];
    float* s_in = sm;
    float* s_w  = sm + RB * KP;
    __shared__ float s_b[NOUT];

    const int tid = threadIdx.x;
    const int rowbase = blockIdx.x * RB;

    for (int i = tid; i < K * NOUT; i += 256) s_w[i] = W[i];
    if (tid < NOUT) s_b[tid] = bias[tid];

    int nrow_blk = nrows - rowbase; if (nrow_blk > RB) nrow_blk = RB;
    const float* gin = in + (size_t)rowbase * K;
    for (int i = tid; i < nrow_blk * K; i += 256) {
        int r = i / K;
        int k = i - r * K;
        s_in[r * KP + k] = gin[i];
    }
    __syncthreads();

    const int cg = tid / RG;
    const int rg = tid - cg * RG;

    unsigned long long acc[RPT][CP2];
#pragma unroll
    for (int j = 0; j < RPT; j++)
#pragma unroll
        for (int c = 0; c < CP2; c++) acc[j][c] = 0ULL;

    const float* xbase = s_in + rg * KP;
    const float* wbase = s_w + cg * CPT;

#pragma unroll 8
    for (int k = 0; k < K; k++) {
        unsigned long long xd[RPT];
#pragma unroll
        for (int j = 0; j < RPT; j++) xd[j] = dup2(xbase[j * RG * KP + k]);
        const unsigned long long* wrow = (const unsigned long long*)(wbase + k * NOUT);
#pragma unroll
        for (int c = 0; c < CP2; c++) {
            unsigned long long wv = wrow[c];
#pragma unroll
            for (int j = 0; j < RPT; j++) ffma2(acc[j][c], xd[j], wv);
        }
    }

#pragma unroll
    for (int j = 0; j < RPT; j++) {
        int row = rowbase + rg + j * RG;
        if (row < nrows) {
            float* orow = out + (size_t)row * NOUT + cg * CPT;
#pragma unroll
            for (int c = 0; c < CP2; c++) {
                float2 f = u2f2(acc[j][c]);
                float v0 = f.x + s_b[cg * CPT + 2 * c];
                float v1 = f.y + s_b[cg * CPT + 2 * c + 1];
                if (do_relu) { v0 = fmaxf(v0, 0.f); v1 = fmaxf(v1, 0.f); }
                float2 o; o.x = v0; o.y = v1;
                ((float2*)orow)[c] = o;
            }
        }
    }
}

// ---------------- trivial item linear ----------------
__global__ void item_lin_kernel(const float* __restrict__ fx, const float* __restrict__ w,
                                const float* __restrict__ b, float* __restrict__ out, int ni)
{
    int i = blockIdx.x * blockDim.x + threadIdx.x;
    if (i < ni * 32) {
        int r = i >> 5, c = i & 31;
        out[i] = fmaf(fx[r], w[c], b[c]);
    }
}

// ---------------- CSR build ----------------
__global__ void count_kernel(const int* __restrict__ src, const int* __restrict__ dst,
                             int* __restrict__ c1, int* __restrict__ c2, int E)
{
    int i = blockIdx.x * blockDim.x + threadIdx.x;
    if (i < E) {
        atomicAdd(&c1[dst[i]], 1);
        atomicAdd(&c2[src[i]], 1);
    }
}

// two exclusive scans in one launch (single block)
__global__ void scan2_kernel(const int* __restrict__ cA, int* __restrict__ oA, int* __restrict__ uA, int nA,
                             const int* __restrict__ cB, int* __restrict__ oB, int* __restrict__ uB, int nB)
{
    __shared__ int wsum[32];
    __shared__ int s_carry;
    int tid = threadIdx.x;
    for (int seg = 0; seg < 2; seg++) {
        const int* cnt = seg ? cB : cA;
        int* off = seg ? oB : oA;
        int* cur = seg ? uB : uA;
        int n = seg ? nB : nA;
        if (tid == 0) s_carry = 0;
        __syncthreads();
        int nquad = (n + 3) >> 2;
        for (int base = 0; base < nquad; base += 1024) {
            int qi = base + tid;
            int4 v = make_int4(0, 0, 0, 0);
            if (qi < nquad) {
                int i0 = qi << 2;
                if (i0 + 3 < n) v = ((const int4*)cnt)[qi];
                else {
                    v.x = cnt[i0];
                    if (i0 + 1 < n) v.y = cnt[i0 + 1];
                    if (i0 + 2 < n) v.z = cnt[i0 + 2];
                }
            }
            int tsum = v.x + v.y + v.z + v.w;
            int x = tsum;
#pragma unroll
            for (int d = 1; d < 32; d <<= 1) {
                int y = __shfl_up_sync(0xffffffffu, x, d);
                if ((tid & 31) >= d) x += y;
            }
            if ((tid & 31) == 31) wsum[tid >> 5] = x;
            __syncthreads();
            if (tid < 32) {
                int w = wsum[tid];
#pragma unroll
                for (int d = 1; d < 32; d <<= 1) {
                    int y = __shfl_up_sync(0xffffffffu, w, d);
                    if (tid >= d) w += y;
                }
                wsum[tid] = w;
            }
            __syncthreads();
            int wo = (tid >= 32) ? wsum[(tid >> 5) - 1] : 0;
            int excl = s_carry + wo + x - tsum;
            if (qi < nquad) {
                int i0 = qi << 2;
                int e0 = excl, e1 = e0 + v.x, e2 = e1 + v.y, e3 = e2 + v.z;
                off[i0] = e0; cur[i0] = e0;
                if (i0 + 1 < n) { off[i0 + 1] = e1; cur[i0 + 1] = e1; }
                if (i0 + 2 < n) { off[i0 + 2] = e2; cur[i0 + 2] = e2; }
                if (i0 + 3 < n) { off[i0 + 3] = e3; cur[i0 + 3] = e3; }
            }
            __syncthreads();
            if (tid == 0) s_carry += wsum[31];
            __syncthreads();
        }
    }
}

// scatter: CSR slots + CSR-ordered other-endpoint + CSR-ordered edge attrs
__global__ void scatter_kernel(const int* __restrict__ src, const int* __restrict__ dst,
                               const float* __restrict__ eattr,
                               int* __restrict__ cur1, int* __restrict__ cur2,
                               int* __restrict__ oth1, int* __restrict__ oth2,
                               float4* __restrict__ ea1, int E)
{
    int i = blockIdx.x * blockDim.x + threadIdx.x;
    if (i < E) {
        int s = src[i], d = dst[i];
        int p1 = atomicAdd(&cur1[d], 1);
        oth1[p1] = s;
        float a0 = eattr[(size_t)i * 3];
        float a1 = eattr[(size_t)i * 3 + 1];
        float a2 = eattr[(size_t)i * 3 + 2];
        ea1[p1] = make_float4(a0, a1, a2, 0.f);
        int p2 = atomicAdd(&cur2[s], 1);
        oth2[p2] = d;
    }
}

// ---------------- fused GATv2 conv: online softmax + aggregation --------------
// warp per destination node; lane owns 4 channels (head = lane>>3).
// Single pass over edges: logit -> running max/sum/accumulator (flash-style).
__global__ void gat_conv_kernel(
    const float* __restrict__ xl,      // [n_src,128] source-side projections
    const float* __restrict__ xr,      // [n_dst,128] dest-side projections
    const int* __restrict__ off, const int* __restrict__ cnt,
    const int* __restrict__ other,     // CSR-ordered source indices
    const float4* __restrict__ ea,     // CSR-ordered edge attrs or null
    const float* __restrict__ we,      // [3,128] or null
    const float* __restrict__ att,     // [4,32] flattened
    const float* __restrict__ bias, float* __restrict__ out,
    int n, int do_relu)
{
    __shared__ int    s_o[8][32];
    __shared__ float4 s_ea[8][32];

    const int lane = threadIdx.x & 31;
    const int wrp = threadIdx.x >> 5;
    const int node = blockIdx.x * 8 + wrp;
    if (node >= n) return;

    float4 att4 = ((const float4*)att)[lane];
    float4 bias4 = ((const float4*)bias)[lane];
    const int start = off[node];
    const int m = cnt[node];

    if (m == 0) {
        float4 o = bias4;
        if (do_relu) {
            o.x = fmaxf(o.x, 0.f); o.y = fmaxf(o.y, 0.f);
            o.z = fmaxf(o.z, 0.f); o.w = fmaxf(o.w, 0.f);
        }
        ((float4*)(out + (size_t)node * 128))[lane] = o;
        return;
    }

    float4 we0 = make_float4(0, 0, 0, 0), we1 = we0, we2 = we0;
    if (we) {
        we0 = ((const float4*)we)[lane];
        we1 = ((const float4*)(we + 128))[lane];
        we2 = ((const float4*)(we + 256))[lane];
    }
    float4 xr4 = __ldg((const float4*)(xr + (size_t)node * 128) + lane);

    float M = __int_as_float(0xff800000u);   // -inf
    float ssum = 0.f;
    float4 a = make_float4(0.f, 0.f, 0.f, 0.f);

    for (int base = 0; base < m; base += 32) {
        int i = base + lane;
        if (i < m) {
            s_o[wrp][lane] = __ldg(other + start + i);
            if (ea) s_ea[wrp][lane] = __ldg(ea + start + i);
        }
        __syncwarp();
        int lim = m - base; if (lim > 32) lim = 32;
        for (int j = 0; j < lim; j++) {
            int srcn = s_o[wrp][j];
            float4 xs = __ldg((const float4*)(xl + (size_t)srcn * 128) + lane);
            float4 m4;
            m4.x = xs.x + xr4.x; m4.y = xs.y + xr4.y;
            m4.z = xs.z + xr4.z; m4.w = xs.w + xr4.w;
            if (ea) {
                float4 e = s_ea[wrp][j];
                m4.x = fmaf(e.x, we0.x, fmaf(e.y, we1.x, fmaf(e.z, we2.x, m4.x)));
                m4.y = fmaf(e.x, we0.y, fmaf(e.y, we1.y, fmaf(e.z, we2.y, m4.y)));
                m4.z = fmaf(e.x, we0.z, fmaf(e.y, we1.z, fmaf(e.z, we2.z, m4.z)));
                m4.w = fmaf(e.x, we0.w, fmaf(e.y, we1.w, fmaf(e.z, we2.w, m4.w)));
            }
            float g0 = fmaxf(m4.x, 0.2f * m4.x);
            float g1 = fmaxf(m4.y, 0.2f * m4.y);
            float g2 = fmaxf(m4.z, 0.2f * m4.z);
            float g3 = fmaxf(m4.w, 0.2f * m4.w);
            float t = g0 * att4.x + g1 * att4.y + g2 * att4.z + g3 * att4.w;
            // head logit: reduce across 8-lane group
            t += __shfl_xor_sync(0xffffffffu, t, 1);
            t += __shfl_xor_sync(0xffffffffu, t, 2);
            t += __shfl_xor_sync(0xffffffffu, t, 4);
            // online softmax update (per head; all lanes of group identical state)
            float Mn = fmaxf(M, t);
            float corr = __expf(M - Mn);       // first iter: exp(-inf)=0
            float p = __expf(t - Mn);
            ssum = ssum * corr + p;
            a.x = fmaf(a.x, corr, p * xs.x);
            a.y = fmaf(a.y, corr, p * xs.y);
            a.z = fmaf(a.z, corr, p * xs.z);
            a.w = fmaf(a.w, corr, p * xs.w);
            M = Mn;
        }
        __syncwarp();
    }

    float inv = 1.f / (ssum + 1e-16f);
    float4 o;
    o.x = fmaf(a.x, inv, bias4.x);
    o.y = fmaf(a.y, inv, bias4.y);
    o.z = fmaf(a.z, inv, bias4.z);
    o.w = fmaf(a.w, inv, bias4.w);
    if (do_relu) {
        o.x = fmaxf(o.x, 0.f); o.y = fmaxf(o.y, 0.f);
        o.z = fmaxf(o.z, 0.f); o.w = fmaxf(o.w, 0.f);
    }
    ((float4*)(out + (size_t)node * 128))[lane] = o;
}

// ---------------- host launch ----------------
extern "C" void kernel_launch(void* const* d_in, const int* in_sizes, int n_in,
                              void* d_out, int out_size)
{
    (void)n_in; (void)out_size;
    const float* customer_x = (const float*)d_in[0];
    const float* fund_x     = (const float*)d_in[1];
    const float* edge_attr  = (const float*)d_in[2];
    const float* user_lin_w = (const float*)d_in[3];
    const float* user_lin_b = (const float*)d_in[4];
    const float* item_lin_w = (const float*)d_in[5];
    const float* item_lin_b = (const float*)d_in[6];
    const float* conv1_wl   = (const float*)d_in[7];
    const float* conv1_bl   = (const float*)d_in[8];
    const float* conv1_wr   = (const float*)d_in[9];
    const float* conv1_br   = (const float*)d_in[10];
    const float* conv1_we   = (const float*)d_in[11];
    const float* conv1_att  = (const float*)d_in[12];
    const float* conv1_bias = (const float*)d_in[13];
    const float* conv2_wl   = (const float*)d_in[14];
    const float* conv2_bl   = (const float*)d_in[15];
    const float* conv2_wr   = (const float*)d_in[16];
    const float* conv2_br   = (const float*)d_in[17];
    const float* conv2_att  = (const float*)d_in[18];
    const float* conv2_bias = (const float*)d_in[19];
    const float* proj_w1    = (const float*)d_in[20];
    const float* proj_b1    = (const float*)d_in[21];
    const float* proj_w2    = (const float*)d_in[22];
    const float* proj_b2    = (const float*)d_in[23];
    const int*   edge_src   = (const int*)d_in[24];
    const int*   edge_dst   = (const int*)d_in[25];

    const int Nu = in_sizes[0] / 101;
    const int Ni = in_sizes[1];
    const int E  = in_sizes[24];

    float *user_x, *item_x, *xl1, *xr1, *xr2, *item2, *xl2, *hid;
    int *deg, *off, *cur, *oth1, *oth2;
    float4* ea1;
    cudaGetSymbolAddress((void**)&user_x, g_user_x);
    cudaGetSymbolAddress((void**)&item_x, g_item_x);
    cudaGetSymbolAddress((void**)&xl1,    g_xl1);
    cudaGetSymbolAddress((void**)&xr1,    g_xr1);
    cudaGetSymbolAddress((void**)&xr2,    g_xr2);
    cudaGetSymbolAddress((void**)&item2,  g_item2);
    cudaGetSymbolAddress((void**)&xl2,    g_xl2);
    cudaGetSymbolAddress((void**)&hid,    g_hid);
    cudaGetSymbolAddress((void**)&deg,    g_deg);
    cudaGetSymbolAddress((void**)&off,    g_off);
    cudaGetSymbolAddress((void**)&cur,    g_cur);
    cudaGetSymbolAddress((void**)&oth1,   g_oth1);
    cudaGetSymbolAddress((void**)&oth2,   g_oth2);
    cudaGetSymbolAddress((void**)&ea1,    g_ea1);

    int *cnt1 = deg, *cnt2 = deg + NI_MAX;
    int *off1 = off, *off2 = off + NI_MAX;
    int *cur1 = cur, *cur2 = cur + NI_MAX;

    const int smemUser  = (128 * 101 + 101 * 32) * 4;            // gemm<101,32,8,2>
    const int smemMM32  = 4 * 128 * (32 + 8) * 2;                // mma_gemm<32>   (40960)
    const int smemMM128 = 4 * 128 * (128 + 8) * 2;               // mma_gemm<128> (139264)
    cudaFuncSetAttribute(gemm_kernel<101, 32, 8, 2>, cudaFuncAttributeMaxDynamicSharedMemorySize, smemUser);
    cudaFuncSetAttribute(mma_gemm<32>,  cudaFuncAttributeMaxDynamicSharedMemorySize, smemMM32);
    cudaFuncSetAttribute(mma_gemm<128>, cudaFuncAttributeMaxDynamicSharedMemorySize, smemMM128);

    float* user_out = (float*)d_out;             // [Nu,128]
    float* z        = user_out + (size_t)Nu * 128;

    // 1: memset combined degree array
    cudaMemsetAsync(deg, 0, (NI_MAX + Nu) * sizeof(int));
    // 2-4: CSR build
    count_kernel<<<(E + 255) / 256, 256>>>(edge_src, edge_dst, cnt1, cnt2, E);
    scan2_kernel<<<1, 1024>>>(cnt1, off1, cur1, Ni, cnt2, off2, cur2, Nu);
    scatter_kernel<<<(E + 255) / 256, 256>>>(edge_src, edge_dst, edge_attr,
                                             cur1, cur2, oth1, oth2, ea1, E);
    // 5: user linear (K=101, FFMA2)
    gemm_kernel<101, 32, 8, 2><<<(Nu + 127) / 128, 256, smemUser>>>(customer_x, user_lin_w, user_lin_b, user_x, Nu, 0);
    // 6: mma_gemm<32> xl1  (ncu capture lands here)
    mma_gemm<32><<<(Nu + 127) / 128, 256, smemMM32>>>(user_x, conv1_wl, conv1_bl, xl1, Nu, 0);
    // 7: item linear
    item_lin_kernel<<<(Ni * 32 + 255) / 256, 256>>>(fund_x, item_lin_w, item_lin_b, item_x, Ni);
    // 8-9: remaining projections
    mma_gemm<32><<<(Nu + 127) / 128, 256, smemMM32>>>(user_x, conv2_wr, conv2_br, xr2, Nu, 0);
    mma_gemm<32><<<(Ni + 127) / 128, 256, smemMM32>>>(item_x, conv1_wr, conv1_br, xr1, Ni, 0);

    // conv1: user -> item (fused logits+softmax+aggregate, online)
    gat_conv_kernel<<<(Ni + 7) / 8, 256>>>(xl1, xr1, off1, cnt1, oth1, ea1, conv1_we,
                                           conv1_att, conv1_bias, item2, Ni, 1);

    // conv2: item -> user (flipped edges, no edge_attr)
    mma_gemm<128><<<(Ni + 127) / 128, 256, smemMM128>>>(item2, conv2_wl, conv2_bl, xl2, Ni, 0);
    gat_conv_kernel<<<(Nu + 7) / 8, 256>>>(xl2, xr2, off2, cnt2, oth2, nullptr, nullptr,
                                           conv2_att, conv2_bias, user_out, Nu, 0);

    // final MLP
    mma_gemm<128><<<(Nu + 127) / 128, 256, smemMM128>>>(user_out, proj_w1, proj_b1, hid, Nu, 1);
    mma_gemm<128><<<(Nu + 127) / 128, 256, smemMM128>>>(hid, proj_w2, proj_b2, z, Nu, 0);
}

// round 7
// speedup vs baseline: 2.1345x; 1.1806x over previous
#include <cuda_runtime.h>
#include <cuda_bf16.h>
#include <cstdint>

#define NU_MAX 200000
#define NI_MAX 20000
#define NE_MAX 1000000

// ---------------- scratch (device globals; no allocation allowed) -------------
__device__ float  g_user_x[NU_MAX * 32];
__device__ float  g_item_x[NI_MAX * 32];
__device__ float  g_xl1[NU_MAX * 128];
__device__ float  g_xr1[NI_MAX * 128];
__device__ float  g_xr2[NU_MAX * 128];
__device__ float  g_item2[NI_MAX * 128];
__device__ float  g_xl2[NI_MAX * 128];
__device__ float  g_hid[NU_MAX * 128];
__device__ int    g_deg[NI_MAX + NU_MAX]; // cnt1 | cnt2 (one memset)
__device__ int2   g_offcnt[NI_MAX + NU_MAX];
__device__ int    g_cur[NI_MAX + NU_MAX];
__device__ int    g_oth1[NE_MAX];         // CSR(dst)-ordered src for conv1
__device__ int    g_oth2[NE_MAX];         // CSR(src)-ordered dst for conv2
__device__ float4 g_ea1[NE_MAX];          // CSR(dst)-ordered edge_attr (conv1)

// ================= helpers =================
__device__ __forceinline__ uint32_t smem_u32(const void* p) {
    uint32_t a;
    asm("{ .reg .u64 t; cvta.to.shared.u64 t, %1; cvt.u32.u64 %0, t; }" : "=r"(a) : "l"(p));
    return a;
}
__device__ __forceinline__ void ldm_x4(uint32_t* r, uint32_t addr) {
    asm volatile("ldmatrix.sync.aligned.m8n8.x4.shared.b16 {%0,%1,%2,%3}, [%4];"
                 : "=r"(r[0]), "=r"(r[1]), "=r"(r[2]), "=r"(r[3]) : "r"(addr));
}
__device__ __forceinline__ void mma_bf16(float* c, const uint32_t* a, uint32_t b0, uint32_t b1) {
    asm volatile("mma.sync.aligned.m16n8k16.row.col.f32.bf16.bf16.f32 "
                 "{%0,%1,%2,%3}, {%4,%5,%6,%7}, {%8,%9}, {%0,%1,%2,%3};"
                 : "+f"(c[0]), "+f"(c[1]), "+f"(c[2]), "+f"(c[3])
                 : "r"(a[0]), "r"(a[1]), "r"(a[2]), "r"(a[3]), "r"(b0), "r"(b1));
}
__device__ __forceinline__ uint32_t pack_bf(__nv_bfloat16 a, __nv_bfloat16 b) {
    return (uint32_t)__bfloat16_as_ushort(a) | ((uint32_t)__bfloat16_as_ushort(b) << 16);
}

// ---------------- HMMA GEMM: out[nrows,128] = in[nrows,K] @ W[K,128] + b ------
// bf16 hi/lo split (3 terms), fp32 accumulate. Block = 128 rows x 128 cols,
// 8 warps x (16 rows x 128 cols). K chunked (CHUNK<=64) so smem fits 2 blocks/SM.
template<int K>
__global__ void __launch_bounds__(256, 2) mma_gemm(
    const float* __restrict__ in, const float* __restrict__ W,
    const float* __restrict__ bias, float* __restrict__ out,
    int nrows, int do_relu)
{
    constexpr int CHUNK = (K < 64) ? K : 64;
    constexpr int NCH = K / CHUNK;
    constexpr int KP = CHUNK + 8;            // padded bf16 row stride
    constexpr int TILE = 128 * KP;
    constexpr int QPR = CHUNK / 4;           // float4 quads per row chunk (8 or 16)

    extern __shared__ __nv_bfloat16 smbf[];
    __nv_bfloat16* sAh = smbf;
    __nv_bfloat16* sAl = sAh + TILE;
    __nv_bfloat16* sBh = sAl + TILE;
    __nv_bfloat16* sBl = sBh + TILE;
    __shared__ float s_bias[128];

    const int tid = threadIdx.x;
    const int rowbase = blockIdx.x * 128;
    if (tid < 128) s_bias[tid] = bias[tid];

    int nrow_blk = nrows - rowbase; if (nrow_blk > 128) nrow_blk = 128;

    const int wid = tid >> 5;
    const int lane = tid & 31;
    const int m0 = wid * 16;
    const int lrow = lane & 15;
    const int lcol = (lane >> 4) << 3;

    float c[16][4];
#pragma unroll
    for (int nb = 0; nb < 16; nb++)
#pragma unroll
        for (int q = 0; q < 4; q++) c[nb][q] = 0.f;

    const uint32_t sAh0 = smem_u32(sAh), sAl0 = smem_u32(sAl);
    const uint32_t sBh0 = smem_u32(sBh), sBl0 = smem_u32(sBl);
    const uint32_t offA = (uint32_t)((m0 + lrow) * KP + lcol) * 2;

#pragma unroll
    for (int ch = 0; ch < NCH; ch++) {
        if (ch) __syncthreads();   // previous chunk's MMAs done before overwrite

        // A chunk: 128 rows x CHUNK cols, vectorized float4
        const float* gin = in + (size_t)rowbase * K + ch * CHUNK;
        for (int q = tid; q < 128 * QPR; q += 256) {
            int r = q / QPR;                  // QPR power of 2 -> shift
            int c4 = (q - r * QPR) * 4;
            float4 v = (r < nrow_blk) ? *(const float4*)(gin + (size_t)r * K + c4)
                                      : make_float4(0.f, 0.f, 0.f, 0.f);
            __nv_bfloat16 h0 = __float2bfloat16(v.x), h1 = __float2bfloat16(v.y);
            __nv_bfloat16 h2 = __float2bfloat16(v.z), h3 = __float2bfloat16(v.w);
            __nv_bfloat16 l0 = __float2bfloat16(v.x - __bfloat162float(h0));
            __nv_bfloat16 l1 = __float2bfloat16(v.y - __bfloat162float(h1));
            __nv_bfloat16 l2 = __float2bfloat16(v.z - __bfloat162float(h2));
            __nv_bfloat16 l3 = __float2bfloat16(v.w - __bfloat162float(h3));
            uint32_t* ph = (uint32_t*)(sAh + r * KP + c4);
            uint32_t* pl = (uint32_t*)(sAl + r * KP + c4);
            ph[0] = pack_bf(h0, h1); ph[1] = pack_bf(h2, h3);
            pl[0] = pack_bf(l0, l1); pl[1] = pack_bf(l2, l3);
        }
        // B chunk = W^T : sB[n][k] = W[ch*CHUNK+k][n]
        for (int i = tid; i < CHUNK * 128; i += 256) {
            int k = i >> 7;
            int n = i & 127;
            float x = W[(size_t)(ch * CHUNK + k) * 128 + n];
            __nv_bfloat16 hi = __float2bfloat16(x);
            __nv_bfloat16 lo = __float2bfloat16(x - __bfloat162float(hi));
            sBh[n * KP + k] = hi;
            sBl[n * KP + k] = lo;
        }
        __syncthreads();

#pragma unroll
        for (int s = 0; s < CHUNK / 16; s++) {
            uint32_t ah[4], al[4];
            ldm_x4(ah, sAh0 + offA + s * 32);
            ldm_x4(al, sAl0 + offA + s * 32);
#pragma unroll
            for (int nbp = 0; nbp < 8; nbp++) {
                uint32_t offB = (uint32_t)((nbp * 16 + lrow) * KP + lcol) * 2 + s * 32;
                uint32_t bh[4], bl[4];
                ldm_x4(bh, sBh0 + offB);
                ldm_x4(bl, sBl0 + offB);
                mma_bf16(c[2 * nbp],     ah, bh[0], bh[2]);
                mma_bf16(c[2 * nbp],     ah, bl[0], bl[2]);
                mma_bf16(c[2 * nbp],     al, bh[0], bh[2]);
                mma_bf16(c[2 * nbp + 1], ah, bh[1], bh[3]);
                mma_bf16(c[2 * nbp + 1], ah, bl[1], bl[3]);
                mma_bf16(c[2 * nbp + 1], al, bh[1], bh[3]);
            }
        }
    }

    // epilogue: thread -> rows m0 + lane/4 (+8), col pair nb*8 + 2*(lane%3)
    const int r0 = rowbase + m0 + (lane >> 2);
    const int r1 = r0 + 8;
    const int cb = (lane & 3) * 2;
#pragma unroll
    for (int nb = 0; nb < 16; nb++) {
        int col = nb * 8 + cb;
        float2 v0, v1;
        v0.x = c[nb][0] + s_bias[col];
        v0.y = c[nb][1] + s_bias[col + 1];
        v1.x = c[nb][2] + s_bias[col];
        v1.y = c[nb][3] + s_bias[col + 1];
        if (do_relu) {
            v0.x = fmaxf(v0.x, 0.f); v0.y = fmaxf(v0.y, 0.f);
            v1.x = fmaxf(v1.x, 0.f); v1.y = fmaxf(v1.y, 0.f);
        }
        if (r0 < nrows) *(float2*)(out + (size_t)r0 * 128 + col) = v0;
        if (r1 < nrows) *(float2*)(out + (size_t)r1 * 128 + col) = v1;
    }
}

// ================= f32x2 FFMA2 GEMM (K=101 user linear) ======================
__device__ __forceinline__ unsigned long long dup2(float x) {
    unsigned long long r;
    unsigned int xi = __float_as_uint(x);
    asm("mov.b64 %0, {%1, %1};" : "=l"(r) : "r"(xi));
    return r;
}
__device__ __forceinline__ void ffma2(unsigned long long& d, unsigned long long a,
                                      unsigned long long b) {
    asm("fma.rn.f32x2 %0, %1, %2, %0;" : "+l"(d) : "l"(a), "l"(b));
}
__device__ __forceinline__ float2 u2f2(unsigned long long v) {
    float2 f;
    unsigned int lo, hi;
    asm("mov.b64 {%0, %1}, %2;" : "=r"(lo), "=r"(hi) : "l"(v));
    f.x = __uint_as_float(lo); f.y = __uint_as_float(hi);
    return f;
}

template<int K, int NOUT, int CPT, int RPT>
__global__ void __launch_bounds__(256) gemm_kernel(
    const float* __restrict__ in, const float* __restrict__ W,
    const float* __restrict__ bias, float* __restrict__ out,
    int nrows, int do_relu)
{
    constexpr int CG = NOUT / CPT;
    constexpr int RG = 256 / CG;
    constexpr int RB = RG * RPT;
    constexpr int KP = (K & 1) ? K : (K + 1);
    constexpr int CP2 = CPT / 2;

    extern __shared__ float sm[];
    float* s_in = sm;
    float* s_w  = sm + RB * KP;
    __shared__ float s_b[NOUT];

    const int tid = threadIdx.x;
    const int rowbase = blockIdx.x * RB;

    for (int i = tid; i < K * NOUT; i += 256) s_w[i] = W[i];
    if (tid < NOUT) s_b[tid] = bias[tid];

    int nrow_blk = nrows - rowbase; if (nrow_blk > RB) nrow_blk = RB;
    const float* gin = in + (size_t)rowbase * K;
    for (int i = tid; i < nrow_blk * K; i += 256) {
        int r = i / K;
        int k = i - r * K;
        s_in[r * KP + k] = gin[i];
    }
    __syncthreads();

    const int cg = tid / RG;
    const int rg = tid - cg * RG;

    unsigned long long acc[RPT][CP2];
#pragma unroll
    for (int j = 0; j < RPT; j++)
#pragma unroll
        for (int c = 0; c < CP2; c++) acc[j][c] = 0ULL;

    const float* xbase = s_in + rg * KP;
    const float* wbase = s_w + cg * CPT;

#pragma unroll 8
    for (int k = 0; k < K; k++) {
        unsigned long long xd[RPT];
#pragma unroll
        for (int j = 0; j < RPT; j++) xd[j] = dup2(xbase[j * RG * KP + k]);
        const unsigned long long* wrow = (const unsigned long long*)(wbase + k * NOUT);
#pragma unroll
        for (int c = 0; c < CP2; c++) {
            unsigned long long wv = wrow[c];
#pragma unroll
            for (int j = 0; j < RPT; j++) ffma2(acc[j][c], xd[j], wv);
        }
    }

#pragma unroll
    for (int j = 0; j < RPT; j++) {
        int row = rowbase + rg + j * RG;
        if (row < nrows) {
            float* orow = out + (size_t)row * NOUT + cg * CPT;
#pragma unroll
            for (int c = 0; c < CP2; c++) {
                float2 f = u2f2(acc[j][c]);
                float v0 = f.x + s_b[cg * CPT + 2 * c];
                float v1 = f.y + s_b[cg * CPT + 2 * c + 1];
                if (do_relu) { v0 = fmaxf(v0, 0.f); v1 = fmaxf(v1, 0.f); }
                float2 o; o.x = v0; o.y = v1;
                ((float2*)orow)[c] = o;
            }
        }
    }
}

// ---------------- trivial item linear ----------------
__global__ void item_lin_kernel(const float* __restrict__ fx, const float* __restrict__ w,
                                const float* __restrict__ b, float* __restrict__ out, int ni)
{
    int i = blockIdx.x * blockDim.x + threadIdx.x;
    if (i < ni * 32) {
        int r = i >> 5, c = i & 31;
        out[i] = fmaf(fx[r], w[c], b[c]);
    }
}

// ---------------- CSR build ----------------
__global__ void count_kernel(const int* __restrict__ src, const int* __restrict__ dst,
                             int* __restrict__ c1, int* __restrict__ c2, int E)
{
    int i = blockIdx.x * blockDim.x + threadIdx.x;
    if (i < E) {
        atomicAdd(&c1[dst[i]], 1);
        atomicAdd(&c2[src[i]], 1);
    }
}

// two exclusive scans in one launch (single block); writes packed (off,cnt)
__global__ void scan2_kernel(const int* __restrict__ cA, int2* __restrict__ oA, int* __restrict__ uA, int nA,
                             const int* __restrict__ cB, int2* __restrict__ oB, int* __restrict__ uB, int nB)
{
    __shared__ int wsum[32];
    __shared__ int s_carry;
    int tid = threadIdx.x;
    for (int seg = 0; seg < 2; seg++) {
        const int* cnt = seg ? cB : cA;
        int2* off = seg ? oB : oA;
        int* cur = seg ? uB : uA;
        int n = seg ? nB : nA;
        if (tid == 0) s_carry = 0;
        __syncthreads();
        int nquad = (n + 3) >> 2;
        for (int base = 0; base < nquad; base += 1024) {
            int qi = base + tid;
            int4 v = make_int4(0, 0, 0, 0);
            if (qi < nquad) {
                int i0 = qi << 2;
                if (i0 + 3 < n) v = ((const int4*)cnt)[qi];
                else {
                    v.x = cnt[i0];
                    if (i0 + 1 < n) v.y = cnt[i0 + 1];
                    if (i0 + 2 < n) v.z = cnt[i0 + 2];
                }
            }
            int tsum = v.x + v.y + v.z + v.w;
            int x = tsum;
#pragma unroll
            for (int d = 1; d < 32; d <<= 1) {
                int y = __shfl_up_sync(0xffffffffu, x, d);
                if ((tid & 31) >= d) x += y;
            }
            if ((tid & 31) == 31) wsum[tid >> 5] = x;
            __syncthreads();
            if (tid < 32) {
                int w = wsum[tid];
#pragma unroll
                for (int d = 1; d < 32; d <<= 1) {
                    int y = __shfl_up_sync(0xffffffffu, w, d);
                    if (tid >= d) w += y;
                }
                wsum[tid] = w;
            }
            __syncthreads();
            int wo = (tid >= 32) ? wsum[(tid >> 5) - 1] : 0;
            int excl = s_carry + wo + x - tsum;
            if (qi < nquad) {
                int i0 = qi << 2;
                int e0 = excl, e1 = e0 + v.x, e2 = e1 + v.y, e3 = e2 + v.z;
                off[i0] = make_int2(e0, v.x); cur[i0] = e0;
                if (i0 + 1 < n) { off[i0 + 1] = make_int2(e1, v.y); cur[i0 + 1] = e1; }
                if (i0 + 2 < n) { off[i0 + 2] = make_int2(e2, v.z); cur[i0 + 2] = e2; }
                if (i0 + 3 < n) { off[i0 + 3] = make_int2(e3, v.w); cur[i0 + 3] = e3; }
            }
            __syncthreads();
            if (tid == 0) s_carry += wsum[31];
            __syncthreads();
        }
    }
}

// scatter: CSR slots + CSR-ordered other-endpoint + CSR-ordered edge attrs
__global__ void scatter_kernel(const int* __restrict__ src, const int* __restrict__ dst,
                               const float* __restrict__ eattr,
                               int* __restrict__ cur1, int* __restrict__ cur2,
                               int* __restrict__ oth1, int* __restrict__ oth2,
                               float4* __restrict__ ea1, int E)
{
    int i = blockIdx.x * blockDim.x + threadIdx.x;
    if (i < E) {
        int s = src[i], d = dst[i];
        int p1 = atomicAdd(&cur1[d], 1);
        oth1[p1] = s;
        float a0 = eattr[(size_t)i * 3];
        float a1 = eattr[(size_t)i * 3 + 1];
        float a2 = eattr[(size_t)i * 3 + 2];
        ea1[p1] = make_float4(a0, a1, a2, 0.f);
        int p2 = atomicAdd(&cur2[s], 1);
        oth2[p2] = d;
    }
}

// ---------------- fused GATv2 conv: online softmax + aggregation --------------
// warp per destination node; lane owns 4 channels (head = lane>>3).
// Dual even/odd softmax chains shorten the serial dependency per edge.
struct Chain { float M, S; float4 A; };

__device__ __forceinline__ void chain_update(
    Chain& ch, float t, const float4& xs)
{
    float Mn = fmaxf(ch.M, t);
    float corr = __expf(ch.M - Mn);
    float p = __expf(t - Mn);
    ch.S = ch.S * corr + p;
    ch.A.x = fmaf(ch.A.x, corr, p * xs.x);
    ch.A.y = fmaf(ch.A.y, corr, p * xs.y);
    ch.A.z = fmaf(ch.A.z, corr, p * xs.z);
    ch.A.w = fmaf(ch.A.w, corr, p * xs.w);
    ch.M = Mn;
}

__global__ void gat_conv_kernel(
    const float* __restrict__ xl,      // [n_src,128]
    const float* __restrict__ xr,      // [n_dst,128]
    const int2* __restrict__ offcnt,
    const int* __restrict__ other,     // CSR-ordered source indices
    const float4* __restrict__ ea,     // CSR-ordered edge attrs or null
    const float* __restrict__ we,      // [3,128] or null
    const float* __restrict__ att,     // [4,32] flattened
    const float* __restrict__ bias, float* __restrict__ out,
    int n, int do_relu)
{
    __shared__ int    s_o[8][32];
    __shared__ float4 s_ea[8][32];

    const int lane = threadIdx.x & 31;
    const int wrp = threadIdx.x >> 5;
    const int node = blockIdx.x * 8 + wrp;
    if (node >= n) return;

    float4 att4 = ((const float4*)att)[lane];
    float4 bias4 = ((const float4*)bias)[lane];
    int2 oc = __ldg(offcnt + node);
    const int start = oc.x;
    const int m = oc.y;

    if (m == 0) {
        float4 o = bias4;
        if (do_relu) {
            o.x = fmaxf(o.x, 0.f); o.y = fmaxf(o.y, 0.f);
            o.z = fmaxf(o.z, 0.f); o.w = fmaxf(o.w, 0.f);
        }
        ((float4*)(out + (size_t)node * 128))[lane] = o;
        return;
    }

    float4 we0 = make_float4(0, 0, 0, 0), we1 = we0, we2 = we0;
    if (we) {
        we0 = ((const float4*)we)[lane];
        we1 = ((const float4*)(we + 128))[lane];
        we2 = ((const float4*)(we + 256))[lane];
    }
    float4 xr4 = __ldg((const float4*)(xr + (size_t)node * 128) + lane);

    const float NEGINF = __int_as_float(0xff800000u);
    Chain c0, c1;
    c0.M = NEGINF; c0.S = 0.f; c0.A = make_float4(0.f, 0.f, 0.f, 0.f);
    c1 = c0;

    for (int base = 0; base < m; base += 32) {
        int i = base + lane;
        if (i < m) {
            s_o[wrp][lane] = __ldg(other + start + i);
            if (ea) s_ea[wrp][lane] = __ldg(ea + start + i);
        }
        __syncwarp();
        int lim = m - base; if (lim > 32) lim = 32;
        for (int j = 0; j < lim; j++) {
            int srcn = s_o[wrp][j];
            float4 xs = __ldg((const float4*)(xl + (size_t)srcn * 128) + lane);
            float4 m4;
            m4.x = xs.x + xr4.x; m4.y = xs.y + xr4.y;
            m4.z = xs.z + xr4.z; m4.w = xs.w + xr4.w;
            if (ea) {
                float4 e = s_ea[wrp][j];
                m4.x = fmaf(e.x, we0.x, fmaf(e.y, we1.x, fmaf(e.z, we2.x, m4.x)));
                m4.y = fmaf(e.x, we0.y, fmaf(e.y, we1.y, fmaf(e.z, we2.y, m4.y)));
                m4.z = fmaf(e.x, we0.z, fmaf(e.y, we1.z, fmaf(e.z, we2.z, m4.z)));
                m4.w = fmaf(e.x, we0.w, fmaf(e.y, we1.w, fmaf(e.z, we2.w, m4.w)));
            }
            float g0 = fmaxf(m4.x, 0.2f * m4.x);
            float g1 = fmaxf(m4.y, 0.2f * m4.y);
            float g2 = fmaxf(m4.z, 0.2f * m4.z);
            float g3 = fmaxf(m4.w, 0.2f * m4.w);
            float t = g0 * att4.x + g1 * att4.y + g2 * att4.z + g3 * att4.w;
            t += __shfl_xor_sync(0xffffffffu, t, 1);
            t += __shfl_xor_sync(0xffffffffu, t, 2);
            t += __shfl_xor_sync(0xffffffffu, t, 4);
            if (j & 1) chain_update(c1, t, xs);
            else       chain_update(c0, t, xs);
        }
        __syncwarp();
    }

    // merge chains (c1 empty when m==1: exp(-inf)=0 handles it)
    float Mn = fmaxf(c0.M, c1.M);
    float w0 = __expf(c0.M - Mn), w1 = __expf(c1.M - Mn);
    float ssum = c0.S * w0 + c1.S * w1;
    float4 a;
    a.x = c0.A.x * w0 + c1.A.x * w1;
    a.y = c0.A.y * w0 + c1.A.y * w1;
    a.z = c0.A.z * w0 + c1.A.z * w1;
    a.w = c0.A.w * w0 + c1.A.w * w1;

    float inv = 1.f / (ssum + 1e-16f);
    float4 o;
    o.x = fmaf(a.x, inv, bias4.x);
    o.y = fmaf(a.y, inv, bias4.y);
    o.z = fmaf(a.z, inv, bias4.z);
    o.w = fmaf(a.w, inv, bias4.w);
    if (do_relu) {
        o.x = fmaxf(o.x, 0.f); o.y = fmaxf(o.y, 0.f);
        o.z = fmaxf(o.z, 0.f); o.w = fmaxf(o.w, 0.f);
    }
    ((float4*)(out + (size_t)node * 128))[lane] = o;
}

// ---------------- host launch ----------------
extern "C" void kernel_launch(void* const* d_in, const int* in_sizes, int n_in,
                              void* d_out, int out_size)
{
    (void)n_in; (void)out_size;
    const float* customer_x = (const float*)d_in[0];
    const float* fund_x     = (const float*)d_in[1];
    const float* edge_attr  = (const float*)d_in[2];
    const float* user_lin_w = (const float*)d_in[3];
    const float* user_lin_b = (const float*)d_in[4];
    const float* item_lin_w = (const float*)d_in[5];
    const float* item_lin_b = (const float*)d_in[6];
    const float* conv1_wl   = (const float*)d_in[7];
    const float* conv1_bl   = (const float*)d_in[8];
    const float* conv1_wr   = (const float*)d_in[9];
    const float* conv1_br   = (const float*)d_in[10];
    const float* conv1_we   = (const float*)d_in[11];
    const float* conv1_att  = (const float*)d_in[12];
    const float* conv1_bias = (const float*)d_in[13];
    const float* conv2_wl   = (const float*)d_in[14];
    const float* conv2_bl   = (const float*)d_in[15];
    const float* conv2_wr   = (const float*)d_in[16];
    const float* conv2_br   = (const float*)d_in[17];
    const float* conv2_att  = (const float*)d_in[18];
    const float* conv2_bias = (const float*)d_in[19];
    const float* proj_w1    = (const float*)d_in[20];
    const float* proj_b1    = (const float*)d_in[21];
    const float* proj_w2    = (const float*)d_in[22];
    const float* proj_b2    = (const float*)d_in[23];
    const int*   edge_src   = (const int*)d_in[24];
    const int*   edge_dst   = (const int*)d_in[25];

    const int Nu = in_sizes[0] / 101;
    const int Ni = in_sizes[1];
    const int E  = in_sizes[24];

    float *user_x, *item_x, *xl1, *xr1, *xr2, *item2, *xl2, *hid;
    int *deg, *cur, *oth1, *oth2;
    int2* offcnt;
    float4* ea1;
    cudaGetSymbolAddress((void**)&user_x, g_user_x);
    cudaGetSymbolAddress((void**)&item_x, g_item_x);
    cudaGetSymbolAddress((void**)&xl1,    g_xl1);
    cudaGetSymbolAddress((void**)&xr1,    g_xr1);
    cudaGetSymbolAddress((void**)&xr2,    g_xr2);
    cudaGetSymbolAddress((void**)&item2,  g_item2);
    cudaGetSymbolAddress((void**)&xl2,    g_xl2);
    cudaGetSymbolAddress((void**)&hid,    g_hid);
    cudaGetSymbolAddress((void**)&deg,    g_deg);
    cudaGetSymbolAddress((void**)&offcnt, g_offcnt);
    cudaGetSymbolAddress((void**)&cur,    g_cur);
    cudaGetSymbolAddress((void**)&oth1,   g_oth1);
    cudaGetSymbolAddress((void**)&oth2,   g_oth2);
    cudaGetSymbolAddress((void**)&ea1,    g_ea1);

    int  *cnt1 = deg, *cnt2 = deg + NI_MAX;
    int2 *oc1 = offcnt, *oc2 = offcnt + NI_MAX;
    int  *cur1 = cur, *cur2 = cur + NI_MAX;

    const int smemUser  = (64 * 101 + 101 * 32) * 4;             // gemm<101,32,8,1>
    const int smemMM32  = 4 * 128 * (32 + 8) * 2;                // mma_gemm<32>   (40960)
    const int smemMM128 = 4 * 128 * (64 + 8) * 2;                // mma_gemm<128>  (73728)
    cudaFuncSetAttribute(gemm_kernel<101, 32, 8, 1>, cudaFuncAttributeMaxDynamicSharedMemorySize, smemUser);
    cudaFuncSetAttribute(mma_gemm<32>,  cudaFuncAttributeMaxDynamicSharedMemorySize, smemMM32);
    cudaFuncSetAttribute(mma_gemm<128>, cudaFuncAttributeMaxDynamicSharedMemorySize, smemMM128);

    float* user_out = (float*)d_out;             // [Nu,128]
    float* z        = user_out + (size_t)Nu * 128;

    // CSR build
    cudaMemsetAsync(deg, 0, (NI_MAX + Nu) * sizeof(int));
    count_kernel<<<(E + 255) / 256, 256>>>(edge_src, edge_dst, cnt1, cnt2, E);
    scan2_kernel<<<1, 1024>>>(cnt1, oc1, cur1, Ni, cnt2, oc2, cur2, Nu);
    scatter_kernel<<<(E + 255) / 256, 256>>>(edge_src, edge_dst, edge_attr,
                                             cur1, cur2, oth1, oth2, ea1, E);
    // user linear (K=101, FFMA2, RPT=1 for occupancy)
    gemm_kernel<101, 32, 8, 1><<<(Nu + 63) / 64, 256, smemUser>>>(customer_x, user_lin_w, user_lin_b, user_x, Nu, 0);
    // projections
    mma_gemm<32><<<(Nu + 127) / 128, 256, smemMM32>>>(user_x, conv1_wl, conv1_bl, xl1, Nu, 0);
    item_lin_kernel<<<(Ni * 32 + 255) / 256, 256>>>(fund_x, item_lin_w, item_lin_b, item_x, Ni);
    mma_gemm<32><<<(Nu + 127) / 128, 256, smemMM32>>>(user_x, conv2_wr, conv2_br, xr2, Nu, 0);
    mma_gemm<32><<<(Ni + 127) / 128, 256, smemMM32>>>(item_x, conv1_wr, conv1_br, xr1, Ni, 0);

    // conv1: user -> item (fused online softmax + aggregate)
    gat_conv_kernel<<<(Ni + 7) / 8, 256>>>(xl1, xr1, oc1, oth1, ea1, conv1_we,
                                           conv1_att, conv1_bias, item2, Ni, 1);

    // conv2: item -> user (flipped edges, no edge_attr)
    mma_gemm<128><<<(Ni + 127) / 128, 256, smemMM128>>>(item2, conv2_wl, conv2_bl, xl2, Ni, 0);
    gat_conv_kernel<<<(Nu + 7) / 8, 256>>>(xl2, xr2, oc2, oth2, nullptr, nullptr,
                                           conv2_att, conv2_bias, user_out, Nu, 0);

    // final MLP
    mma_gemm<128><<<(Nu + 127) / 128, 256, smemMM128>>>(user_out, proj_w1, proj_b1, hid, Nu, 1);
    mma_gemm<128><<<(Nu + 127) / 128, 256, smemMM128>>>(hid, proj_w2, proj_b2, z, Nu, 0);
}

// round 8
// speedup vs baseline: 2.1367x; 1.0011x over previous
#include <cuda_runtime.h>
#include <cuda_bf16.h>
#include <cstdint>

#define NU_MAX 200000
#define NI_MAX 20000
#define NE_MAX 1000000

// ---------------- scratch (device globals; no allocation allowed) -------------
__device__ float  g_user_x[NU_MAX * 32];
__device__ float  g_item_x[NI_MAX * 32];
__device__ float  g_xl1[NU_MAX * 128];
__device__ float  g_xr1[NI_MAX * 128];
__device__ float  g_xr2[NU_MAX * 128];
__device__ float  g_item2[NI_MAX * 128];
__device__ float  g_xl2[NI_MAX * 128];
__device__ float  g_hid[NU_MAX * 128];
__device__ int    g_deg[NI_MAX + NU_MAX]; // cnt1 | cnt2 (one memset)
__device__ int2   g_offcnt[NI_MAX + NU_MAX];
__device__ int    g_cur[NI_MAX + NU_MAX];
__device__ int    g_oth1[NE_MAX];         // CSR(dst)-ordered src for conv1
__device__ int    g_oth2[NE_MAX];         // CSR(src)-ordered dst for conv2
__device__ float4 g_ea1[NE_MAX];          // CSR(dst)-ordered edge_attr (conv1)

// ================= helpers =================
__device__ __forceinline__ uint32_t smem_u32(const void* p) {
    uint32_t a;
    asm("{ .reg .u64 t; cvta.to.shared.u64 t, %1; cvt.u32.u64 %0, t; }" : "=r"(a) : "l"(p));
    return a;
}
__device__ __forceinline__ void ldm_x4(uint32_t* r, uint32_t addr) {
    asm volatile("ldmatrix.sync.aligned.m8n8.x4.shared.b16 {%0,%1,%2,%3}, [%4];"
                 : "=r"(r[0]), "=r"(r[1]), "=r"(r[2]), "=r"(r[3]) : "r"(addr));
}
__device__ __forceinline__ void mma_bf16(float* c, const uint32_t* a, uint32_t b0, uint32_t b1) {
    asm volatile("mma.sync.aligned.m16n8k16.row.col.f32.bf16.bf16.f32 "
                 "{%0,%1,%2,%3}, {%4,%5,%6,%7}, {%8,%9}, {%0,%1,%2,%3};"
                 : "+f"(c[0]), "+f"(c[1]), "+f"(c[2]), "+f"(c[3])
                 : "r"(a[0]), "r"(a[1]), "r"(a[2]), "r"(a[3]), "r"(b0), "r"(b1));
}
__device__ __forceinline__ uint32_t pack_bf(__nv_bfloat16 a, __nv_bfloat16 b) {
    return (uint32_t)__bfloat16_as_ushort(a) | ((uint32_t)__bfloat16_as_ushort(b) << 16);
}

// ---------------- HMMA GEMM: out[nrows,128] = in[nrows,K] @ W[K,128] + b ------
// bf16 hi/lo split (3 terms), fp32 accumulate. Block = 128 rows x 128 cols,
// 8 warps x (16 rows x 128 cols). K chunked (CHUNK<=64) so smem fits 2 blocks/SM.
template<int K>
__global__ void __launch_bounds__(256, 2) mma_gemm(
    const float* __restrict__ in, const float* __restrict__ W,
    const float* __restrict__ bias, float* __restrict__ out,
    int nrows, int do_relu)
{
    constexpr int CHUNK = (K < 64) ? K : 64;
    constexpr int NCH = K / CHUNK;
    constexpr int KP = CHUNK + 8;            // padded bf16 row stride
    constexpr int TILE = 128 * KP;
    constexpr int QPR = CHUNK / 4;           // float4 quads per row chunk (8 or 16)

    extern __shared__ __nv_bfloat16 smbf[];
    __nv_bfloat16* sAh = smbf;
    __nv_bfloat16* sAl = sAh + TILE;
    __nv_bfloat16* sBh = sAl + TILE;
    __nv_bfloat16* sBl = sBh + TILE;
    __shared__ float s_bias[128];

    const int tid = threadIdx.x;
    const int rowbase = blockIdx.x * 128;
    if (tid < 128) s_bias[tid] = bias[tid];

    int nrow_blk = nrows - rowbase; if (nrow_blk > 128) nrow_blk = 128;

    const int wid = tid >> 5;
    const int lane = tid & 31;
    const int m0 = wid * 16;
    const int lrow = lane & 15;
    const int lcol = (lane >> 4) << 3;

    float c[16][4];
#pragma unroll
    for (int nb = 0; nb < 16; nb++)
#pragma unroll
        for (int q = 0; q < 4; q++) c[nb][q] = 0.f;

    const uint32_t sAh0 = smem_u32(sAh), sAl0 = smem_u32(sAl);
    const uint32_t sBh0 = smem_u32(sBh), sBl0 = smem_u32(sBl);
    const uint32_t offA = (uint32_t)((m0 + lrow) * KP + lcol) * 2;

#pragma unroll
    for (int ch = 0; ch < NCH; ch++) {
        if (ch) __syncthreads();   // previous chunk's MMAs done before overwrite

        // A chunk: 128 rows x CHUNK cols, vectorized float4
        const float* gin = in + (size_t)rowbase * K + ch * CHUNK;
        for (int q = tid; q < 128 * QPR; q += 256) {
            int r = q / QPR;                  // QPR power of 2 -> shift
            int c4 = (q - r * QPR) * 4;
            float4 v = (r < nrow_blk) ? *(const float4*)(gin + (size_t)r * K + c4)
                                      : make_float4(0.f, 0.f, 0.f, 0.f);
            __nv_bfloat16 h0 = __float2bfloat16(v.x), h1 = __float2bfloat16(v.y);
            __nv_bfloat16 h2 = __float2bfloat16(v.z), h3 = __float2bfloat16(v.w);
            __nv_bfloat16 l0 = __float2bfloat16(v.x - __bfloat162float(h0));
            __nv_bfloat16 l1 = __float2bfloat16(v.y - __bfloat162float(h1));
            __nv_bfloat16 l2 = __float2bfloat16(v.z - __bfloat162float(h2));
            __nv_bfloat16 l3 = __float2bfloat16(v.w - __bfloat162float(h3));
            uint32_t* ph = (uint32_t*)(sAh + r * KP + c4);
            uint32_t* pl = (uint32_t*)(sAl + r * KP + c4);
            ph[0] = pack_bf(h0, h1); ph[1] = pack_bf(h2, h3);
            pl[0] = pack_bf(l0, l1); pl[1] = pack_bf(l2, l3);
        }
        // B chunk = W^T : sB[n][k] = W[ch*CHUNK+k][n]
        for (int i = tid; i < CHUNK * 128; i += 256) {
            int k = i >> 7;
            int n = i & 127;
            float x = W[(size_t)(ch * CHUNK + k) * 128 + n];
            __nv_bfloat16 hi = __float2bfloat16(x);
            __nv_bfloat16 lo = __float2bfloat16(x - __bfloat162float(hi));
            sBh[n * KP + k] = hi;
            sBl[n * KP + k] = lo;
        }
        __syncthreads();

#pragma unroll
        for (int s = 0; s < CHUNK / 16; s++) {
            uint32_t ah[4], al[4];
            ldm_x4(ah, sAh0 + offA + s * 32);
            ldm_x4(al, sAl0 + offA + s * 32);
#pragma unroll
            for (int nbp = 0; nbp < 8; nbp++) {
                uint32_t offB = (uint32_t)((nbp * 16 + lrow) * KP + lcol) * 2 + s * 32;
                uint32_t bh[4], bl[4];
                ldm_x4(bh, sBh0 + offB);
                ldm_x4(bl, sBl0 + offB);
                mma_bf16(c[2 * nbp],     ah, bh[0], bh[2]);
                mma_bf16(c[2 * nbp],     ah, bl[0], bl[2]);
                mma_bf16(c[2 * nbp],     al, bh[0], bh[2]);
                mma_bf16(c[2 * nbp + 1], ah, bh[1], bh[3]);
                mma_bf16(c[2 * nbp + 1], ah, bl[1], bl[3]);
                mma_bf16(c[2 * nbp + 1], al, bh[1], bh[3]);
            }
        }
    }

    // epilogue: thread -> rows m0 + lane/4 (+8), col pair nb*8 + 2*(lane%3)
    const int r0 = rowbase + m0 + (lane >> 2);
    const int r1 = r0 + 8;
    const int cb = (lane & 3) * 2;
#pragma unroll
    for (int nb = 0; nb < 16; nb++) {
        int col = nb * 8 + cb;
        float2 v0, v1;
        v0.x = c[nb][0] + s_bias[col];
        v0.y = c[nb][1] + s_bias[col + 1];
        v1.x = c[nb][2] + s_bias[col];
        v1.y = c[nb][3] + s_bias[col + 1];
        if (do_relu) {
            v0.x = fmaxf(v0.x, 0.f); v0.y = fmaxf(v0.y, 0.f);
            v1.x = fmaxf(v1.x, 0.f); v1.y = fmaxf(v1.y, 0.f);
        }
        if (r0 < nrows) *(float2*)(out + (size_t)r0 * 128 + col) = v0;
        if (r1 < nrows) *(float2*)(out + (size_t)r1 * 128 + col) = v1;
    }
}

// ================= f32x2 FFMA2 GEMM (K=101 user linear) ======================
__device__ __forceinline__ unsigned long long dup2(float x) {
    unsigned long long r;
    unsigned int xi = __float_as_uint(x);
    asm("mov.b64 %0, {%1, %1};" : "=l"(r) : "r"(xi));
    return r;
}
__device__ __forceinline__ void ffma2(unsigned long long& d, unsigned long long a,
                                      unsigned long long b) {
    asm("fma.rn.f32x2 %0, %1, %2, %0;" : "+l"(d) : "l"(a), "l"(b));
}
__device__ __forceinline__ float2 u2f2(unsigned long long v) {
    float2 f;
    unsigned int lo, hi;
    asm("mov.b64 {%0, %1}, %2;" : "=r"(lo), "=r"(hi) : "l"(v));
    f.x = __uint_as_float(lo); f.y = __uint_as_float(hi);
    return f;
}

template<int K, int NOUT, int CPT, int RPT>
__global__ void __launch_bounds__(256) gemm_kernel(
    const float* __restrict__ in, const float* __restrict__ W,
    const float* __restrict__ bias, float* __restrict__ out,
    int nrows, int do_relu)
{
    constexpr int CG = NOUT / CPT;
    constexpr int RG = 256 / CG;
    constexpr int RB = RG * RPT;
    constexpr int KP = (K & 1) ? K : (K + 1);
    constexpr int CP2 = CPT / 2;

    extern __shared__ float sm[];
    float* s_in = sm;
    float* s_w  = sm + RB * KP;
    __shared__ float s_b[NOUT];

    const int tid = threadIdx.x;
    const int rowbase = blockIdx.x * RB;

    for (int i = tid; i < K * NOUT; i += 256) s_w[i] = W[i];
    if (tid < NOUT) s_b[tid] = bias[tid];

    int nrow_blk = nrows - rowbase; if (nrow_blk > RB) nrow_blk = RB;
    const float* gin = in + (size_t)rowbase * K;
    for (int i = tid; i < nrow_blk * K; i += 256) {
        int r = i / K;
        int k = i - r * K;
        s_in[r * KP + k] = gin[i];
    }
    __syncthreads();

    const int cg = tid / RG;
    const int rg = tid - cg * RG;

    unsigned long long acc[RPT][CP2];
#pragma unroll
    for (int j = 0; j < RPT; j++)
#pragma unroll
        for (int c = 0; c < CP2; c++) acc[j][c] = 0ULL;

    const float* xbase = s_in + rg * KP;
    const float* wbase = s_w + cg * CPT;

#pragma unroll 8
    for (int k = 0; k < K; k++) {
        unsigned long long xd[RPT];
#pragma unroll
        for (int j = 0; j < RPT; j++) xd[j] = dup2(xbase[j * RG * KP + k]);
        const unsigned long long* wrow = (const unsigned long long*)(wbase + k * NOUT);
#pragma unroll
        for (int c = 0; c < CP2; c++) {
            unsigned long long wv = wrow[c];
#pragma unroll
            for (int j = 0; j < RPT; j++) ffma2(acc[j][c], xd[j], wv);
        }
    }

#pragma unroll
    for (int j = 0; j < RPT; j++) {
        int row = rowbase + rg + j * RG;
        if (row < nrows) {
            float* orow = out + (size_t)row * NOUT + cg * CPT;
#pragma unroll
            for (int c = 0; c < CP2; c++) {
                float2 f = u2f2(acc[j][c]);
                float v0 = f.x + s_b[cg * CPT + 2 * c];
                float v1 = f.y + s_b[cg * CPT + 2 * c + 1];
                if (do_relu) { v0 = fmaxf(v0, 0.f); v1 = fmaxf(v1, 0.f); }
                float2 o; o.x = v0; o.y = v1;
                ((float2*)orow)[c] = o;
            }
        }
    }
}

// ---------------- trivial item linear ----------------
__global__ void item_lin_kernel(const float* __restrict__ fx, const float* __restrict__ w,
                                const float* __restrict__ b, float* __restrict__ out, int ni)
{
    int i = blockIdx.x * blockDim.x + threadIdx.x;
    if (i < ni * 32) {
        int r = i >> 5, c = i & 31;
        out[i] = fmaf(fx[r], w[c], b[c]);
    }
}

// ---------------- CSR build ----------------
__global__ void count_kernel(const int* __restrict__ src, const int* __restrict__ dst,
                             int* __restrict__ c1, int* __restrict__ c2, int E)
{
    int i = blockIdx.x * blockDim.x + threadIdx.x;
    if (i < E) {
        atomicAdd(&c1[dst[i]], 1);
        atomicAdd(&c2[src[i]], 1);
    }
}

// two exclusive scans in one launch (single block); writes packed (off,cnt)
__global__ void scan2_kernel(const int* __restrict__ cA, int2* __restrict__ oA, int* __restrict__ uA, int nA,
                             const int* __restrict__ cB, int2* __restrict__ oB, int* __restrict__ uB, int nB)
{
    __shared__ int wsum[32];
    __shared__ int s_carry;
    int tid = threadIdx.x;
    for (int seg = 0; seg < 2; seg++) {
        const int* cnt = seg ? cB : cA;
        int2* off = seg ? oB : oA;
        int* cur = seg ? uB : uA;
        int n = seg ? nB : nA;
        if (tid == 0) s_carry = 0;
        __syncthreads();
        int nquad = (n + 3) >> 2;
        for (int base = 0; base < nquad; base += 1024) {
            int qi = base + tid;
            int4 v = make_int4(0, 0, 0, 0);
            if (qi < nquad) {
                int i0 = qi << 2;
                if (i0 + 3 < n) v = ((const int4*)cnt)[qi];
                else {
                    v.x = cnt[i0];
                    if (i0 + 1 < n) v.y = cnt[i0 + 1];
                    if (i0 + 2 < n) v.z = cnt[i0 + 2];
                }
            }
            int tsum = v.x + v.y + v.z + v.w;
            int x = tsum;
#pragma unroll
            for (int d = 1; d < 32; d <<= 1) {
                int y = __shfl_up_sync(0xffffffffu, x, d);
                if ((tid & 31) >= d) x += y;
            }
            if ((tid & 31) == 31) wsum[tid >> 5] = x;
            __syncthreads();
            if (tid < 32) {
                int w = wsum[tid];
#pragma unroll
                for (int d = 1; d < 32; d <<= 1) {
                    int y = __shfl_up_sync(0xffffffffu, w, d);
                    if (tid >= d) w += y;
                }
                wsum[tid] = w;
            }
            __syncthreads();
            int wo = (tid >= 32) ? wsum[(tid >> 5) - 1] : 0;
            int excl = s_carry + wo + x - tsum;
            if (qi < nquad) {
                int i0 = qi << 2;
                int e0 = excl, e1 = e0 + v.x, e2 = e1 + v.y, e3 = e2 + v.z;
                off[i0] = make_int2(e0, v.x); cur[i0] = e0;
                if (i0 + 1 < n) { off[i0 + 1] = make_int2(e1, v.y); cur[i0 + 1] = e1; }
                if (i0 + 2 < n) { off[i0 + 2] = make_int2(e2, v.z); cur[i0 + 2] = e2; }
                if (i0 + 3 < n) { off[i0 + 3] = make_int2(e3, v.w); cur[i0 + 3] = e3; }
            }
            __syncthreads();
            if (tid == 0) s_carry += wsum[31];
            __syncthreads();
        }
    }
}

// scatter: CSR slots + CSR-ordered other-endpoint + CSR-ordered edge attrs
__global__ void scatter_kernel(const int* __restrict__ src, const int* __restrict__ dst,
                               const float* __restrict__ eattr,
                               int* __restrict__ cur1, int* __restrict__ cur2,
                               int* __restrict__ oth1, int* __restrict__ oth2,
                               float4* __restrict__ ea1, int E)
{
    int i = blockIdx.x * blockDim.x + threadIdx.x;
    if (i < E) {
        int s = src[i], d = dst[i];
        int p1 = atomicAdd(&cur1[d], 1);
        oth1[p1] = s;
        float a0 = eattr[(size_t)i * 3];
        float a1 = eattr[(size_t)i * 3 + 1];
        float a2 = eattr[(size_t)i * 3 + 2];
        ea1[p1] = make_float4(a0, a1, a2, 0.f);
        int p2 = atomicAdd(&cur2[s], 1);
        oth2[p2] = d;
    }
}

// ---------------- fused GATv2 conv: online softmax + aggregation --------------
// warp per destination node; lane owns 4 channels (head = lane>>3).
// Dual even/odd softmax chains shorten the serial dependency per edge.
struct Chain { float M, S; float4 A; };

__device__ __forceinline__ void chain_update(
    Chain& ch, float t, const float4& xs)
{
    float Mn = fmaxf(ch.M, t);
    float corr = __expf(ch.M - Mn);
    float p = __expf(t - Mn);
    ch.S = ch.S * corr + p;
    ch.A.x = fmaf(ch.A.x, corr, p * xs.x);
    ch.A.y = fmaf(ch.A.y, corr, p * xs.y);
    ch.A.z = fmaf(ch.A.z, corr, p * xs.z);
    ch.A.w = fmaf(ch.A.w, corr, p * xs.w);
    ch.M = Mn;
}

__global__ void gat_conv_kernel(
    const float* __restrict__ xl,      // [n_src,128]
    const float* __restrict__ xr,      // [n_dst,128]
    const int2* __restrict__ offcnt,
    const int* __restrict__ other,     // CSR-ordered source indices
    const float4* __restrict__ ea,     // CSR-ordered edge attrs or null
    const float* __restrict__ we,      // [3,128] or null
    const float* __restrict__ att,     // [4,32] flattened
    const float* __restrict__ bias, float* __restrict__ out,
    int n, int do_relu)
{
    __shared__ int    s_o[8][32];
    __shared__ float4 s_ea[8][32];

    const int lane = threadIdx.x & 31;
    const int wrp = threadIdx.x >> 5;
    const int node = blockIdx.x * 8 + wrp;
    if (node >= n) return;

    float4 att4 = ((const float4*)att)[lane];
    float4 bias4 = ((const float4*)bias)[lane];
    int2 oc = __ldg(offcnt + node);
    const int start = oc.x;
    const int m = oc.y;

    if (m == 0) {
        float4 o = bias4;
        if (do_relu) {
            o.x = fmaxf(o.x, 0.f); o.y = fmaxf(o.y, 0.f);
            o.z = fmaxf(o.z, 0.f); o.w = fmaxf(o.w, 0.f);
        }
        ((float4*)(out + (size_t)node * 128))[lane] = o;
        return;
    }

    float4 we0 = make_float4(0, 0, 0, 0), we1 = we0, we2 = we0;
    if (we) {
        we0 = ((const float4*)we)[lane];
        we1 = ((const float4*)(we + 128))[lane];
        we2 = ((const float4*)(we + 256))[lane];
    }
    float4 xr4 = __ldg((const float4*)(xr + (size_t)node * 128) + lane);

    const float NEGINF = __int_as_float(0xff800000u);
    Chain c0, c1;
    c0.M = NEGINF; c0.S = 0.f; c0.A = make_float4(0.f, 0.f, 0.f, 0.f);
    c1 = c0;

    for (int base = 0; base < m; base += 32) {
        int i = base + lane;
        if (i < m) {
            s_o[wrp][lane] = __ldg(other + start + i);
            if (ea) s_ea[wrp][lane] = __ldg(ea + start + i);
        }
        __syncwarp();
        int lim = m - base; if (lim > 32) lim = 32;
        for (int j = 0; j < lim; j++) {
            int srcn = s_o[wrp][j];
            float4 xs = __ldg((const float4*)(xl + (size_t)srcn * 128) + lane);
            float4 m4;
            m4.x = xs.x + xr4.x; m4.y = xs.y + xr4.y;
            m4.z = xs.z + xr4.z; m4.w = xs.w + xr4.w;
            if (ea) {
                float4 e = s_ea[wrp][j];
                m4.x = fmaf(e.x, we0.x, fmaf(e.y, we1.x, fmaf(e.z, we2.x, m4.x)));
                m4.y = fmaf(e.x, we0.y, fmaf(e.y, we1.y, fmaf(e.z, we2.y, m4.y)));
                m4.z = fmaf(e.x, we0.z, fmaf(e.y, we1.z, fmaf(e.z, we2.z, m4.z)));
                m4.w = fmaf(e.x, we0.w, fmaf(e.y, we1.w, fmaf(e.z, we2.w, m4.w)));
            }
            float g0 = fmaxf(m4.x, 0.2f * m4.x);
            float g1 = fmaxf(m4.y, 0.2f * m4.y);
            float g2 = fmaxf(m4.z, 0.2f * m4.z);
            float g3 = fmaxf(m4.w, 0.2f * m4.w);
            float t = g0 * att4.x + g1 * att4.y + g2 * att4.z + g3 * att4.w;
            t += __shfl_xor_sync(0xffffffffu, t, 1);
            t += __shfl_xor_sync(0xffffffffu, t, 2);
            t += __shfl_xor_sync(0xffffffffu, t, 4);
            if (j & 1) chain_update(c1, t, xs);
            else       chain_update(c0, t, xs);
        }
        __syncwarp();
    }

    // merge chains (c1 empty when m==1: exp(-inf)=0 handles it)
    float Mn = fmaxf(c0.M, c1.M);
    float w0 = __expf(c0.M - Mn), w1 = __expf(c1.M - Mn);
    float ssum = c0.S * w0 + c1.S * w1;
    float4 a;
    a.x = c0.A.x * w0 + c1.A.x * w1;
    a.y = c0.A.y * w0 + c1.A.y * w1;
    a.z = c0.A.z * w0 + c1.A.z * w1;
    a.w = c0.A.w * w0 + c1.A.w * w1;

    float inv = 1.f / (ssum + 1e-16f);
    float4 o;
    o.x = fmaf(a.x, inv, bias4.x);
    o.y = fmaf(a.y, inv, bias4.y);
    o.z = fmaf(a.z, inv, bias4.z);
    o.w = fmaf(a.w, inv, bias4.w);
    if (do_relu) {
        o.x = fmaxf(o.x, 0.f); o.y = fmaxf(o.y, 0.f);
        o.z = fmaxf(o.z, 0.f); o.w = fmaxf(o.w, 0.f);
    }
    ((float4*)(out + (size_t)node * 128))[lane] = o;
}

// ---------------- host launch ----------------
extern "C" void kernel_launch(void* const* d_in, const int* in_sizes, int n_in,
                              void* d_out, int out_size)
{
    (void)n_in; (void)out_size;
    const float* customer_x = (const float*)d_in[0];
    const float* fund_x     = (const float*)d_in[1];
    const float* edge_attr  = (const float*)d_in[2];
    const float* user_lin_w = (const float*)d_in[3];
    const float* user_lin_b = (const float*)d_in[4];
    const float* item_lin_w = (const float*)d_in[5];
    const float* item_lin_b = (const float*)d_in[6];
    const float* conv1_wl   = (const float*)d_in[7];
    const float* conv1_bl   = (const float*)d_in[8];
    const float* conv1_wr   = (const float*)d_in[9];
    const float* conv1_br   = (const float*)d_in[10];
    const float* conv1_we   = (const float*)d_in[11];
    const float* conv1_att  = (const float*)d_in[12];
    const float* conv1_bias = (const float*)d_in[13];
    const float* conv2_wl   = (const float*)d_in[14];
    const float* conv2_bl   = (const float*)d_in[15];
    const float* conv2_wr   = (const float*)d_in[16];
    const float* conv2_br   = (const float*)d_in[17];
    const float* conv2_att  = (const float*)d_in[18];
    const float* conv2_bias = (const float*)d_in[19];
    const float* proj_w1    = (const float*)d_in[20];
    const float* proj_b1    = (const float*)d_in[21];
    const float* proj_w2    = (const float*)d_in[22];
    const float* proj_b2    = (const float*)d_in[23];
    const int*   edge_src   = (const int*)d_in[24];
    const int*   edge_dst   = (const int*)d_in[25];

    const int Nu = in_sizes[0] / 101;
    const int Ni = in_sizes[1];
    const int E  = in_sizes[24];

    float *user_x, *item_x, *xl1, *xr1, *xr2, *item2, *xl2, *hid;
    int *deg, *cur, *oth1, *oth2;
    int2* offcnt;
    float4* ea1;
    cudaGetSymbolAddress((void**)&user_x, g_user_x);
    cudaGetSymbolAddress((void**)&item_x, g_item_x);
    cudaGetSymbolAddress((void**)&xl1,    g_xl1);
    cudaGetSymbolAddress((void**)&xr1,    g_xr1);
    cudaGetSymbolAddress((void**)&xr2,    g_xr2);
    cudaGetSymbolAddress((void**)&item2,  g_item2);
    cudaGetSymbolAddress((void**)&xl2,    g_xl2);
    cudaGetSymbolAddress((void**)&hid,    g_hid);
    cudaGetSymbolAddress((void**)&deg,    g_deg);
    cudaGetSymbolAddress((void**)&offcnt, g_offcnt);
    cudaGetSymbolAddress((void**)&cur,    g_cur);
    cudaGetSymbolAddress((void**)&oth1,   g_oth1);
    cudaGetSymbolAddress((void**)&oth2,   g_oth2);
    cudaGetSymbolAddress((void**)&ea1,    g_ea1);

    int  *cnt1 = deg, *cnt2 = deg + NI_MAX;
    int2 *oc1 = offcnt, *oc2 = offcnt + NI_MAX;
    int  *cur1 = cur, *cur2 = cur + NI_MAX;

    const int smemUser  = (64 * 101 + 101 * 32) * 4;             // gemm<101,32,8,1>
    const int smemMM32  = 4 * 128 * (32 + 8) * 2;                // mma_gemm<32>   (40960)
    const int smemMM128 = 4 * 128 * (64 + 8) * 2;                // mma_gemm<128>  (73728)
    cudaFuncSetAttribute(gemm_kernel<101, 32, 8, 1>, cudaFuncAttributeMaxDynamicSharedMemorySize, smemUser);
    cudaFuncSetAttribute(mma_gemm<32>,  cudaFuncAttributeMaxDynamicSharedMemorySize, smemMM32);
    cudaFuncSetAttribute(mma_gemm<128>, cudaFuncAttributeMaxDynamicSharedMemorySize, smemMM128);

    float* user_out = (float*)d_out;             // [Nu,128]
    float* z        = user_out + (size_t)Nu * 128;

    // CSR build
    cudaMemsetAsync(deg, 0, (NI_MAX + Nu) * sizeof(int));
    count_kernel<<<(E + 255) / 256, 256>>>(edge_src, edge_dst, cnt1, cnt2, E);
    scan2_kernel<<<1, 1024>>>(cnt1, oc1, cur1, Ni, cnt2, oc2, cur2, Nu);
    scatter_kernel<<<(E + 255) / 256, 256>>>(edge_src, edge_dst, edge_attr,
                                             cur1, cur2, oth1, oth2, ea1, E);
    // user linear (K=101, FFMA2, RPT=1 for occupancy)
    gemm_kernel<101, 32, 8, 1><<<(Nu + 63) / 64, 256, smemUser>>>(customer_x, user_lin_w, user_lin_b, user_x, Nu, 0);
    // projections
    mma_gemm<32><<<(Nu + 127) / 128, 256, smemMM32>>>(user_x, conv1_wl, conv1_bl, xl1, Nu, 0);
    item_lin_kernel<<<(Ni * 32 + 255) / 256, 256>>>(fund_x, item_lin_w, item_lin_b, item_x, Ni);
    mma_gemm<32><<<(Nu + 127) / 128, 256, smemMM32>>>(user_x, conv2_wr, conv2_br, xr2, Nu, 0);
    mma_gemm<32><<<(Ni + 127) / 128, 256, smemMM32>>>(item_x, conv1_wr, conv1_br, xr1, Ni, 0);

    // conv1: user -> item (fused online softmax + aggregate)
    gat_conv_kernel<<<(Ni + 7) / 8, 256>>>(xl1, xr1, oc1, oth1, ea1, conv1_we,
                                           conv1_att, conv1_bias, item2, Ni, 1);

    // conv2: item -> user (flipped edges, no edge_attr)
    mma_gemm<128><<<(Ni + 127) / 128, 256, smemMM128>>>(item2, conv2_wl, conv2_bl, xl2, Ni, 0);
    gat_conv_kernel<<<(Nu + 7) / 8, 256>>>(xl2, xr2, oc2, oth2, nullptr, nullptr,
                                           conv2_att, conv2_bias, user_out, Nu, 0);

    // final MLP
    mma_gemm<128><<<(Nu + 127) / 128, 256, smemMM128>>>(user_out, proj_w1, proj_b1, hid, Nu, 1);
    mma_gemm<128><<<(Nu + 127) / 128, 256, smemMM128>>>(hid, proj_w2, proj_b2, z, Nu, 0);
}

// round 9
// speedup vs baseline: 2.5667x; 1.2012x over previous
#include <cuda_runtime.h>
#include <cuda_bf16.h>
#include <cstdint>

#define NU_MAX 200000
#define NI_MAX 20000
#define NE_MAX 1000000

// ---------------- scratch (device globals; no allocation allowed) -------------
__device__ float  g_user_x[NU_MAX * 32];
__device__ float  g_item_x[NI_MAX * 32];
__device__ float  g_xl1[NU_MAX * 128];
__device__ float  g_xr1[NI_MAX * 128];
__device__ float  g_xr2[NU_MAX * 128];
__device__ float  g_item2[NI_MAX * 128];
__device__ float  g_xl2[NI_MAX * 128];
__device__ float  g_hid[NU_MAX * 128];
__device__ int    g_deg[NI_MAX + NU_MAX];
__device__ int2   g_offcnt[NI_MAX + NU_MAX];
__device__ int    g_cur[NI_MAX + NU_MAX];
__device__ int    g_oth1[NE_MAX];
__device__ int    g_oth2[NE_MAX];
__device__ float4 g_ea1[NE_MAX];
__device__ __align__(16) __nv_bfloat16 g_wpack[150000];   // prepacked hi/lo weights

// packed-weight offsets (bf16 elements)
#define WP_C1WL 0
#define WP_C2WR 10240
#define WP_C1WR 20480
#define WP_C2WL 30720
#define WP_PW1  67584
#define WP_PW2  104448
#define WP_ULW  141312

// ================= helpers =================
__device__ __forceinline__ uint32_t smem_u32(const void* p) {
    uint32_t a;
    asm("{ .reg .u64 t; cvta.to.shared.u64 t, %1; cvt.u32.u64 %0, t; }" : "=r"(a) : "l"(p));
    return a;
}
__device__ __forceinline__ void ldm_x4(uint32_t* r, uint32_t addr) {
    asm volatile("ldmatrix.sync.aligned.m8n8.x4.shared.b16 {%0,%1,%2,%3}, [%4];"
                 : "=r"(r[0]), "=r"(r[1]), "=r"(r[2]), "=r"(r[3]) : "r"(addr));
}
__device__ __forceinline__ void mma_bf16(float* c, const uint32_t* a, uint32_t b0, uint32_t b1) {
    asm volatile("mma.sync.aligned.m16n8k16.row.col.f32.bf16.bf16.f32 "
                 "{%0,%1,%2,%3}, {%4,%5,%6,%7}, {%8,%9}, {%0,%1,%2,%3};"
                 : "+f"(c[0]), "+f"(c[1]), "+f"(c[2]), "+f"(c[3])
                 : "r"(a[0]), "r"(a[1]), "r"(a[2]), "r"(a[3]), "r"(b0), "r"(b1));
}
__device__ __forceinline__ uint32_t pack_bf(__nv_bfloat16 a, __nv_bfloat16 b) {
    return (uint32_t)__bfloat16_as_ushort(a) | ((uint32_t)__bfloat16_as_ushort(b) << 16);
}

// ---------------- weight prepack: fp32 W[K,NOUT] -> hi/lo bf16 tiles ----------
// layout per matrix: for ch in 0..NCH: [hi tile NOUT x KP][lo tile NOUT x KP],
// tile[n*KP + kloc] = W[(ch*CHUNK+kloc)*NOUT + n]  (transposed, padded with 0)
template<int K, int NOUT, int CHUNK, int KP, int NCH>
__device__ __forceinline__ void prep_one(const float* __restrict__ W,
                                         __nv_bfloat16* __restrict__ dst, int i)
{
    constexpr int TOT = NCH * 2 * NOUT * KP;
    if (i >= TOT) return;
    int ch = i / (2 * NOUT * KP);
    int r = i - ch * (2 * NOUT * KP);
    int half = r / (NOUT * KP);
    int q = r - half * (NOUT * KP);
    int n = q / KP;
    int kloc = q - n * KP;
    int k = ch * CHUNK + kloc;
    float v = (kloc < CHUNK && k < K) ? W[k * NOUT + n] : 0.f;
    __nv_bfloat16 hi = __float2bfloat16(v);
    dst[i] = half ? __float2bfloat16(v - __bfloat162float(hi)) : hi;
}

__global__ void prepack_kernel(const float* w0, const float* w1, const float* w2,
                               const float* w3, const float* w4, const float* w5,
                               const float* w6, __nv_bfloat16* dst)
{
    int i = blockIdx.x * 256 + threadIdx.x;
    switch (blockIdx.y) {
    case 0: prep_one<32, 128, 32, 40, 1>(w0, dst + WP_C1WL, i); break;
    case 1: prep_one<32, 128, 32, 40, 1>(w1, dst + WP_C2WR, i); break;
    case 2: prep_one<32, 128, 32, 40, 1>(w2, dst + WP_C1WR, i); break;
    case 3: prep_one<128, 128, 64, 72, 2>(w3, dst + WP_C2WL, i); break;
    case 4: prep_one<128, 128, 64, 72, 2>(w4, dst + WP_PW1, i); break;
    case 5: prep_one<128, 128, 64, 72, 2>(w5, dst + WP_PW2, i); break;
    case 6: prep_one<101, 32, 112, 120, 1>(w6, dst + WP_ULW, i); break;
    }
}

// ---------------- HMMA GEMM: out[nrows,128] = in[nrows,K] @ W[K,128] + b ------
// bf16 hi/lo split (3 terms), fp32 accumulate; B from prepacked global (raw copy).
template<int K>
__global__ void __launch_bounds__(256, 2) mma_gemm(
    const float* __restrict__ in, const __nv_bfloat16* __restrict__ Wp,
    const float* __restrict__ bias, float* __restrict__ out,
    int nrows, int do_relu)
{
    constexpr int CHUNK = (K < 64) ? K : 64;
    constexpr int NCH = K / CHUNK;
    constexpr int KP = CHUNK + 8;
    constexpr int TILE = 128 * KP;
    constexpr int QPR = CHUNK / 4;

    extern __shared__ __nv_bfloat16 smbf[];
    __nv_bfloat16* sAh = smbf;
    __nv_bfloat16* sAl = sAh + TILE;
    __nv_bfloat16* sBh = sAl + TILE;        // sBh,sBl contiguous for bulk copy
    __shared__ float s_bias[128];

    const int tid = threadIdx.x;
    const int rowbase = blockIdx.x * 128;
    if (tid < 128) s_bias[tid] = bias[tid];

    int nrow_blk = nrows - rowbase; if (nrow_blk > 128) nrow_blk = 128;

    const int wid = tid >> 5;
    const int lane = tid & 31;
    const int m0 = wid * 16;
    const int lrow = lane & 15;
    const int lcol = (lane >> 4) << 3;

    float c[16][4];
#pragma unroll
    for (int nb = 0; nb < 16; nb++)
#pragma unroll
        for (int q = 0; q < 4; q++) c[nb][q] = 0.f;

    const uint32_t sAh0 = smem_u32(sAh), sAl0 = smem_u32(sAl);
    const uint32_t sBh0 = smem_u32(sBh), sBl0 = sBh0 + TILE * 2;
    const uint32_t offA = (uint32_t)((m0 + lrow) * KP + lcol) * 2;

#pragma unroll
    for (int ch = 0; ch < NCH; ch++) {
        if (ch) __syncthreads();

        // A chunk: 128 rows x CHUNK cols, float4 + hi/lo split
        const float* gin = in + (size_t)rowbase * K + ch * CHUNK;
        for (int q = tid; q < 128 * QPR; q += 256) {
            int r = q / QPR;
            int c4 = (q - r * QPR) * 4;
            float4 v = (r < nrow_blk) ? *(const float4*)(gin + (size_t)r * K + c4)
                                      : make_float4(0.f, 0.f, 0.f, 0.f);
            __nv_bfloat16 h0 = __float2bfloat16(v.x), h1 = __float2bfloat16(v.y);
            __nv_bfloat16 h2 = __float2bfloat16(v.z), h3 = __float2bfloat16(v.w);
            __nv_bfloat16 l0 = __float2bfloat16(v.x - __bfloat162float(h0));
            __nv_bfloat16 l1 = __float2bfloat16(v.y - __bfloat162float(h1));
            __nv_bfloat16 l2 = __float2bfloat16(v.z - __bfloat162float(h2));
            __nv_bfloat16 l3 = __float2bfloat16(v.w - __bfloat162float(h3));
            uint32_t* ph = (uint32_t*)(sAh + r * KP + c4);
            uint32_t* pl = (uint32_t*)(sAl + r * KP + c4);
            ph[0] = pack_bf(h0, h1); ph[1] = pack_bf(h2, h3);
            pl[0] = pack_bf(l0, l1); pl[1] = pack_bf(l2, l3);
        }
        // B chunk: raw uint4 copy of prepacked hi+lo tiles
        {
            const uint4* bsrc = (const uint4*)(Wp + (size_t)ch * 2 * TILE);
            uint4* bdst = (uint4*)sBh;
            for (int i = tid; i < (2 * TILE) / 8; i += 256) bdst[i] = bsrc[i];
        }
        __syncthreads();

#pragma unroll
        for (int s = 0; s < CHUNK / 16; s++) {
            uint32_t ah[4], al[4];
            ldm_x4(ah, sAh0 + offA + s * 32);
            ldm_x4(al, sAl0 + offA + s * 32);
#pragma unroll
            for (int nbp = 0; nbp < 8; nbp++) {
                uint32_t offB = (uint32_t)((nbp * 16 + lrow) * KP + lcol) * 2 + s * 32;
                uint32_t bh[4], bl[4];
                ldm_x4(bh, sBh0 + offB);
                ldm_x4(bl, sBl0 + offB);
                mma_bf16(c[2 * nbp],     ah, bh[0], bh[2]);
                mma_bf16(c[2 * nbp],     ah, bl[0], bl[2]);
                mma_bf16(c[2 * nbp],     al, bh[0], bh[2]);
                mma_bf16(c[2 * nbp + 1], ah, bh[1], bh[3]);
                mma_bf16(c[2 * nbp + 1], ah, bl[1], bl[3]);
                mma_bf16(c[2 * nbp + 1], al, bh[1], bh[3]);
            }
        }
    }

    const int r0 = rowbase + m0 + (lane >> 2);
    const int r1 = r0 + 8;
    const int cb = (lane & 3) * 2;
#pragma unroll
    for (int nb = 0; nb < 16; nb++) {
        int col = nb * 8 + cb;
        float2 v0, v1;
        v0.x = c[nb][0] + s_bias[col];
        v0.y = c[nb][1] + s_bias[col + 1];
        v1.x = c[nb][2] + s_bias[col];
        v1.y = c[nb][3] + s_bias[col + 1];
        if (do_relu) {
            v0.x = fmaxf(v0.x, 0.f); v0.y = fmaxf(v0.y, 0.f);
            v1.x = fmaxf(v1.x, 0.f); v1.y = fmaxf(v1.y, 0.f);
        }
        if (r0 < nrows) *(float2*)(out + (size_t)r0 * 128 + col) = v0;
        if (r1 < nrows) *(float2*)(out + (size_t)r1 * 128 + col) = v1;
    }
}

// ---------------- HMMA user linear: out[nrows,32] = in[nrows,101] @ W + b -----
// K padded to 112 (7 MMA steps), N=32.
__global__ void __launch_bounds__(256, 2) mma_gemm101(
    const float* __restrict__ in, const __nv_bfloat16* __restrict__ Wp,
    const float* __restrict__ bias, float* __restrict__ out, int nrows)
{
    constexpr int K = 101;
    constexpr int KP = 120;
    constexpr int TILEA = 128 * KP;
    constexpr int TILEB = 32 * KP;

    extern __shared__ __nv_bfloat16 smbf[];
    __nv_bfloat16* sAh = smbf;
    __nv_bfloat16* sAl = sAh + TILEA;
    __nv_bfloat16* sBh = sAl + TILEA;
    __shared__ float s_bias[32];

    const int tid = threadIdx.x;
    const int rowbase = blockIdx.x * 128;
    if (tid < 32) s_bias[tid] = bias[tid];

    int nrow_blk = nrows - rowbase; if (nrow_blk > 128) nrow_blk = 128;

    // zero A tiles (pad cols 101..111 must be 0)
    {
        uint4* z = (uint4*)sAh;
        for (int i = tid; i < (2 * TILEA) / 8; i += 256) z[i] = make_uint4(0, 0, 0, 0);
    }
    __syncthreads();

    // B: raw copy of prepacked tiles
    {
        const uint4* bsrc = (const uint4*)Wp;
        uint4* bdst = (uint4*)sBh;
        for (int i = tid; i < (2 * TILEB) / 8; i += 256) bdst[i] = bsrc[i];
    }
    // A fill
    const float* gin = in + (size_t)rowbase * K;
    if (rowbase + 128 <= nrows) {
        // full block: region is float4-aligned (128*101 % 4 == 0)
        for (int q = tid; q < (128 * K) / 4; q += 256) {
            float4 v = ((const float4*)gin)[q];
            int f = q * 4;
            float vv[4] = {v.x, v.y, v.z, v.w};
#pragma unroll
            for (int e = 0; e < 4; e++) {
                int idx = f + e;
                int r = idx / K;
                int cc = idx - r * K;
                __nv_bfloat16 hi = __float2bfloat16(vv[e]);
                __nv_bfloat16 lo = __float2bfloat16(vv[e] - __bfloat162float(hi));
                sAh[r * KP + cc] = hi;
                sAl[r * KP + cc] = lo;
            }
        }
    } else {
        for (int i = tid; i < 128 * K; i += 256) {
            int r = i / K;
            int cc = i - r * K;
            float x = (r < nrow_blk) ? gin[i] : 0.f;
            __nv_bfloat16 hi = __float2bfloat16(x);
            __nv_bfloat16 lo = __float2bfloat16(x - __bfloat162float(hi));
            sAh[r * KP + cc] = hi;
            sAl[r * KP + cc] = lo;
        }
    }
    __syncthreads();

    const int wid = tid >> 5;
    const int lane = tid & 31;
    const int m0 = wid * 16;
    const int lrow = lane & 15;
    const int lcol = (lane >> 4) << 3;

    float c[4][4];
#pragma unroll
    for (int nb = 0; nb < 4; nb++)
#pragma unroll
        for (int q = 0; q < 4; q++) c[nb][q] = 0.f;

    const uint32_t sAh0 = smem_u32(sAh), sAl0 = smem_u32(sAl);
    const uint32_t sBh0 = smem_u32(sBh), sBl0 = sBh0 + TILEB * 2;
    const uint32_t offA = (uint32_t)((m0 + lrow) * KP + lcol) * 2;

#pragma unroll
    for (int s = 0; s < 7; s++) {
        uint32_t ah[4], al[4];
        ldm_x4(ah, sAh0 + offA + s * 32);
        ldm_x4(al, sAl0 + offA + s * 32);
#pragma unroll
        for (int nbp = 0; nbp < 2; nbp++) {
            uint32_t offB = (uint32_t)((nbp * 16 + lrow) * KP + lcol) * 2 + s * 32;
            uint32_t bh[4], bl[4];
            ldm_x4(bh, sBh0 + offB);
            ldm_x4(bl, sBl0 + offB);
            mma_bf16(c[2 * nbp],     ah, bh[0], bh[2]);
            mma_bf16(c[2 * nbp],     ah, bl[0], bl[2]);
            mma_bf16(c[2 * nbp],     al, bh[0], bh[2]);
            mma_bf16(c[2 * nbp + 1], ah, bh[1], bh[3]);
            mma_bf16(c[2 * nbp + 1], ah, bl[1], bl[3]);
            mma_bf16(c[2 * nbp + 1], al, bh[1], bh[3]);
        }
    }

    const int r0 = rowbase + m0 + (lane >> 2);
    const int r1 = r0 + 8;
    const int cb = (lane & 3) * 2;
#pragma unroll
    for (int nb = 0; nb < 4; nb++) {
        int col = nb * 8 + cb;
        float2 v0, v1;
        v0.x = c[nb][0] + s_bias[col];
        v0.y = c[nb][1] + s_bias[col + 1];
        v1.x = c[nb][2] + s_bias[col];
        v1.y = c[nb][3] + s_bias[col + 1];
        if (r0 < nrows) *(float2*)(out + (size_t)r0 * 32 + col) = v0;
        if (r1 < nrows) *(float2*)(out + (size_t)r1 * 32 + col) = v1;
    }
}

// ---------------- trivial item linear ----------------
__global__ void item_lin_kernel(const float* __restrict__ fx, const float* __restrict__ w,
                                const float* __restrict__ b, float* __restrict__ out, int ni)
{
    int i = blockIdx.x * blockDim.x + threadIdx.x;
    if (i < ni * 32) {
        int r = i >> 5, c = i & 31;
        out[i] = fmaf(fx[r], w[c], b[c]);
    }
}

// ---------------- CSR build ----------------
__global__ void count_kernel(const int* __restrict__ src, const int* __restrict__ dst,
                             int* __restrict__ c1, int* __restrict__ c2, int E)
{
    int i = blockIdx.x * blockDim.x + threadIdx.x;
    if (i < E) {
        atomicAdd(&c1[dst[i]], 1);
        atomicAdd(&c2[src[i]], 1);
    }
}

__global__ void scan2_kernel(const int* __restrict__ cA, int2* __restrict__ oA, int* __restrict__ uA, int nA,
                             const int* __restrict__ cB, int2* __restrict__ oB, int* __restrict__ uB, int nB)
{
    __shared__ int wsum[32];
    __shared__ int s_carry;
    int tid = threadIdx.x;
    for (int seg = 0; seg < 2; seg++) {
        const int* cnt = seg ? cB : cA;
        int2* off = seg ? oB : oA;
        int* cur = seg ? uB : uA;
        int n = seg ? nB : nA;
        if (tid == 0) s_carry = 0;
        __syncthreads();
        int nquad = (n + 3) >> 2;
        for (int base = 0; base < nquad; base += 1024) {
            int qi = base + tid;
            int4 v = make_int4(0, 0, 0, 0);
            if (qi < nquad) {
                int i0 = qi << 2;
                if (i0 + 3 < n) v = ((const int4*)cnt)[qi];
                else {
                    v.x = cnt[i0];
                    if (i0 + 1 < n) v.y = cnt[i0 + 1];
                    if (i0 + 2 < n) v.z = cnt[i0 + 2];
                }
            }
            int tsum = v.x + v.y + v.z + v.w;
            int x = tsum;
#pragma unroll
            for (int d = 1; d < 32; d <<= 1) {
                int y = __shfl_up_sync(0xffffffffu, x, d);
                if ((tid & 31) >= d) x += y;
            }
            if ((tid & 31) == 31) wsum[tid >> 5] = x;
            __syncthreads();
            if (tid < 32) {
                int w = wsum[tid];
#pragma unroll
                for (int d = 1; d < 32; d <<= 1) {
                    int y = __shfl_up_sync(0xffffffffu, w, d);
                    if (tid >= d) w += y;
                }
                wsum[tid] = w;
            }
            __syncthreads();
            int wo = (tid >= 32) ? wsum[(tid >> 5) - 1] : 0;
            int excl = s_carry + wo + x - tsum;
            if (qi < nquad) {
                int i0 = qi << 2;
                int e0 = excl, e1 = e0 + v.x, e2 = e1 + v.y, e3 = e2 + v.z;
                off[i0] = make_int2(e0, v.x); cur[i0] = e0;
                if (i0 + 1 < n) { off[i0 + 1] = make_int2(e1, v.y); cur[i0 + 1] = e1; }
                if (i0 + 2 < n) { off[i0 + 2] = make_int2(e2, v.z); cur[i0 + 2] = e2; }
                if (i0 + 3 < n) { off[i0 + 3] = make_int2(e3, v.w); cur[i0 + 3] = e3; }
            }
            __syncthreads();
            if (tid == 0) s_carry += wsum[31];
            __syncthreads();
        }
    }
}

__global__ void scatter_kernel(const int* __restrict__ src, const int* __restrict__ dst,
                               const float* __restrict__ eattr,
                               int* __restrict__ cur1, int* __restrict__ cur2,
                               int* __restrict__ oth1, int* __restrict__ oth2,
                               float4* __restrict__ ea1, int E)
{
    int i = blockIdx.x * blockDim.x + threadIdx.x;
    if (i < E) {
        int s = src[i], d = dst[i];
        int p1 = atomicAdd(&cur1[d], 1);
        oth1[p1] = s;
        float a0 = eattr[(size_t)i * 3];
        float a1 = eattr[(size_t)i * 3 + 1];
        float a2 = eattr[(size_t)i * 3 + 2];
        ea1[p1] = make_float4(a0, a1, a2, 0.f);
        int p2 = atomicAdd(&cur2[s], 1);
        oth2[p2] = d;
    }
}

// ---------------- fused GATv2 conv: online softmax + aggregation --------------
struct Chain { float M, S; float4 A; };

__device__ __forceinline__ void chain_update(Chain& ch, float t, const float4& xs)
{
    float Mn = fmaxf(ch.M, t);
    float corr = __expf(ch.M - Mn);
    float p = __expf(t - Mn);
    ch.S = ch.S * corr + p;
    ch.A.x = fmaf(ch.A.x, corr, p * xs.x);
    ch.A.y = fmaf(ch.A.y, corr, p * xs.y);
    ch.A.z = fmaf(ch.A.z, corr, p * xs.z);
    ch.A.w = fmaf(ch.A.w, corr, p * xs.w);
    ch.M = Mn;
}

__global__ void gat_conv_kernel(
    const float* __restrict__ xl, const float* __restrict__ xr,
    const int2* __restrict__ offcnt,
    const int* __restrict__ other,
    const float4* __restrict__ ea,
    const float* __restrict__ we,
    const float* __restrict__ att,
    const float* __restrict__ bias, float* __restrict__ out,
    int n, int do_relu)
{
    __shared__ int    s_o[8][32];
    __shared__ float4 s_ea[8][32];

    const int lane = threadIdx.x & 31;
    const int wrp = threadIdx.x >> 5;
    const int node = blockIdx.x * 8 + wrp;
    if (node >= n) return;

    float4 att4 = ((const float4*)att)[lane];
    float4 bias4 = ((const float4*)bias)[lane];
    int2 oc = __ldg(offcnt + node);
    const int start = oc.x;
    const int m = oc.y;

    if (m == 0) {
        float4 o = bias4;
        if (do_relu) {
            o.x = fmaxf(o.x, 0.f); o.y = fmaxf(o.y, 0.f);
            o.z = fmaxf(o.z, 0.f); o.w = fmaxf(o.w, 0.f);
        }
        ((float4*)(out + (size_t)node * 128))[lane] = o;
        return;
    }

    float4 we0 = make_float4(0, 0, 0, 0), we1 = we0, we2 = we0;
    if (we) {
        we0 = ((const float4*)we)[lane];
        we1 = ((const float4*)(we + 128))[lane];
        we2 = ((const float4*)(we + 256))[lane];
    }
    float4 xr4 = __ldg((const float4*)(xr + (size_t)node * 128) + lane);

    const float NEGINF = __int_as_float(0xff800000u);
    Chain c0, c1;
    c0.M = NEGINF; c0.S = 0.f; c0.A = make_float4(0.f, 0.f, 0.f, 0.f);
    c1 = c0;

    for (int base = 0; base < m; base += 32) {
        int i = base + lane;
        if (i < m) {
            s_o[wrp][lane] = __ldg(other + start + i);
            if (ea) s_ea[wrp][lane] = __ldg(ea + start + i);
        }
        __syncwarp();
        int lim = m - base; if (lim > 32) lim = 32;
        for (int j = 0; j < lim; j++) {
            int srcn = s_o[wrp][j];
            float4 xs = __ldg((const float4*)(xl + (size_t)srcn * 128) + lane);
            float4 m4;
            m4.x = xs.x + xr4.x; m4.y = xs.y + xr4.y;
            m4.z = xs.z + xr4.z; m4.w = xs.w + xr4.w;
            if (ea) {
                float4 e = s_ea[wrp][j];
                m4.x = fmaf(e.x, we0.x, fmaf(e.y, we1.x, fmaf(e.z, we2.x, m4.x)));
                m4.y = fmaf(e.x, we0.y, fmaf(e.y, we1.y, fmaf(e.z, we2.y, m4.y)));
                m4.z = fmaf(e.x, we0.z, fmaf(e.y, we1.z, fmaf(e.z, we2.z, m4.z)));
                m4.w = fmaf(e.x, we0.w, fmaf(e.y, we1.w, fmaf(e.z, we2.w, m4.w)));
            }
            float g0 = fmaxf(m4.x, 0.2f * m4.x);
            float g1 = fmaxf(m4.y, 0.2f * m4.y);
            float g2 = fmaxf(m4.z, 0.2f * m4.z);
            float g3 = fmaxf(m4.w, 0.2f * m4.w);
            float t = g0 * att4.x + g1 * att4.y + g2 * att4.z + g3 * att4.w;
            t += __shfl_xor_sync(0xffffffffu, t, 1);
            t += __shfl_xor_sync(0xffffffffu, t, 2);
            t += __shfl_xor_sync(0xffffffffu, t, 4);
            if (j & 1) chain_update(c1, t, xs);
            else       chain_update(c0, t, xs);
        }
        __syncwarp();
    }

    float Mn = fmaxf(c0.M, c1.M);
    float w0 = __expf(c0.M - Mn), w1 = __expf(c1.M - Mn);
    float ssum = c0.S * w0 + c1.S * w1;
    float4 a;
    a.x = c0.A.x * w0 + c1.A.x * w1;
    a.y = c0.A.y * w0 + c1.A.y * w1;
    a.z = c0.A.z * w0 + c1.A.z * w1;
    a.w = c0.A.w * w0 + c1.A.w * w1;

    float inv = 1.f / (ssum + 1e-16f);
    float4 o;
    o.x = fmaf(a.x, inv, bias4.x);
    o.y = fmaf(a.y, inv, bias4.y);
    o.z = fmaf(a.z, inv, bias4.z);
    o.w = fmaf(a.w, inv, bias4.w);
    if (do_relu) {
        o.x = fmaxf(o.x, 0.f); o.y = fmaxf(o.y, 0.f);
        o.z = fmaxf(o.z, 0.f); o.w = fmaxf(o.w, 0.f);
    }
    ((float4*)(out + (size_t)node * 128))[lane] = o;
}

// ---------------- host launch ----------------
extern "C" void kernel_launch(void* const* d_in, const int* in_sizes, int n_in,
                              void* d_out, int out_size)
{
    (void)n_in; (void)out_size;
    const float* customer_x = (const float*)d_in[0];
    const float* fund_x     = (const float*)d_in[1];
    const float* edge_attr  = (const float*)d_in[2];
    const float* user_lin_w = (const float*)d_in[3];
    const float* user_lin_b = (const float*)d_in[4];
    const float* item_lin_w = (const float*)d_in[5];
    const float* item_lin_b = (const float*)d_in[6];
    const float* conv1_wl   = (const float*)d_in[7];
    const float* conv1_bl   = (const float*)d_in[8];
    const float* conv1_wr   = (const float*)d_in[9];
    const float* conv1_br   = (const float*)d_in[10];
    const float* conv1_we   = (const float*)d_in[11];
    const float* conv1_att  = (const float*)d_in[12];
    const float* conv1_bias = (const float*)d_in[13];
    const float* conv2_wl   = (const float*)d_in[14];
    const float* conv2_bl   = (const float*)d_in[15];
    const float* conv2_wr   = (const float*)d_in[16];
    const float* conv2_br   = (const float*)d_in[17];
    const float* conv2_att  = (const float*)d_in[18];
    const float* conv2_bias = (const float*)d_in[19];
    const float* proj_w1    = (const float*)d_in[20];
    const float* proj_b1    = (const float*)d_in[21];
    const float* proj_w2    = (const float*)d_in[22];
    const float* proj_b2    = (const float*)d_in[23];
    const int*   edge_src   = (const int*)d_in[24];
    const int*   edge_dst   = (const int*)d_in[25];

    const int Nu = in_sizes[0] / 101;
    const int Ni = in_sizes[1];
    const int E  = in_sizes[24];

    float *user_x, *item_x, *xl1, *xr1, *xr2, *item2, *xl2, *hid;
    int *deg, *cur, *oth1, *oth2;
    int2* offcnt;
    float4* ea1;
    __nv_bfloat16* wp;
    cudaGetSymbolAddress((void**)&user_x, g_user_x);
    cudaGetSymbolAddress((void**)&item_x, g_item_x);
    cudaGetSymbolAddress((void**)&xl1,    g_xl1);
    cudaGetSymbolAddress((void**)&xr1,    g_xr1);
    cudaGetSymbolAddress((void**)&xr2,    g_xr2);
    cudaGetSymbolAddress((void**)&item2,  g_item2);
    cudaGetSymbolAddress((void**)&xl2,    g_xl2);
    cudaGetSymbolAddress((void**)&hid,    g_hid);
    cudaGetSymbolAddress((void**)&deg,    g_deg);
    cudaGetSymbolAddress((void**)&offcnt, g_offcnt);
    cudaGetSymbolAddress((void**)&cur,    g_cur);
    cudaGetSymbolAddress((void**)&oth1,   g_oth1);
    cudaGetSymbolAddress((void**)&oth2,   g_oth2);
    cudaGetSymbolAddress((void**)&ea1,    g_ea1);
    cudaGetSymbolAddress((void**)&wp,     g_wpack);

    int  *cnt1 = deg, *cnt2 = deg + NI_MAX;
    int2 *oc1 = offcnt, *oc2 = offcnt + NI_MAX;
    int  *cur1 = cur, *cur2 = cur + NI_MAX;

    const int smemMM32  = 4 * 128 * 40 * 2;                  // 40960
    const int smemMM128 = 4 * 128 * 72 * 2;                  // 73728
    const int smemMM101 = (2 * 128 * 120 + 2 * 32 * 120) * 2; // 76800
    cudaFuncSetAttribute(mma_gemm<32>,  cudaFuncAttributeMaxDynamicSharedMemorySize, smemMM32);
    cudaFuncSetAttribute(mma_gemm<128>, cudaFuncAttributeMaxDynamicSharedMemorySize, smemMM128);
    cudaFuncSetAttribute(mma_gemm101,   cudaFuncAttributeMaxDynamicSharedMemorySize, smemMM101);

    float* user_out = (float*)d_out;             // [Nu,128]
    float* z        = user_out + (size_t)Nu * 128;

    // fork/join streams: CSR build runs concurrently with prepack+projections.
    // Created fresh each call (host-side handles only; kernel_launch is called
    // a bounded number of times), never destroyed so captured graph stays valid.
    cudaStream_t s1;
    cudaStreamCreateWithFlags(&s1, cudaStreamNonBlocking);
    cudaEvent_t eFork, eJoin;
    cudaEventCreateWithFlags(&eFork, cudaEventDisableTiming);
    cudaEventCreateWithFlags(&eJoin, cudaEventDisableTiming);

    // main: weight prepack
    prepack_kernel<<<dim3(144, 7), 256>>>(conv1_wl, conv2_wr, conv1_wr,
                                          conv2_wl, proj_w1, proj_w2,
                                          user_lin_w, wp);
    // fork side stream
    cudaEventRecord(eFork, 0);
    cudaStreamWaitEvent(s1, eFork, 0);

    // side: CSR build
    cudaMemsetAsync(deg, 0, (NI_MAX + Nu) * sizeof(int), s1);
    count_kernel<<<(E + 255) / 256, 256, 0, s1>>>(edge_src, edge_dst, cnt1, cnt2, E);
    // main: user linear (HMMA)
    mma_gemm101<<<(Nu + 127) / 128, 256, smemMM101>>>(customer_x, wp + WP_ULW, user_lin_b, user_x, Nu);
    // side
    scan2_kernel<<<1, 1024, 0, s1>>>(cnt1, oc1, cur1, Ni, cnt2, oc2, cur2, Nu);
    // main: projections
    mma_gemm<32><<<(Nu + 127) / 128, 256, smemMM32>>>(user_x, wp + WP_C1WL, conv1_bl, xl1, Nu, 0);
    item_lin_kernel<<<(Ni * 32 + 255) / 256, 256>>>(fund_x, item_lin_w, item_lin_b, item_x, Ni);
    // side
    scatter_kernel<<<(E + 255) / 256, 256, 0, s1>>>(edge_src, edge_dst, edge_attr,
                                                    cur1, cur2, oth1, oth2, ea1, E);
    // main
    mma_gemm<32><<<(Nu + 127) / 128, 256, smemMM32>>>(user_x, wp + WP_C2WR, conv2_br, xr2, Nu, 0);
    mma_gemm<32><<<(Ni + 127) / 128, 256, smemMM32>>>(item_x, wp + WP_C1WR, conv1_br, xr1, Ni, 0);

    // join: CSR results needed from here on
    cudaEventRecord(eJoin, s1);
    cudaStreamWaitEvent(0, eJoin, 0);

    // conv1: user -> item
    gat_conv_kernel<<<(Ni + 7) / 8, 256>>>(xl1, xr1, oc1, oth1, ea1, conv1_we,
                                           conv1_att, conv1_bias, item2, Ni, 1);
    // conv2: item -> user
    mma_gemm<128><<<(Ni + 127) / 128, 256, smemMM128>>>(item2, wp + WP_C2WL, conv2_bl, xl2, Ni, 0);
    gat_conv_kernel<<<(Nu + 7) / 8, 256>>>(xl2, xr2, oc2, oth2, nullptr, nullptr,
                                           conv2_att, conv2_bias, user_out, Nu, 0);
    // final MLP
    mma_gemm<128><<<(Nu + 127) / 128, 256, smemMM128>>>(user_out, wp + WP_PW1, proj_b1, hid, Nu, 1);
    mma_gemm<128><<<(Nu + 127) / 128, 256, smemMM128>>>(hid, wp + WP_PW2, proj_b2, z, Nu, 0);
}

// round 10
// speedup vs baseline: 2.9592x; 1.1529x over previous
#include <cuda_runtime.h>
#include <cuda_bf16.h>
#include <cstdint>

#define NU_MAX 200000
#define NI_MAX 20000
#define NE_MAX 1000000

// ---------------- scratch (device globals; no allocation allowed) -------------
__device__ float  g_user_x[NU_MAX * 32];
__device__ float  g_item_x[NI_MAX * 32];
__device__ float  g_xl1[NU_MAX * 128];
__device__ float  g_xr1[NI_MAX * 128];
__device__ float  g_xr2[NU_MAX * 128];
__device__ float  g_item2[NI_MAX * 128];
__device__ float  g_xl2[NI_MAX * 128];
__device__ float  g_hid[NU_MAX * 128];
__device__ int    g_deg[NI_MAX + NU_MAX];
__device__ int2   g_offcnt[NI_MAX + NU_MAX];
__device__ int    g_cur[NI_MAX + NU_MAX];
__device__ int    g_bsum[64];             // per-block sums for multi-block scan
__device__ int    g_oth1[NE_MAX];
__device__ int    g_oth2[NE_MAX];
__device__ float4 g_ea1[NE_MAX];
__device__ __align__(16) __nv_bfloat16 g_wpack[150000];   // prepacked hi/lo weights

// packed-weight offsets (bf16 elements)
#define WP_C1WL 0
#define WP_C2WR 10240
#define WP_C1WR 20480
#define WP_C2WL 30720
#define WP_PW1  67584
#define WP_PW2  104448
#define WP_ULW  141312

// ================= helpers =================
__device__ __forceinline__ uint32_t smem_u32(const void* p) {
    uint32_t a;
    asm("{ .reg .u64 t; cvta.to.shared.u64 t, %1; cvt.u32.u64 %0, t; }" : "=r"(a) : "l"(p));
    return a;
}
__device__ __forceinline__ void ldm_x4(uint32_t* r, uint32_t addr) {
    asm volatile("ldmatrix.sync.aligned.m8n8.x4.shared.b16 {%0,%1,%2,%3}, [%4];"
                 : "=r"(r[0]), "=r"(r[1]), "=r"(r[2]), "=r"(r[3]) : "r"(addr));
}
__device__ __forceinline__ void mma_bf16(float* c, const uint32_t* a, uint32_t b0, uint32_t b1) {
    asm volatile("mma.sync.aligned.m16n8k16.row.col.f32.bf16.bf16.f32 "
                 "{%0,%1,%2,%3}, {%4,%5,%6,%7}, {%8,%9}, {%0,%1,%2,%3};"
                 : "+f"(c[0]), "+f"(c[1]), "+f"(c[2]), "+f"(c[3])
                 : "r"(a[0]), "r"(a[1]), "r"(a[2]), "r"(a[3]), "r"(b0), "r"(b1));
}
__device__ __forceinline__ uint32_t pack_bf(__nv_bfloat16 a, __nv_bfloat16 b) {
    return (uint32_t)__bfloat16_as_ushort(a) | ((uint32_t)__bfloat16_as_ushort(b) << 16);
}

// ---------------- weight prepack: fp32 W[K,NOUT] -> hi/lo bf16 tiles ----------
template<int K, int NOUT, int CHUNK, int KP, int NCH>
__device__ __forceinline__ void prep_one(const float* __restrict__ W,
                                         __nv_bfloat16* __restrict__ dst, int i)
{
    constexpr int TOT = NCH * 2 * NOUT * KP;
    if (i >= TOT) return;
    int ch = i / (2 * NOUT * KP);
    int r = i - ch * (2 * NOUT * KP);
    int half = r / (NOUT * KP);
    int q = r - half * (NOUT * KP);
    int n = q / KP;
    int kloc = q - n * KP;
    int k = ch * CHUNK + kloc;
    float v = (kloc < CHUNK && k < K) ? W[k * NOUT + n] : 0.f;
    __nv_bfloat16 hi = __float2bfloat16(v);
    dst[i] = half ? __float2bfloat16(v - __bfloat162float(hi)) : hi;
}

__global__ void prepack_kernel(const float* w0, const float* w1, const float* w2,
                               const float* w3, const float* w4, const float* w5,
                               const float* w6, __nv_bfloat16* dst)
{
    int i = blockIdx.x * 256 + threadIdx.x;
    switch (blockIdx.y) {
    case 0: prep_one<32, 128, 32, 40, 1>(w0, dst + WP_C1WL, i); break;
    case 1: prep_one<32, 128, 32, 40, 1>(w1, dst + WP_C2WR, i); break;
    case 2: prep_one<32, 128, 32, 40, 1>(w2, dst + WP_C1WR, i); break;
    case 3: prep_one<128, 128, 64, 72, 2>(w3, dst + WP_C2WL, i); break;
    case 4: prep_one<128, 128, 64, 72, 2>(w4, dst + WP_PW1, i); break;
    case 5: prep_one<128, 128, 64, 72, 2>(w5, dst + WP_PW2, i); break;
    case 6: prep_one<101, 32, 112, 120, 1>(w6, dst + WP_ULW, i); break;
    }
}

// ---------------- HMMA GEMM: out[nrows,128] = in[nrows,K] @ W[K,128] + b ------
template<int K>
__global__ void __launch_bounds__(256, 2) mma_gemm(
    const float* __restrict__ in, const __nv_bfloat16* __restrict__ Wp,
    const float* __restrict__ bias, float* __restrict__ out,
    int nrows, int do_relu)
{
    constexpr int CHUNK = (K < 64) ? K : 64;
    constexpr int NCH = K / CHUNK;
    constexpr int KP = CHUNK + 8;
    constexpr int TILE = 128 * KP;
    constexpr int QPR = CHUNK / 4;

    extern __shared__ __nv_bfloat16 smbf[];
    __nv_bfloat16* sAh = smbf;
    __nv_bfloat16* sAl = sAh + TILE;
    __nv_bfloat16* sBh = sAl + TILE;
    __shared__ float s_bias[128];

    const int tid = threadIdx.x;
    const int rowbase = blockIdx.x * 128;
    if (tid < 128) s_bias[tid] = bias[tid];

    int nrow_blk = nrows - rowbase; if (nrow_blk > 128) nrow_blk = 128;

    const int wid = tid >> 5;
    const int lane = tid & 31;
    const int m0 = wid * 16;
    const int lrow = lane & 15;
    const int lcol = (lane >> 4) << 3;

    float c[16][4];
#pragma unroll
    for (int nb = 0; nb < 16; nb++)
#pragma unroll
        for (int q = 0; q < 4; q++) c[nb][q] = 0.f;

    const uint32_t sAh0 = smem_u32(sAh), sAl0 = smem_u32(sAl);
    const uint32_t sBh0 = smem_u32(sBh), sBl0 = sBh0 + TILE * 2;
    const uint32_t offA = (uint32_t)((m0 + lrow) * KP + lcol) * 2;

#pragma unroll
    for (int ch = 0; ch < NCH; ch++) {
        if (ch) __syncthreads();

        const float* gin = in + (size_t)rowbase * K + ch * CHUNK;
        for (int q = tid; q < 128 * QPR; q += 256) {
            int r = q / QPR;
            int c4 = (q - r * QPR) * 4;
            float4 v = (r < nrow_blk) ? *(const float4*)(gin + (size_t)r * K + c4)
                                      : make_float4(0.f, 0.f, 0.f, 0.f);
            __nv_bfloat16 h0 = __float2bfloat16(v.x), h1 = __float2bfloat16(v.y);
            __nv_bfloat16 h2 = __float2bfloat16(v.z), h3 = __float2bfloat16(v.w);
            __nv_bfloat16 l0 = __float2bfloat16(v.x - __bfloat162float(h0));
            __nv_bfloat16 l1 = __float2bfloat16(v.y - __bfloat162float(h1));
            __nv_bfloat16 l2 = __float2bfloat16(v.z - __bfloat162float(h2));
            __nv_bfloat16 l3 = __float2bfloat16(v.w - __bfloat162float(h3));
            uint32_t* ph = (uint32_t*)(sAh + r * KP + c4);
            uint32_t* pl = (uint32_t*)(sAl + r * KP + c4);
            ph[0] = pack_bf(h0, h1); ph[1] = pack_bf(h2, h3);
            pl[0] = pack_bf(l0, l1); pl[1] = pack_bf(l2, l3);
        }
        {
            const uint4* bsrc = (const uint4*)(Wp + (size_t)ch * 2 * TILE);
            uint4* bdst = (uint4*)sBh;
            for (int i = tid; i < (2 * TILE) / 8; i += 256) bdst[i] = bsrc[i];
        }
        __syncthreads();

#pragma unroll
        for (int s = 0; s < CHUNK / 16; s++) {
            uint32_t ah[4], al[4];
            ldm_x4(ah, sAh0 + offA + s * 32);
            ldm_x4(al, sAl0 + offA + s * 32);
#pragma unroll
            for (int nbp = 0; nbp < 8; nbp++) {
                uint32_t offB = (uint32_t)((nbp * 16 + lrow) * KP + lcol) * 2 + s * 32;
                uint32_t bh[4], bl[4];
                ldm_x4(bh, sBh0 + offB);
                ldm_x4(bl, sBl0 + offB);
                mma_bf16(c[2 * nbp],     ah, bh[0], bh[2]);
                mma_bf16(c[2 * nbp],     ah, bl[0], bl[2]);
                mma_bf16(c[2 * nbp],     al, bh[0], bh[2]);
                mma_bf16(c[2 * nbp + 1], ah, bh[1], bh[3]);
                mma_bf16(c[2 * nbp + 1], ah, bl[1], bl[3]);
                mma_bf16(c[2 * nbp + 1], al, bh[1], bh[3]);
            }
        }
    }

    const int r0 = rowbase + m0 + (lane >> 2);
    const int r1 = r0 + 8;
    const int cb = (lane & 3) * 2;
#pragma unroll
    for (int nb = 0; nb < 16; nb++) {
        int col = nb * 8 + cb;
        float2 v0, v1;
        v0.x = c[nb][0] + s_bias[col];
        v0.y = c[nb][1] + s_bias[col + 1];
        v1.x = c[nb][2] + s_bias[col];
        v1.y = c[nb][3] + s_bias[col + 1];
        if (do_relu) {
            v0.x = fmaxf(v0.x, 0.f); v0.y = fmaxf(v0.y, 0.f);
            v1.x = fmaxf(v1.x, 0.f); v1.y = fmaxf(v1.y, 0.f);
        }
        if (r0 < nrows) *(float2*)(out + (size_t)r0 * 128 + col) = v0;
        if (r1 < nrows) *(float2*)(out + (size_t)r1 * 128 + col) = v1;
    }
}

// ---------------- HMMA user linear: out[nrows,32] = in[nrows,101] @ W + b -----
__global__ void __launch_bounds__(256, 2) mma_gemm101(
    const float* __restrict__ in, const __nv_bfloat16* __restrict__ Wp,
    const float* __restrict__ bias, float* __restrict__ out, int nrows)
{
    constexpr int K = 101;
    constexpr int KP = 120;
    constexpr int TILEA = 128 * KP;
    constexpr int TILEB = 32 * KP;

    extern __shared__ __nv_bfloat16 smbf[];
    __nv_bfloat16* sAh = smbf;
    __nv_bfloat16* sAl = sAh + TILEA;
    __nv_bfloat16* sBh = sAl + TILEA;
    __shared__ float s_bias[32];

    const int tid = threadIdx.x;
    const int rowbase = blockIdx.x * 128;
    if (tid < 32) s_bias[tid] = bias[tid];

    int nrow_blk = nrows - rowbase; if (nrow_blk > 128) nrow_blk = 128;

    {
        uint4* z = (uint4*)sAh;
        for (int i = tid; i < (2 * TILEA) / 8; i += 256) z[i] = make_uint4(0, 0, 0, 0);
    }
    __syncthreads();

    {
        const uint4* bsrc = (const uint4*)Wp;
        uint4* bdst = (uint4*)sBh;
        for (int i = tid; i < (2 * TILEB) / 8; i += 256) bdst[i] = bsrc[i];
    }
    const float* gin = in + (size_t)rowbase * K;
    if (rowbase + 128 <= nrows) {
        for (int q = tid; q < (128 * K) / 4; q += 256) {
            float4 v = ((const float4*)gin)[q];
            int f = q * 4;
            float vv[4] = {v.x, v.y, v.z, v.w};
#pragma unroll
            for (int e = 0; e < 4; e++) {
                int idx = f + e;
                int r = idx / K;
                int cc = idx - r * K;
                __nv_bfloat16 hi = __float2bfloat16(vv[e]);
                __nv_bfloat16 lo = __float2bfloat16(vv[e] - __bfloat162float(hi));
                sAh[r * KP + cc] = hi;
                sAl[r * KP + cc] = lo;
            }
        }
    } else {
        for (int i = tid; i < 128 * K; i += 256) {
            int r = i / K;
            int cc = i - r * K;
            float x = (r < nrow_blk) ? gin[i] : 0.f;
            __nv_bfloat16 hi = __float2bfloat16(x);
            __nv_bfloat16 lo = __float2bfloat16(x - __bfloat162float(hi));
            sAh[r * KP + cc] = hi;
            sAl[r * KP + cc] = lo;
        }
    }
    __syncthreads();

    const int wid = tid >> 5;
    const int lane = tid & 31;
    const int m0 = wid * 16;
    const int lrow = lane & 15;
    const int lcol = (lane >> 4) << 3;

    float c[4][4];
#pragma unroll
    for (int nb = 0; nb < 4; nb++)
#pragma unroll
        for (int q = 0; q < 4; q++) c[nb][q] = 0.f;

    const uint32_t sAh0 = smem_u32(sAh), sAl0 = smem_u32(sAl);
    const uint32_t sBh0 = smem_u32(sBh), sBl0 = sBh0 + TILEB * 2;
    const uint32_t offA = (uint32_t)((m0 + lrow) * KP + lcol) * 2;

#pragma unroll
    for (int s = 0; s < 7; s++) {
        uint32_t ah[4], al[4];
        ldm_x4(ah, sAh0 + offA + s * 32);
        ldm_x4(al, sAl0 + offA + s * 32);
#pragma unroll
        for (int nbp = 0; nbp < 2; nbp++) {
            uint32_t offB = (uint32_t)((nbp * 16 + lrow) * KP + lcol) * 2 + s * 32;
            uint32_t bh[4], bl[4];
            ldm_x4(bh, sBh0 + offB);
            ldm_x4(bl, sBl0 + offB);
            mma_bf16(c[2 * nbp],     ah, bh[0], bh[2]);
            mma_bf16(c[2 * nbp],     ah, bl[0], bl[2]);
            mma_bf16(c[2 * nbp],     al, bh[0], bh[2]);
            mma_bf16(c[2 * nbp + 1], ah, bh[1], bh[3]);
            mma_bf16(c[2 * nbp + 1], ah, bl[1], bl[3]);
            mma_bf16(c[2 * nbp + 1], al, bh[1], bh[3]);
        }
    }

    const int r0 = rowbase + m0 + (lane >> 2);
    const int r1 = r0 + 8;
    const int cb = (lane & 3) * 2;
#pragma unroll
    for (int nb = 0; nb < 4; nb++) {
        int col = nb * 8 + cb;
        float2 v0, v1;
        v0.x = c[nb][0] + s_bias[col];
        v0.y = c[nb][1] + s_bias[col + 1];
        v1.x = c[nb][2] + s_bias[col];
        v1.y = c[nb][3] + s_bias[col + 1];
        if (r0 < nrows) *(float2*)(out + (size_t)r0 * 32 + col) = v0;
        if (r1 < nrows) *(float2*)(out + (size_t)r1 * 32 + col) = v1;
    }
}

// ---------------- trivial item linear ----------------
__global__ void item_lin_kernel(const float* __restrict__ fx, const float* __restrict__ w,
                                const float* __restrict__ b, float* __restrict__ out, int ni)
{
    int i = blockIdx.x * blockDim.x + threadIdx.x;
    if (i < ni * 32) {
        int r = i >> 5, c = i & 31;
        out[i] = fmaf(fx[r], w[c], b[c]);
    }
}

// ---------------- CSR build ----------------
__global__ void count_kernel(const int* __restrict__ src, const int* __restrict__ dst,
                             int* __restrict__ c1, int* __restrict__ c2, int E)
{
    int i = blockIdx.x * blockDim.x + threadIdx.x;
    if (i < E) {
        atomicAdd(&c1[dst[i]], 1);
        atomicAdd(&c2[src[i]], 1);
    }
}

// ===== multi-block scan over the COMBINED degree array =====
// Segment 1 = cnt1 (indices [0, NI_MAX)), segment 2 = cnt2 ([NI_MAX, NI_MAX+Nu)).
// Sum of segment 1 == E, so segment-2 offsets are (combined_scan - E).
// 4096 elements per block (1024 threads x int4).

__global__ void scan_p1(const int* __restrict__ cnt, int* __restrict__ bsum, int ntot)
{
    __shared__ int wsum[32];
    int tid = threadIdx.x;
    int i0 = blockIdx.x * 4096 + tid * 4;
    int s = 0;
    if (i0 + 3 < ntot) {
        int4 v = *(const int4*)(cnt + i0);
        s = v.x + v.y + v.z + v.w;
    } else {
        for (int e = 0; e < 4 && i0 + e < ntot; e++) s += cnt[i0 + e];
    }
#pragma unroll
    for (int d = 16; d; d >>= 1) s += __shfl_xor_sync(0xffffffffu, s, d);
    if ((tid & 31) == 0) wsum[tid >> 5] = s;
    __syncthreads();
    if (tid < 32) {
        int w = wsum[tid];
#pragma unroll
        for (int d = 16; d; d >>= 1) w += __shfl_xor_sync(0xffffffffu, w, d);
        if (tid == 0) bsum[blockIdx.x] = w;
    }
}

__global__ void scan_p2(int* __restrict__ bsum, int nblk)
{
    int tid = threadIdx.x;   // 64 threads
    int v = (tid < nblk) ? bsum[tid] : 0;
    int x = v;
#pragma unroll
    for (int d = 1; d < 32; d <<= 1) {
        int y = __shfl_up_sync(0xffffffffu, x, d);
        if ((tid & 31) >= d) x += y;
    }
    __shared__ int w0;
    if (tid == 31) w0 = x;
    __syncthreads();
    int excl = x - v + ((tid >= 32) ? w0 : 0);
    if (tid < nblk) bsum[tid] = excl;
}

__global__ void scan_p3(const int* __restrict__ cnt, const int* __restrict__ bsum,
                        int2* __restrict__ offcnt, int* __restrict__ cur,
                        int ntot, int seg2_start, int E)
{
    __shared__ int wsum[32];
    int tid = threadIdx.x;
    int i0 = blockIdx.x * 4096 + tid * 4;
    int4 v = make_int4(0, 0, 0, 0);
    if (i0 + 3 < ntot) v = *(const int4*)(cnt + i0);
    else {
        if (i0 < ntot)     v.x = cnt[i0];
        if (i0 + 1 < ntot) v.y = cnt[i0 + 1];
        if (i0 + 2 < ntot) v.z = cnt[i0 + 2];
    }
    int tsum = v.x + v.y + v.z + v.w;
    int x = tsum;
#pragma unroll
    for (int d = 1; d < 32; d <<= 1) {
        int y = __shfl_up_sync(0xffffffffu, x, d);
        if ((tid & 31) >= d) x += y;
    }
    if ((tid & 31) == 31) wsum[tid >> 5] = x;
    __syncthreads();
    if (tid < 32) {
        int w = wsum[tid];
#pragma unroll
        for (int d = 1; d < 32; d <<= 1) {
            int y = __shfl_up_sync(0xffffffffu, w, d);
            if (tid >= d) w += y;
        }
        wsum[tid] = w;
    }
    __syncthreads();
    int wo = (tid >= 32) ? wsum[(tid >> 5) - 1] : 0;
    int excl = bsum[blockIdx.x] + wo + x - tsum;

    int e0 = excl, e1 = e0 + v.x, e2 = e1 + v.y, e3 = e2 + v.z;
    int off4[4] = {e0, e1, e2, e3};
    int cnt4[4] = {v.x, v.y, v.z, v.w};
#pragma unroll
    for (int e = 0; e < 4; e++) {
        int i = i0 + e;
        if (i < ntot) {
            int o = off4[e] - ((i >= seg2_start) ? E : 0);
            offcnt[i] = make_int2(o, cnt4[e]);
            cur[i] = o;
        }
    }
}

__global__ void scatter_kernel(const int* __restrict__ src, const int* __restrict__ dst,
                               const float* __restrict__ eattr,
                               int* __restrict__ cur1, int* __restrict__ cur2,
                               int* __restrict__ oth1, int* __restrict__ oth2,
                               float4* __restrict__ ea1, int E)
{
    int i = blockIdx.x * blockDim.x + threadIdx.x;
    if (i < E) {
        int s = src[i], d = dst[i];
        int p1 = atomicAdd(&cur1[d], 1);
        oth1[p1] = s;
        float a0 = eattr[(size_t)i * 3];
        float a1 = eattr[(size_t)i * 3 + 1];
        float a2 = eattr[(size_t)i * 3 + 2];
        ea1[p1] = make_float4(a0, a1, a2, 0.f);
        int p2 = atomicAdd(&cur2[s], 1);
        oth2[p2] = d;
    }
}

// ---------------- fused GATv2 conv: online softmax + aggregation --------------
struct Chain { float M, S; float4 A; };

__device__ __forceinline__ void chain_update(Chain& ch, float t, const float4& xs)
{
    float Mn = fmaxf(ch.M, t);
    float corr = __expf(ch.M - Mn);
    float p = __expf(t - Mn);
    ch.S = ch.S * corr + p;
    ch.A.x = fmaf(ch.A.x, corr, p * xs.x);
    ch.A.y = fmaf(ch.A.y, corr, p * xs.y);
    ch.A.z = fmaf(ch.A.z, corr, p * xs.z);
    ch.A.w = fmaf(ch.A.w, corr, p * xs.w);
    ch.M = Mn;
}

__global__ void gat_conv_kernel(
    const float* __restrict__ xl, const float* __restrict__ xr,
    const int2* __restrict__ offcnt,
    const int* __restrict__ other,
    const float4* __restrict__ ea,
    const float* __restrict__ we,
    const float* __restrict__ att,
    const float* __restrict__ bias, float* __restrict__ out,
    int n, int do_relu)
{
    __shared__ int    s_o[8][32];
    __shared__ float4 s_ea[8][32];

    const int lane = threadIdx.x & 31;
    const int wrp = threadIdx.x >> 5;
    const int node = blockIdx.x * 8 + wrp;
    if (node >= n) return;

    float4 att4 = ((const float4*)att)[lane];
    float4 bias4 = ((const float4*)bias)[lane];
    int2 oc = __ldg(offcnt + node);
    const int start = oc.x;
    const int m = oc.y;

    if (m == 0) {
        float4 o = bias4;
        if (do_relu) {
            o.x = fmaxf(o.x, 0.f); o.y = fmaxf(o.y, 0.f);
            o.z = fmaxf(o.z, 0.f); o.w = fmaxf(o.w, 0.f);
        }
        ((float4*)(out + (size_t)node * 128))[lane] = o;
        return;
    }

    float4 we0 = make_float4(0, 0, 0, 0), we1 = we0, we2 = we0;
    if (we) {
        we0 = ((const float4*)we)[lane];
        we1 = ((const float4*)(we + 128))[lane];
        we2 = ((const float4*)(we + 256))[lane];
    }
    float4 xr4 = __ldg((const float4*)(xr + (size_t)node * 128) + lane);

    const float NEGINF = __int_as_float(0xff800000u);
    Chain c0, c1;
    c0.M = NEGINF; c0.S = 0.f; c0.A = make_float4(0.f, 0.f, 0.f, 0.f);
    c1 = c0;

    for (int base = 0; base < m; base += 32) {
        int i = base + lane;
        if (i < m) {
            s_o[wrp][lane] = __ldg(other + start + i);
            if (ea) s_ea[wrp][lane] = __ldg(ea + start + i);
        }
        __syncwarp();
        int lim = m - base; if (lim > 32) lim = 32;
        for (int j = 0; j < lim; j++) {
            int srcn = s_o[wrp][j];
            float4 xs = __ldg((const float4*)(xl + (size_t)srcn * 128) + lane);
            float4 m4;
            m4.x = xs.x + xr4.x; m4.y = xs.y + xr4.y;
            m4.z = xs.z + xr4.z; m4.w = xs.w + xr4.w;
            if (ea) {
                float4 e = s_ea[wrp][j];
                m4.x = fmaf(e.x, we0.x, fmaf(e.y, we1.x, fmaf(e.z, we2.x, m4.x)));
                m4.y = fmaf(e.x, we0.y, fmaf(e.y, we1.y, fmaf(e.z, we2.y, m4.y)));
                m4.z = fmaf(e.x, we0.z, fmaf(e.y, we1.z, fmaf(e.z, we2.z, m4.z)));
                m4.w = fmaf(e.x, we0.w, fmaf(e.y, we1.w, fmaf(e.z, we2.w, m4.w)));
            }
            float g0 = fmaxf(m4.x, 0.2f * m4.x);
            float g1 = fmaxf(m4.y, 0.2f * m4.y);
            float g2 = fmaxf(m4.z, 0.2f * m4.z);
            float g3 = fmaxf(m4.w, 0.2f * m4.w);
            float t = g0 * att4.x + g1 * att4.y + g2 * att4.z + g3 * att4.w;
            t += __shfl_xor_sync(0xffffffffu, t, 1);
            t += __shfl_xor_sync(0xffffffffu, t, 2);
            t += __shfl_xor_sync(0xffffffffu, t, 4);
            if (j & 1) chain_update(c1, t, xs);
            else       chain_update(c0, t, xs);
        }
        __syncwarp();
    }

    float Mn = fmaxf(c0.M, c1.M);
    float w0 = __expf(c0.M - Mn), w1 = __expf(c1.M - Mn);
    float ssum = c0.S * w0 + c1.S * w1;
    float4 a;
    a.x = c0.A.x * w0 + c1.A.x * w1;
    a.y = c0.A.y * w0 + c1.A.y * w1;
    a.z = c0.A.z * w0 + c1.A.z * w1;
    a.w = c0.A.w * w0 + c1.A.w * w1;

    float inv = 1.f / (ssum + 1e-16f);
    float4 o;
    o.x = fmaf(a.x, inv, bias4.x);
    o.y = fmaf(a.y, inv, bias4.y);
    o.z = fmaf(a.z, inv, bias4.z);
    o.w = fmaf(a.w, inv, bias4.w);
    if (do_relu) {
        o.x = fmaxf(o.x, 0.f); o.y = fmaxf(o.y, 0.f);
        o.z = fmaxf(o.z, 0.f); o.w = fmaxf(o.w, 0.f);
    }
    ((float4*)(out + (size_t)node * 128))[lane] = o;
}

// ---------------- host launch ----------------
extern "C" void kernel_launch(void* const* d_in, const int* in_sizes, int n_in,
                              void* d_out, int out_size)
{
    (void)n_in; (void)out_size;
    const float* customer_x = (const float*)d_in[0];
    const float* fund_x     = (const float*)d_in[1];
    const float* edge_attr  = (const float*)d_in[2];
    const float* user_lin_w = (const float*)d_in[3];
    const float* user_lin_b = (const float*)d_in[4];
    const float* item_lin_w = (const float*)d_in[5];
    const float* item_lin_b = (const float*)d_in[6];
    const float* conv1_wl   = (const float*)d_in[7];
    const float* conv1_bl   = (const float*)d_in[8];
    const float* conv1_wr   = (const float*)d_in[9];
    const float* conv1_br   = (const float*)d_in[10];
    const float* conv1_we   = (const float*)d_in[11];
    const float* conv1_att  = (const float*)d_in[12];
    const float* conv1_bias = (const float*)d_in[13];
    const float* conv2_wl   = (const float*)d_in[14];
    const float* conv2_bl   = (const float*)d_in[15];
    const float* conv2_wr   = (const float*)d_in[16];
    const float* conv2_br   = (const float*)d_in[17];
    const float* conv2_att  = (const float*)d_in[18];
    const float* conv2_bias = (const float*)d_in[19];
    const float* proj_w1    = (const float*)d_in[20];
    const float* proj_b1    = (const float*)d_in[21];
    const float* proj_w2    = (const float*)d_in[22];
    const float* proj_b2    = (const float*)d_in[23];
    const int*   edge_src   = (const int*)d_in[24];
    const int*   edge_dst   = (const int*)d_in[25];

    const int Nu = in_sizes[0] / 101;
    const int Ni = in_sizes[1];
    const int E  = in_sizes[24];

    float *user_x, *item_x, *xl1, *xr1, *xr2, *item2, *xl2, *hid;
    int *deg, *cur, *oth1, *oth2, *bsum;
    int2* offcnt;
    float4* ea1;
    __nv_bfloat16* wp;
    cudaGetSymbolAddress((void**)&user_x, g_user_x);
    cudaGetSymbolAddress((void**)&item_x, g_item_x);
    cudaGetSymbolAddress((void**)&xl1,    g_xl1);
    cudaGetSymbolAddress((void**)&xr1,    g_xr1);
    cudaGetSymbolAddress((void**)&xr2,    g_xr2);
    cudaGetSymbolAddress((void**)&item2,  g_item2);
    cudaGetSymbolAddress((void**)&xl2,    g_xl2);
    cudaGetSymbolAddress((void**)&hid,    g_hid);
    cudaGetSymbolAddress((void**)&deg,    g_deg);
    cudaGetSymbolAddress((void**)&offcnt, g_offcnt);
    cudaGetSymbolAddress((void**)&cur,    g_cur);
    cudaGetSymbolAddress((void**)&bsum,   g_bsum);
    cudaGetSymbolAddress((void**)&oth1,   g_oth1);
    cudaGetSymbolAddress((void**)&oth2,   g_oth2);
    cudaGetSymbolAddress((void**)&ea1,    g_ea1);
    cudaGetSymbolAddress((void**)&wp,     g_wpack);

    int  *cnt1 = deg, *cnt2 = deg + NI_MAX;
    int2 *oc1 = offcnt, *oc2 = offcnt + NI_MAX;
    int  *cur1 = cur, *cur2 = cur + NI_MAX;

    const int smemMM32  = 4 * 128 * 40 * 2;
    const int smemMM128 = 4 * 128 * 72 * 2;
    const int smemMM101 = (2 * 128 * 120 + 2 * 32 * 120) * 2;
    cudaFuncSetAttribute(mma_gemm<32>,  cudaFuncAttributeMaxDynamicSharedMemorySize, smemMM32);
    cudaFuncSetAttribute(mma_gemm<128>, cudaFuncAttributeMaxDynamicSharedMemorySize, smemMM128);
    cudaFuncSetAttribute(mma_gemm101,   cudaFuncAttributeMaxDynamicSharedMemorySize, smemMM101);

    float* user_out = (float*)d_out;             // [Nu,128]
    float* z        = user_out + (size_t)Nu * 128;

    const int ntot = NI_MAX + Nu;
    const int nblk = (ntot + 4095) / 4096;

    // fork/join streams (handles created per call, never destroyed -> graph-safe)
    cudaStream_t s1;
    cudaStreamCreateWithFlags(&s1, cudaStreamNonBlocking);
    cudaEvent_t eFork, eJoin;
    cudaEventCreateWithFlags(&eFork, cudaEventDisableTiming);
    cudaEventCreateWithFlags(&eJoin, cudaEventDisableTiming);

    // main: weight prepack
    prepack_kernel<<<dim3(144, 7), 256>>>(conv1_wl, conv2_wr, conv1_wr,
                                          conv2_wl, proj_w1, proj_w2,
                                          user_lin_w, wp);
    // fork side stream
    cudaEventRecord(eFork, 0);
    cudaStreamWaitEvent(s1, eFork, 0);

    // side: CSR build (multi-block scan)
    cudaMemsetAsync(deg, 0, (size_t)ntot * sizeof(int), s1);
    count_kernel<<<(E + 255) / 256, 256, 0, s1>>>(edge_src, edge_dst, cnt1, cnt2, E);
    // main: user linear (HMMA)
    mma_gemm101<<<(Nu + 127) / 128, 256, smemMM101>>>(customer_x, wp + WP_ULW, user_lin_b, user_x, Nu);
    // side: hierarchical scan
    scan_p1<<<nblk, 1024, 0, s1>>>(deg, bsum, ntot);
    scan_p2<<<1, 64, 0, s1>>>(bsum, nblk);
    scan_p3<<<nblk, 1024, 0, s1>>>(deg, bsum, offcnt, cur, ntot, NI_MAX, E);
    // main: projections
    mma_gemm<32><<<(Nu + 127) / 128, 256, smemMM32>>>(user_x, wp + WP_C1WL, conv1_bl, xl1, Nu, 0);
    item_lin_kernel<<<(Ni * 32 + 255) / 256, 256>>>(fund_x, item_lin_w, item_lin_b, item_x, Ni);
    // side
    scatter_kernel<<<(E + 255) / 256, 256, 0, s1>>>(edge_src, edge_dst, edge_attr,
                                                    cur1, cur2, oth1, oth2, ea1, E);
    // main
    mma_gemm<32><<<(Nu + 127) / 128, 256, smemMM32>>>(user_x, wp + WP_C2WR, conv2_br, xr2, Nu, 0);
    mma_gemm<32><<<(Ni + 127) / 128, 256, smemMM32>>>(item_x, wp + WP_C1WR, conv1_br, xr1, Ni, 0);

    // join
    cudaEventRecord(eJoin, s1);
    cudaStreamWaitEvent(0, eJoin, 0);

    // conv1: user -> item
    gat_conv_kernel<<<(Ni + 7) / 8, 256>>>(xl1, xr1, oc1, oth1, ea1, conv1_we,
                                           conv1_att, conv1_bias, item2, Ni, 1);
    // conv2: item -> user
    mma_gemm<128><<<(Ni + 127) / 128, 256, smemMM128>>>(item2, wp + WP_C2WL, conv2_bl, xl2, Ni, 0);
    gat_conv_kernel<<<(Nu + 7) / 8, 256>>>(xl2, xr2, oc2, oth2, nullptr, nullptr,
                                           conv2_att, conv2_bias, user_out, Nu, 0);
    // final MLP
    mma_gemm<128><<<(Nu + 127) / 128, 256, smemMM128>>>(user_out, wp + WP_PW1, proj_b1, hid, Nu, 1);
    mma_gemm<128><<<(Nu + 127) / 128, 256, smemMM128>>>(hid, wp + WP_PW2, proj_b2, z, Nu, 0);
}

// round 11
// speedup vs baseline: 3.0998x; 1.0475x over previous
#include <cuda_runtime.h>
#include <cuda_bf16.h>
#include <cstdint>

#define NU_MAX 200000
#define NI_MAX 20000
#define NE_MAX 1000000

// ---------------- scratch (device globals; no allocation allowed) -------------
__device__ float  g_user_x[NU_MAX * 32];
__device__ float  g_item_x[NI_MAX * 32];
__device__ float  g_xl1[NU_MAX * 128];
__device__ float  g_xr1[NI_MAX * 128];
__device__ float  g_xr2[NU_MAX * 128];
__device__ float  g_item2[NI_MAX * 128];
__device__ float  g_xl2[NI_MAX * 128];
__device__ int    g_deg[NI_MAX + NU_MAX];
__device__ int2   g_offcnt[NI_MAX + NU_MAX];
__device__ int    g_cur[NI_MAX + NU_MAX];
__device__ int    g_bsum[64];
__device__ int    g_oth1[NE_MAX];
__device__ int    g_oth2[NE_MAX];
__device__ float4 g_ea1[NE_MAX];
__device__ __align__(16) __nv_bfloat16 g_wpack[150000];

// packed-weight offsets (bf16 elements)
#define WP_C1WL 0
#define WP_C2WR 10240
#define WP_C1WR 20480
#define WP_C2WL 30720
#define WP_PW1  67584
#define WP_PW2  104448
#define WP_ULW  141312

// ================= helpers =================
__device__ __forceinline__ uint32_t smem_u32(const void* p) {
    uint32_t a;
    asm("{ .reg .u64 t; cvta.to.shared.u64 t, %1; cvt.u32.u64 %0, t; }" : "=r"(a) : "l"(p));
    return a;
}
__device__ __forceinline__ void ldm_x4(uint32_t* r, uint32_t addr) {
    asm volatile("ldmatrix.sync.aligned.m8n8.x4.shared.b16 {%0,%1,%2,%3}, [%4];"
                 : "=r"(r[0]), "=r"(r[1]), "=r"(r[2]), "=r"(r[3]) : "r"(addr));
}
__device__ __forceinline__ void mma_bf16(float* c, const uint32_t* a, uint32_t b0, uint32_t b1) {
    asm volatile("mma.sync.aligned.m16n8k16.row.col.f32.bf16.bf16.f32 "
                 "{%0,%1,%2,%3}, {%4,%5,%6,%7}, {%8,%9}, {%0,%1,%2,%3};"
                 : "+f"(c[0]), "+f"(c[1]), "+f"(c[2]), "+f"(c[3])
                 : "r"(a[0]), "r"(a[1]), "r"(a[2]), "r"(a[3]), "r"(b0), "r"(b1));
}
__device__ __forceinline__ uint32_t pack_bf(__nv_bfloat16 a, __nv_bfloat16 b) {
    return (uint32_t)__bfloat16_as_ushort(a) | ((uint32_t)__bfloat16_as_ushort(b) << 16);
}

// ---------------- weight prepack: fp32 W[K,NOUT] -> hi/lo bf16 tiles ----------
template<int K, int NOUT, int CHUNK, int KP, int NCH>
__device__ __forceinline__ void prep_one(const float* __restrict__ W,
                                         __nv_bfloat16* __restrict__ dst, int i)
{
    constexpr int TOT = NCH * 2 * NOUT * KP;
    if (i >= TOT) return;
    int ch = i / (2 * NOUT * KP);
    int r = i - ch * (2 * NOUT * KP);
    int half = r / (NOUT * KP);
    int q = r - half * (NOUT * KP);
    int n = q / KP;
    int kloc = q - n * KP;
    int k = ch * CHUNK + kloc;
    float v = (kloc < CHUNK && k < K) ? W[k * NOUT + n] : 0.f;
    __nv_bfloat16 hi = __float2bfloat16(v);
    dst[i] = half ? __float2bfloat16(v - __bfloat162float(hi)) : hi;
}

__global__ void prepack_kernel(const float* w0, const float* w1, const float* w2,
                               const float* w3, const float* w4, const float* w5,
                               const float* w6, __nv_bfloat16* dst)
{
    int i = blockIdx.x * 256 + threadIdx.x;
    switch (blockIdx.y) {
    case 0: prep_one<32, 128, 32, 40, 1>(w0, dst + WP_C1WL, i); break;
    case 1: prep_one<32, 128, 32, 40, 1>(w1, dst + WP_C2WR, i); break;
    case 2: prep_one<32, 128, 32, 40, 1>(w2, dst + WP_C1WR, i); break;
    case 3: prep_one<128, 128, 64, 72, 2>(w3, dst + WP_C2WL, i); break;
    case 4: prep_one<128, 128, 64, 72, 2>(w4, dst + WP_PW1, i); break;
    case 5: prep_one<128, 128, 64, 72, 2>(w5, dst + WP_PW2, i); break;
    case 6: prep_one<101, 32, 112, 120, 1>(w6, dst + WP_ULW, i); break;
    }
}

// ---- shared device subroutines for HMMA blocks ----
// A fill: 128 rows x CHUNK cols from fp32 `gin` (row stride K) into hi/lo tiles.
template<int K, int CHUNK, int KP>
__device__ __forceinline__ void fill_A(const float* __restrict__ gin, int nrow_blk,
                                       __nv_bfloat16* sAh, __nv_bfloat16* sAl, int tid)
{
    constexpr int QPR = CHUNK / 4;
    for (int q = tid; q < 128 * QPR; q += 256) {
        int r = q / QPR;
        int c4 = (q - r * QPR) * 4;
        float4 v = (r < nrow_blk) ? *(const float4*)(gin + (size_t)r * K + c4)
                                  : make_float4(0.f, 0.f, 0.f, 0.f);
        __nv_bfloat16 h0 = __float2bfloat16(v.x), h1 = __float2bfloat16(v.y);
        __nv_bfloat16 h2 = __float2bfloat16(v.z), h3 = __float2bfloat16(v.w);
        __nv_bfloat16 l0 = __float2bfloat16(v.x - __bfloat162float(h0));
        __nv_bfloat16 l1 = __float2bfloat16(v.y - __bfloat162float(h1));
        __nv_bfloat16 l2 = __float2bfloat16(v.z - __bfloat162float(h2));
        __nv_bfloat16 l3 = __float2bfloat16(v.w - __bfloat162float(h3));
        uint32_t* ph = (uint32_t*)(sAh + r * KP + c4);
        uint32_t* pl = (uint32_t*)(sAl + r * KP + c4);
        ph[0] = pack_bf(h0, h1); ph[1] = pack_bf(h2, h3);
        pl[0] = pack_bf(l0, l1); pl[1] = pack_bf(l2, l3);
    }
}

// 3-term split mainloop over one chunk: c += A(hi/lo) x B(hi/lo)
template<int KP, int NB>
__device__ __forceinline__ void mma_chunk(float c[][4], uint32_t sAh0, uint32_t sAl0,
                                          uint32_t sBh0, uint32_t sBl0,
                                          uint32_t offA, int lrow, int lcol, int ksteps)
{
    for (int s = 0; s < ksteps; s++) {
        uint32_t ah[4], al[4];
        ldm_x4(ah, sAh0 + offA + s * 32);
        ldm_x4(al, sAl0 + offA + s * 32);
#pragma unroll
        for (int nbp = 0; nbp < NB; nbp++) {
            uint32_t offB = (uint32_t)((nbp * 16 + lrow) * KP + lcol) * 2 + s * 32;
            uint32_t bh[4], bl[4];
            ldm_x4(bh, sBh0 + offB);
            ldm_x4(bl, sBl0 + offB);
            mma_bf16(c[2 * nbp],     ah, bh[0], bh[2]);
            mma_bf16(c[2 * nbp],     ah, bl[0], bl[2]);
            mma_bf16(c[2 * nbp],     al, bh[0], bh[2]);
            mma_bf16(c[2 * nbp + 1], ah, bh[1], bh[3]);
            mma_bf16(c[2 * nbp + 1], ah, bl[1], bl[3]);
            mma_bf16(c[2 * nbp + 1], al, bh[1], bh[3]);
        }
    }
}

// ---------------- HMMA GEMM: out[nrows,128] = in[nrows,K] @ W[K,128] + b ------
template<int K>
__global__ void __launch_bounds__(256, 2) mma_gemm(
    const float* __restrict__ in, const __nv_bfloat16* __restrict__ Wp,
    const float* __restrict__ bias, float* __restrict__ out,
    int nrows, int do_relu)
{
    constexpr int CHUNK = (K < 64) ? K : 64;
    constexpr int NCH = K / CHUNK;
    constexpr int KP = CHUNK + 8;
    constexpr int TILE = 128 * KP;

    extern __shared__ __nv_bfloat16 smbf[];
    __nv_bfloat16* sAh = smbf;
    __nv_bfloat16* sAl = sAh + TILE;
    __nv_bfloat16* sBh = sAl + TILE;
    __shared__ float s_bias[128];

    const int tid = threadIdx.x;
    const int rowbase = blockIdx.x * 128;
    if (tid < 128) s_bias[tid] = bias[tid];
    int nrow_blk = nrows - rowbase; if (nrow_blk > 128) nrow_blk = 128;

    const int wid = tid >> 5;
    const int lane = tid & 31;
    const int m0 = wid * 16;
    const int lrow = lane & 15;
    const int lcol = (lane >> 4) << 3;

    float c[16][4];
#pragma unroll
    for (int nb = 0; nb < 16; nb++)
#pragma unroll
        for (int q = 0; q < 4; q++) c[nb][q] = 0.f;

    const uint32_t sAh0 = smem_u32(sAh), sAl0 = smem_u32(sAl);
    const uint32_t sBh0 = smem_u32(sBh), sBl0 = sBh0 + TILE * 2;
    const uint32_t offA = (uint32_t)((m0 + lrow) * KP + lcol) * 2;

#pragma unroll
    for (int ch = 0; ch < NCH; ch++) {
        if (ch) __syncthreads();
        fill_A<K, CHUNK, KP>(in + (size_t)rowbase * K + ch * CHUNK, nrow_blk, sAh, sAl, tid);
        {
            const uint4* bsrc = (const uint4*)(Wp + (size_t)ch * 2 * TILE);
            uint4* bdst = (uint4*)sBh;
            for (int i = tid; i < (2 * TILE) / 8; i += 256) bdst[i] = bsrc[i];
        }
        __syncthreads();
        mma_chunk<KP, 8>(c, sAh0, sAl0, sBh0, sBl0, offA, lrow, lcol, CHUNK / 16);
    }

    const int r0 = rowbase + m0 + (lane >> 2);
    const int r1 = r0 + 8;
    const int cb = (lane & 3) * 2;
#pragma unroll
    for (int nb = 0; nb < 16; nb++) {
        int col = nb * 8 + cb;
        float2 v0, v1;
        v0.x = c[nb][0] + s_bias[col];
        v0.y = c[nb][1] + s_bias[col + 1];
        v1.x = c[nb][2] + s_bias[col];
        v1.y = c[nb][3] + s_bias[col + 1];
        if (do_relu) {
            v0.x = fmaxf(v0.x, 0.f); v0.y = fmaxf(v0.y, 0.f);
            v1.x = fmaxf(v1.x, 0.f); v1.y = fmaxf(v1.y, 0.f);
        }
        if (r0 < nrows) *(float2*)(out + (size_t)r0 * 128 + col) = v0;
        if (r1 < nrows) *(float2*)(out + (size_t)r1 * 128 + col) = v1;
    }
}

// ---------------- dual-output K=32 GEMM: shares A tile for two weights --------
__global__ void __launch_bounds__(256, 2) mma_gemm32_dual(
    const float* __restrict__ in,
    const __nv_bfloat16* __restrict__ Wp1, const float* __restrict__ b1, float* __restrict__ out1,
    const __nv_bfloat16* __restrict__ Wp2, const float* __restrict__ b2, float* __restrict__ out2,
    int nrows)
{
    constexpr int K = 32, KP = 40, TILE = 128 * KP;

    extern __shared__ __nv_bfloat16 smbf[];
    __nv_bfloat16* sAh = smbf;
    __nv_bfloat16* sAl = sAh + TILE;
    __nv_bfloat16* sBh = sAl + TILE;
    __shared__ float s_b1[128], s_b2[128];

    const int tid = threadIdx.x;
    const int rowbase = blockIdx.x * 128;
    if (tid < 128) { s_b1[tid] = b1[tid]; s_b2[tid] = b2[tid]; }
    int nrow_blk = nrows - rowbase; if (nrow_blk > 128) nrow_blk = 128;

    const int wid = tid >> 5;
    const int lane = tid & 31;
    const int m0 = wid * 16;
    const int lrow = lane & 15;
    const int lcol = (lane >> 4) << 3;

    const uint32_t sAh0 = smem_u32(sAh), sAl0 = smem_u32(sAl);
    const uint32_t sBh0 = smem_u32(sBh), sBl0 = sBh0 + TILE * 2;
    const uint32_t offA = (uint32_t)((m0 + lrow) * KP + lcol) * 2;

    fill_A<K, K, KP>(in + (size_t)rowbase * K, nrow_blk, sAh, sAl, tid);
    {
        const uint4* bsrc = (const uint4*)Wp1;
        uint4* bdst = (uint4*)sBh;
        for (int i = tid; i < (2 * TILE) / 8; i += 256) bdst[i] = bsrc[i];
    }
    __syncthreads();

    const int r0 = rowbase + m0 + (lane >> 2);
    const int r1 = r0 + 8;
    const int cb = (lane & 3) * 2;

    float c[16][4];
#pragma unroll
    for (int nb = 0; nb < 16; nb++)
#pragma unroll
        for (int q = 0; q < 4; q++) c[nb][q] = 0.f;
    mma_chunk<KP, 8>(c, sAh0, sAl0, sBh0, sBl0, offA, lrow, lcol, 2);

#pragma unroll
    for (int nb = 0; nb < 16; nb++) {
        int col = nb * 8 + cb;
        float2 v0, v1;
        v0.x = c[nb][0] + s_b1[col];
        v0.y = c[nb][1] + s_b1[col + 1];
        v1.x = c[nb][2] + s_b1[col];
        v1.y = c[nb][3] + s_b1[col + 1];
        if (r0 < nrows) *(float2*)(out1 + (size_t)r0 * 128 + col) = v0;
        if (r1 < nrows) *(float2*)(out1 + (size_t)r1 * 128 + col) = v1;
    }

    __syncthreads();   // B reads done before overwrite
    {
        const uint4* bsrc = (const uint4*)Wp2;
        uint4* bdst = (uint4*)sBh;
        for (int i = tid; i < (2 * TILE) / 8; i += 256) bdst[i] = bsrc[i];
    }
    __syncthreads();

#pragma unroll
    for (int nb = 0; nb < 16; nb++)
#pragma unroll
        for (int q = 0; q < 4; q++) c[nb][q] = 0.f;
    mma_chunk<KP, 8>(c, sAh0, sAl0, sBh0, sBl0, offA, lrow, lcol, 2);

#pragma unroll
    for (int nb = 0; nb < 16; nb++) {
        int col = nb * 8 + cb;
        float2 v0, v1;
        v0.x = c[nb][0] + s_b2[col];
        v0.y = c[nb][1] + s_b2[col + 1];
        v1.x = c[nb][2] + s_b2[col];
        v1.y = c[nb][3] + s_b2[col + 1];
        if (r0 < nrows) *(float2*)(out2 + (size_t)r0 * 128 + col) = v0;
        if (r1 < nrows) *(float2*)(out2 + (size_t)r1 * 128 + col) = v1;
    }
}

// ---------------- fused 2-layer MLP: z = relu(in@W1+b1)@W2+b2 ----------------
// Stage-1 accumulators are converted to hi/lo bf16 smem tiles in-block; no hid
// round trip through global memory.
__global__ void __launch_bounds__(256, 2) mlp_fused(
    const float* __restrict__ in,
    const __nv_bfloat16* __restrict__ W1p, const float* __restrict__ b1,
    const __nv_bfloat16* __restrict__ W2p, const float* __restrict__ b2,
    float* __restrict__ z, int nrows)
{
    constexpr int K = 128, CHUNK = 64, KP = 72, TILE = 128 * KP;
    // smem elems: [0,T) Ah/Hh0, [T,2T) Al/Hl0, [2T,4T) B1/Hh1+Hl1, [4T,6T) B2
    extern __shared__ __nv_bfloat16 smbf[];
    __nv_bfloat16* sAh = smbf;
    __nv_bfloat16* sAl = sAh + TILE;
    __nv_bfloat16* sBh = sAl + TILE;          // stage1 B (hi+lo)
    __nv_bfloat16* sB2 = smbf + 4 * TILE;     // stage2 B (hi+lo)
    __shared__ float s_b1[128], s_b2[128];

    const int tid = threadIdx.x;
    const int rowbase = blockIdx.x * 128;
    if (tid < 128) { s_b1[tid] = b1[tid]; s_b2[tid] = b2[tid]; }
    int nrow_blk = nrows - rowbase; if (nrow_blk > 128) nrow_blk = 128;

    const int wid = tid >> 5;
    const int lane = tid & 31;
    const int m0 = wid * 16;
    const int lrow = lane & 15;
    const int lcol = (lane >> 4) << 3;

    float c[16][4];
#pragma unroll
    for (int nb = 0; nb < 16; nb++)
#pragma unroll
        for (int q = 0; q < 4; q++) c[nb][q] = 0.f;

    const uint32_t sAh0 = smem_u32(sAh), sAl0 = smem_u32(sAl);
    const uint32_t sBh0 = smem_u32(sBh), sBl0 = sBh0 + TILE * 2;
    const uint32_t sB2h0 = smem_u32(sB2), sB2l0 = sB2h0 + TILE * 2;
    const uint32_t offA = (uint32_t)((m0 + lrow) * KP + lcol) * 2;

    // ---- stage 1: hid = relu(in@W1 + b1) ----
#pragma unroll
    for (int ch = 0; ch < 2; ch++) {
        if (ch) __syncthreads();
        fill_A<K, CHUNK, KP>(in + (size_t)rowbase * K + ch * CHUNK, nrow_blk, sAh, sAl, tid);
        {
            const uint4* bsrc = (const uint4*)(W1p + (size_t)ch * 2 * TILE);
            uint4* bdst = (uint4*)sBh;
            for (int i = tid; i < (2 * TILE) / 8; i += 256) bdst[i] = bsrc[i];
        }
        __syncthreads();
        mma_chunk<KP, 8>(c, sAh0, sAl0, sBh0, sBl0, offA, lrow, lcol, 4);
    }
    __syncthreads();   // all stage-1 smem reads done before H-tile overwrite

    // ---- convert hid rows (in registers) to hi/lo bf16 H tiles ----
    // H layout: chunk ch hi at smbf + ch*2*TILE, lo at smbf + ch*2*TILE + TILE
    {
        const int rr0 = m0 + (lane >> 2);
        const int rr1 = rr0 + 8;
        const int cb = (lane & 3) * 2;
#pragma unroll
        for (int nb = 0; nb < 16; nb++) {
            int col = nb * 8 + cb;
            int ch = col >> 6;
            int kloc = col & 63;
            float v0 = fmaxf(c[nb][0] + s_b1[col], 0.f);
            float v1 = fmaxf(c[nb][1] + s_b1[col + 1], 0.f);
            float v2 = fmaxf(c[nb][2] + s_b1[col], 0.f);
            float v3 = fmaxf(c[nb][3] + s_b1[col + 1], 0.f);
            __nv_bfloat16 h0 = __float2bfloat16(v0), h1 = __float2bfloat16(v1);
            __nv_bfloat16 h2 = __float2bfloat16(v2), h3 = __float2bfloat16(v3);
            __nv_bfloat16 l0 = __float2bfloat16(v0 - __bfloat162float(h0));
            __nv_bfloat16 l1 = __float2bfloat16(v1 - __bfloat162float(h1));
            __nv_bfloat16 l2 = __float2bfloat16(v2 - __bfloat162float(h2));
            __nv_bfloat16 l3 = __float2bfloat16(v3 - __bfloat162float(h3));
            __nv_bfloat16* Hh = smbf + ch * 2 * TILE;
            __nv_bfloat16* Hl = Hh + TILE;
            *(uint32_t*)(Hh + rr0 * KP + kloc) = pack_bf(h0, h1);
            *(uint32_t*)(Hl + rr0 * KP + kloc) = pack_bf(l0, l1);
            *(uint32_t*)(Hh + rr1 * KP + kloc) = pack_bf(h2, h3);
            *(uint32_t*)(Hl + rr1 * KP + kloc) = pack_bf(l2, l3);
        }
    }
    __syncthreads();

    // ---- stage 2: z = hid@W2 + b2 ----
#pragma unroll
    for (int nb = 0; nb < 16; nb++)
#pragma unroll
        for (int q = 0; q < 4; q++) c[nb][q] = 0.f;

#pragma unroll
    for (int ch = 0; ch < 2; ch++) {
        if (ch) __syncthreads();
        {
            const uint4* bsrc = (const uint4*)(W2p + (size_t)ch * 2 * TILE);
            uint4* bdst = (uint4*)sB2;
            for (int i = tid; i < (2 * TILE) / 8; i += 256) bdst[i] = bsrc[i];
        }
        __syncthreads();
        uint32_t Hh0 = smem_u32(smbf + ch * 2 * TILE);
        uint32_t Hl0 = Hh0 + TILE * 2;
        mma_chunk<KP, 8>(c, Hh0, Hl0, sB2h0, sB2l0, offA, lrow, lcol, 4);
    }

    const int r0 = rowbase + m0 + (lane >> 2);
    const int r1 = r0 + 8;
    const int cb = (lane & 3) * 2;
#pragma unroll
    for (int nb = 0; nb < 16; nb++) {
        int col = nb * 8 + cb;
        float2 v0, v1;
        v0.x = c[nb][0] + s_b2[col];
        v0.y = c[nb][1] + s_b2[col + 1];
        v1.x = c[nb][2] + s_b2[col];
        v1.y = c[nb][3] + s_b2[col + 1];
        if (r0 < nrows) *(float2*)(z + (size_t)r0 * 128 + col) = v0;
        if (r1 < nrows) *(float2*)(z + (size_t)r1 * 128 + col) = v1;
    }
}

// ---------------- HMMA user linear: out[nrows,32] = in[nrows,101] @ W + b -----
__global__ void __launch_bounds__(256, 2) mma_gemm101(
    const float* __restrict__ in, const __nv_bfloat16* __restrict__ Wp,
    const float* __restrict__ bias, float* __restrict__ out, int nrows)
{
    constexpr int K = 101;
    constexpr int KP = 120;
    constexpr int TILEA = 128 * KP;
    constexpr int TILEB = 32 * KP;

    extern __shared__ __nv_bfloat16 smbf[];
    __nv_bfloat16* sAh = smbf;
    __nv_bfloat16* sAl = sAh + TILEA;
    __nv_bfloat16* sBh = sAl + TILEA;
    __shared__ float s_bias[32];

    const int tid = threadIdx.x;
    const int rowbase = blockIdx.x * 128;
    if (tid < 32) s_bias[tid] = bias[tid];
    int nrow_blk = nrows - rowbase; if (nrow_blk > 128) nrow_blk = 128;

    {
        uint4* zz = (uint4*)sAh;
        for (int i = tid; i < (2 * TILEA) / 8; i += 256) zz[i] = make_uint4(0, 0, 0, 0);
    }
    __syncthreads();
    {
        const uint4* bsrc = (const uint4*)Wp;
        uint4* bdst = (uint4*)sBh;
        for (int i = tid; i < (2 * TILEB) / 8; i += 256) bdst[i] = bsrc[i];
    }
    const float* gin = in + (size_t)rowbase * K;
    if (rowbase + 128 <= nrows) {
        for (int q = tid; q < (128 * K) / 4; q += 256) {
            float4 v = ((const float4*)gin)[q];
            int f = q * 4;
            float vv[4] = {v.x, v.y, v.z, v.w};
#pragma unroll
            for (int e = 0; e < 4; e++) {
                int idx = f + e;
                int r = idx / K;
                int cc = idx - r * K;
                __nv_bfloat16 hi = __float2bfloat16(vv[e]);
                __nv_bfloat16 lo = __float2bfloat16(vv[e] - __bfloat162float(hi));
                sAh[r * KP + cc] = hi;
                sAl[r * KP + cc] = lo;
            }
        }
    } else {
        for (int i = tid; i < 128 * K; i += 256) {
            int r = i / K;
            int cc = i - r * K;
            float x = (r < nrow_blk) ? gin[i] : 0.f;
            __nv_bfloat16 hi = __float2bfloat16(x);
            __nv_bfloat16 lo = __float2bfloat16(x - __bfloat162float(hi));
            sAh[r * KP + cc] = hi;
            sAl[r * KP + cc] = lo;
        }
    }
    __syncthreads();

    const int wid = tid >> 5;
    const int lane = tid & 31;
    const int m0 = wid * 16;
    const int lrow = lane & 15;
    const int lcol = (lane >> 4) << 3;

    float c[4][4];
#pragma unroll
    for (int nb = 0; nb < 4; nb++)
#pragma unroll
        for (int q = 0; q < 4; q++) c[nb][q] = 0.f;

    const uint32_t sAh0 = smem_u32(sAh), sAl0 = smem_u32(sAl);
    const uint32_t sBh0 = smem_u32(sBh), sBl0 = sBh0 + TILEB * 2;
    const uint32_t offA = (uint32_t)((m0 + lrow) * KP + lcol) * 2;

#pragma unroll
    for (int s = 0; s < 7; s++) {
        uint32_t ah[4], al[4];
        ldm_x4(ah, sAh0 + offA + s * 32);
        ldm_x4(al, sAl0 + offA + s * 32);
#pragma unroll
        for (int nbp = 0; nbp < 2; nbp++) {
            uint32_t offB = (uint32_t)((nbp * 16 + lrow) * KP + lcol) * 2 + s * 32;
            uint32_t bh[4], bl[4];
            ldm_x4(bh, sBh0 + offB);
            ldm_x4(bl, sBl0 + offB);
            mma_bf16(c[2 * nbp],     ah, bh[0], bh[2]);
            mma_bf16(c[2 * nbp],     ah, bl[0], bl[2]);
            mma_bf16(c[2 * nbp],     al, bh[0], bh[2]);
            mma_bf16(c[2 * nbp + 1], ah, bh[1], bh[3]);
            mma_bf16(c[2 * nbp + 1], ah, bl[1], bl[3]);
            mma_bf16(c[2 * nbp + 1], al, bh[1], bh[3]);
        }
    }

    const int r0 = rowbase + m0 + (lane >> 2);
    const int r1 = r0 + 8;
    const int cb = (lane & 3) * 2;
#pragma unroll
    for (int nb = 0; nb < 4; nb++) {
        int col = nb * 8 + cb;
        float2 v0, v1;
        v0.x = c[nb][0] + s_bias[col];
        v0.y = c[nb][1] + s_bias[col + 1];
        v1.x = c[nb][2] + s_bias[col];
        v1.y = c[nb][3] + s_bias[col + 1];
        if (r0 < nrows) *(float2*)(out + (size_t)r0 * 32 + col) = v0;
        if (r1 < nrows) *(float2*)(out + (size_t)r1 * 32 + col) = v1;
    }
}

// ---------------- trivial item linear ----------------
__global__ void item_lin_kernel(const float* __restrict__ fx, const float* __restrict__ w,
                                const float* __restrict__ b, float* __restrict__ out, int ni)
{
    int i = blockIdx.x * blockDim.x + threadIdx.x;
    if (i < ni * 32) {
        int r = i >> 5, c = i & 31;
        out[i] = fmaf(fx[r], w[c], b[c]);
    }
}

// ---------------- CSR build ----------------
__global__ void count_kernel(const int* __restrict__ src, const int* __restrict__ dst,
                             int* __restrict__ c1, int* __restrict__ c2, int E)
{
    int i = blockIdx.x * blockDim.x + threadIdx.x;
    if (i < E) {
        atomicAdd(&c1[dst[i]], 1);
        atomicAdd(&c2[src[i]], 1);
    }
}

__global__ void scan_p1(const int* __restrict__ cnt, int* __restrict__ bsum, int ntot)
{
    __shared__ int wsum[32];
    int tid = threadIdx.x;
    int i0 = blockIdx.x * 4096 + tid * 4;
    int s = 0;
    if (i0 + 3 < ntot) {
        int4 v = *(const int4*)(cnt + i0);
        s = v.x + v.y + v.z + v.w;
    } else {
        for (int e = 0; e < 4 && i0 + e < ntot; e++) s += cnt[i0 + e];
    }
#pragma unroll
    for (int d = 16; d; d >>= 1) s += __shfl_xor_sync(0xffffffffu, s, d);
    if ((tid & 31) == 0) wsum[tid >> 5] = s;
    __syncthreads();
    if (tid < 32) {
        int w = wsum[tid];
#pragma unroll
        for (int d = 16; d; d >>= 1) w += __shfl_xor_sync(0xffffffffu, w, d);
        if (tid == 0) bsum[blockIdx.x] = w;
    }
}

__global__ void scan_p2(int* __restrict__ bsum, int nblk)
{
    int tid = threadIdx.x;   // 64 threads
    int v = (tid < nblk) ? bsum[tid] : 0;
    int x = v;
#pragma unroll
    for (int d = 1; d < 32; d <<= 1) {
        int y = __shfl_up_sync(0xffffffffu, x, d);
        if ((tid & 31) >= d) x += y;
    }
    __shared__ int w0;
    if (tid == 31) w0 = x;
    __syncthreads();
    int excl = x - v + ((tid >= 32) ? w0 : 0);
    if (tid < nblk) bsum[tid] = excl;
}

__global__ void scan_p3(const int* __restrict__ cnt, const int* __restrict__ bsum,
                        int2* __restrict__ offcnt, int* __restrict__ cur,
                        int ntot, int seg2_start, int E)
{
    __shared__ int wsum[32];
    int tid = threadIdx.x;
    int i0 = blockIdx.x * 4096 + tid * 4;
    int4 v = make_int4(0, 0, 0, 0);
    if (i0 + 3 < ntot) v = *(const int4*)(cnt + i0);
    else {
        if (i0 < ntot)     v.x = cnt[i0];
        if (i0 + 1 < ntot) v.y = cnt[i0 + 1];
        if (i0 + 2 < ntot) v.z = cnt[i0 + 2];
    }
    int tsum = v.x + v.y + v.z + v.w;
    int x = tsum;
#pragma unroll
    for (int d = 1; d < 32; d <<= 1) {
        int y = __shfl_up_sync(0xffffffffu, x, d);
        if ((tid & 31) >= d) x += y;
    }
    if ((tid & 31) == 31) wsum[tid >> 5] = x;
    __syncthreads();
    if (tid < 32) {
        int w = wsum[tid];
#pragma unroll
        for (int d = 1; d < 32; d <<= 1) {
            int y = __shfl_up_sync(0xffffffffu, w, d);
            if (tid >= d) w += y;
        }
        wsum[tid] = w;
    }
    __syncthreads();
    int wo = (tid >= 32) ? wsum[(tid >> 5) - 1] : 0;
    int excl = bsum[blockIdx.x] + wo + x - tsum;

    int e0 = excl, e1 = e0 + v.x, e2 = e1 + v.y, e3 = e2 + v.z;
    int off4[4] = {e0, e1, e2, e3};
    int cnt4[4] = {v.x, v.y, v.z, v.w};
#pragma unroll
    for (int e = 0; e < 4; e++) {
        int i = i0 + e;
        if (i < ntot) {
            int o = off4[e] - ((i >= seg2_start) ? E : 0);
            offcnt[i] = make_int2(o, cnt4[e]);
            cur[i] = o;
        }
    }
}

__global__ void scatter_kernel(const int* __restrict__ src, const int* __restrict__ dst,
                               const float* __restrict__ eattr,
                               int* __restrict__ cur1, int* __restrict__ cur2,
                               int* __restrict__ oth1, int* __restrict__ oth2,
                               float4* __restrict__ ea1, int E)
{
    int i = blockIdx.x * blockDim.x + threadIdx.x;
    if (i < E) {
        int s = src[i], d = dst[i];
        int p1 = atomicAdd(&cur1[d], 1);
        oth1[p1] = s;
        float a0 = eattr[(size_t)i * 3];
        float a1 = eattr[(size_t)i * 3 + 1];
        float a2 = eattr[(size_t)i * 3 + 2];
        ea1[p1] = make_float4(a0, a1, a2, 0.f);
        int p2 = atomicAdd(&cur2[s], 1);
        oth2[p2] = d;
    }
}

// ---------------- fused GATv2 conv: online softmax + aggregation --------------
struct Chain { float M, S; float4 A; };

__device__ __forceinline__ void chain_update(Chain& ch, float t, const float4& xs)
{
    float Mn = fmaxf(ch.M, t);
    float corr = __expf(ch.M - Mn);
    float p = __expf(t - Mn);
    ch.S = ch.S * corr + p;
    ch.A.x = fmaf(ch.A.x, corr, p * xs.x);
    ch.A.y = fmaf(ch.A.y, corr, p * xs.y);
    ch.A.z = fmaf(ch.A.z, corr, p * xs.z);
    ch.A.w = fmaf(ch.A.w, corr, p * xs.w);
    ch.M = Mn;
}

__global__ void gat_conv_kernel(
    const float* __restrict__ xl, const float* __restrict__ xr,
    const int2* __restrict__ offcnt,
    const int* __restrict__ other,
    const float4* __restrict__ ea,
    const float* __restrict__ we,
    const float* __restrict__ att,
    const float* __restrict__ bias, float* __restrict__ out,
    int n, int do_relu)
{
    __shared__ int    s_o[8][32];
    __shared__ float4 s_ea[8][32];

    const int lane = threadIdx.x & 31;
    const int wrp = threadIdx.x >> 5;
    const int node = blockIdx.x * 8 + wrp;
    if (node >= n) return;

    float4 att4 = ((const float4*)att)[lane];
    float4 bias4 = ((const float4*)bias)[lane];
    int2 oc = __ldg(offcnt + node);
    const int start = oc.x;
    const int m = oc.y;

    if (m == 0) {
        float4 o = bias4;
        if (do_relu) {
            o.x = fmaxf(o.x, 0.f); o.y = fmaxf(o.y, 0.f);
            o.z = fmaxf(o.z, 0.f); o.w = fmaxf(o.w, 0.f);
        }
        ((float4*)(out + (size_t)node * 128))[lane] = o;
        return;
    }

    float4 we0 = make_float4(0, 0, 0, 0), we1 = we0, we2 = we0;
    if (we) {
        we0 = ((const float4*)we)[lane];
        we1 = ((const float4*)(we + 128))[lane];
        we2 = ((const float4*)(we + 256))[lane];
    }
    float4 xr4 = __ldg((const float4*)(xr + (size_t)node * 128) + lane);

    const float NEGINF = __int_as_float(0xff800000u);
    Chain c0, c1;
    c0.M = NEGINF; c0.S = 0.f; c0.A = make_float4(0.f, 0.f, 0.f, 0.f);
    c1 = c0;

    for (int base = 0; base < m; base += 32) {
        int i = base + lane;
        if (i < m) {
            s_o[wrp][lane] = __ldg(other + start + i);
            if (ea) s_ea[wrp][lane] = __ldg(ea + start + i);
        }
        __syncwarp();
        int lim = m - base; if (lim > 32) lim = 32;
        for (int j = 0; j < lim; j++) {
            int srcn = s_o[wrp][j];
            float4 xs = __ldg((const float4*)(xl + (size_t)srcn * 128) + lane);
            float4 m4;
            m4.x = xs.x + xr4.x; m4.y = xs.y + xr4.y;
            m4.z = xs.z + xr4.z; m4.w = xs.w + xr4.w;
            if (ea) {
                float4 e = s_ea[wrp][j];
                m4.x = fmaf(e.x, we0.x, fmaf(e.y, we1.x, fmaf(e.z, we2.x, m4.x)));
                m4.y = fmaf(e.x, we0.y, fmaf(e.y, we1.y, fmaf(e.z, we2.y, m4.y)));
                m4.z = fmaf(e.x, we0.z, fmaf(e.y, we1.z, fmaf(e.z, we2.z, m4.z)));
                m4.w = fmaf(e.x, we0.w, fmaf(e.y, we1.w, fmaf(e.z, we2.w, m4.w)));
            }
            float g0 = fmaxf(m4.x, 0.2f * m4.x);
            float g1 = fmaxf(m4.y, 0.2f * m4.y);
            float g2 = fmaxf(m4.z, 0.2f * m4.z);
            float g3 = fmaxf(m4.w, 0.2f * m4.w);
            float t = g0 * att4.x + g1 * att4.y + g2 * att4.z + g3 * att4.w;
            t += __shfl_xor_sync(0xffffffffu, t, 1);
            t += __shfl_xor_sync(0xffffffffu, t, 2);
            t += __shfl_xor_sync(0xffffffffu, t, 4);
            if (j & 1) chain_update(c1, t, xs);
            else       chain_update(c0, t, xs);
        }
        __syncwarp();
    }

    float Mn = fmaxf(c0.M, c1.M);
    float w0 = __expf(c0.M - Mn), w1 = __expf(c1.M - Mn);
    float ssum = c0.S * w0 + c1.S * w1;
    float4 a;
    a.x = c0.A.x * w0 + c1.A.x * w1;
    a.y = c0.A.y * w0 + c1.A.y * w1;
    a.z = c0.A.z * w0 + c1.A.z * w1;
    a.w = c0.A.w * w0 + c1.A.w * w1;

    float inv = 1.f / (ssum + 1e-16f);
    float4 o;
    o.x = fmaf(a.x, inv, bias4.x);
    o.y = fmaf(a.y, inv, bias4.y);
    o.z = fmaf(a.z, inv, bias4.z);
    o.w = fmaf(a.w, inv, bias4.w);
    if (do_relu) {
        o.x = fmaxf(o.x, 0.f); o.y = fmaxf(o.y, 0.f);
        o.z = fmaxf(o.z, 0.f); o.w = fmaxf(o.w, 0.f);
    }
    ((float4*)(out + (size_t)node * 128))[lane] = o;
}

// ---------------- host launch ----------------
extern "C" void kernel_launch(void* const* d_in, const int* in_sizes, int n_in,
                              void* d_out, int out_size)
{
    (void)n_in; (void)out_size;
    const float* customer_x = (const float*)d_in[0];
    const float* fund_x     = (const float*)d_in[1];
    const float* edge_attr  = (const float*)d_in[2];
    const float* user_lin_w = (const float*)d_in[3];
    const float* user_lin_b = (const float*)d_in[4];
    const float* item_lin_w = (const float*)d_in[5];
    const float* item_lin_b = (const float*)d_in[6];
    const float* conv1_wl   = (const float*)d_in[7];
    const float* conv1_bl   = (const float*)d_in[8];
    const float* conv1_wr   = (const float*)d_in[9];
    const float* conv1_br   = (const float*)d_in[10];
    const float* conv1_we   = (const float*)d_in[11];
    const float* conv1_att  = (const float*)d_in[12];
    const float* conv1_bias = (const float*)d_in[13];
    const float* conv2_wl   = (const float*)d_in[14];
    const float* conv2_bl   = (const float*)d_in[15];
    const float* conv2_wr   = (const float*)d_in[16];
    const float* conv2_br   = (const float*)d_in[17];
    const float* conv2_att  = (const float*)d_in[18];
    const float* conv2_bias = (const float*)d_in[19];
    const float* proj_w1    = (const float*)d_in[20];
    const float* proj_b1    = (const float*)d_in[21];
    const float* proj_w2    = (const float*)d_in[22];
    const float* proj_b2    = (const float*)d_in[23];
    const int*   edge_src   = (const int*)d_in[24];
    const int*   edge_dst   = (const int*)d_in[25];

    const int Nu = in_sizes[0] / 101;
    const int Ni = in_sizes[1];
    const int E  = in_sizes[24];

    float *user_x, *item_x, *xl1, *xr1, *xr2, *item2, *xl2;
    int *deg, *cur, *oth1, *oth2, *bsum;
    int2* offcnt;
    float4* ea1;
    __nv_bfloat16* wp;
    cudaGetSymbolAddress((void**)&user_x, g_user_x);
    cudaGetSymbolAddress((void**)&item_x, g_item_x);
    cudaGetSymbolAddress((void**)&xl1,    g_xl1);
    cudaGetSymbolAddress((void**)&xr1,    g_xr1);
    cudaGetSymbolAddress((void**)&xr2,    g_xr2);
    cudaGetSymbolAddress((void**)&item2,  g_item2);
    cudaGetSymbolAddress((void**)&xl2,    g_xl2);
    cudaGetSymbolAddress((void**)&deg,    g_deg);
    cudaGetSymbolAddress((void**)&offcnt, g_offcnt);
    cudaGetSymbolAddress((void**)&cur,    g_cur);
    cudaGetSymbolAddress((void**)&bsum,   g_bsum);
    cudaGetSymbolAddress((void**)&oth1,   g_oth1);
    cudaGetSymbolAddress((void**)&oth2,   g_oth2);
    cudaGetSymbolAddress((void**)&ea1,    g_ea1);
    cudaGetSymbolAddress((void**)&wp,     g_wpack);

    int  *cnt1 = deg, *cnt2 = deg + NI_MAX;
    int2 *oc1 = offcnt, *oc2 = offcnt + NI_MAX;
    int  *cur1 = cur, *cur2 = cur + NI_MAX;

    const int smemMM32   = 4 * 128 * 40 * 2;                   // 40960
    const int smemMM128  = 4 * 128 * 72 * 2;                   // 73728
    const int smemMM101  = (2 * 128 * 120 + 2 * 32 * 120) * 2; // 76800
    const int smemFused  = 6 * 128 * 72 * 2;                   // 110592
    cudaFuncSetAttribute(mma_gemm<32>,   cudaFuncAttributeMaxDynamicSharedMemorySize, smemMM32);
    cudaFuncSetAttribute(mma_gemm32_dual,cudaFuncAttributeMaxDynamicSharedMemorySize, smemMM32);
    cudaFuncSetAttribute(mma_gemm<128>,  cudaFuncAttributeMaxDynamicSharedMemorySize, smemMM128);
    cudaFuncSetAttribute(mma_gemm101,    cudaFuncAttributeMaxDynamicSharedMemorySize, smemMM101);
    cudaFuncSetAttribute(mlp_fused,      cudaFuncAttributeMaxDynamicSharedMemorySize, smemFused);

    float* user_out = (float*)d_out;             // [Nu,128]
    float* z        = user_out + (size_t)Nu * 128;

    const int ntot = NI_MAX + Nu;
    const int nblk = (ntot + 4095) / 4096;

    cudaStream_t s1;
    cudaStreamCreateWithFlags(&s1, cudaStreamNonBlocking);
    cudaEvent_t eFork, eJoin;
    cudaEventCreateWithFlags(&eFork, cudaEventDisableTiming);
    cudaEventCreateWithFlags(&eJoin, cudaEventDisableTiming);

    // main: weight prepack
    prepack_kernel<<<dim3(144, 7), 256>>>(conv1_wl, conv2_wr, conv1_wr,
                                          conv2_wl, proj_w1, proj_w2,
                                          user_lin_w, wp);
    cudaEventRecord(eFork, 0);
    cudaStreamWaitEvent(s1, eFork, 0);

    // side: CSR build
    cudaMemsetAsync(deg, 0, (size_t)ntot * sizeof(int), s1);
    count_kernel<<<(E + 255) / 256, 256, 0, s1>>>(edge_src, edge_dst, cnt1, cnt2, E);
    // main: user linear
    mma_gemm101<<<(Nu + 127) / 128, 256, smemMM101>>>(customer_x, wp + WP_ULW, user_lin_b, user_x, Nu);
    // side: hierarchical scan
    scan_p1<<<nblk, 1024, 0, s1>>>(deg, bsum, ntot);
    scan_p2<<<1, 64, 0, s1>>>(bsum, nblk);
    scan_p3<<<nblk, 1024, 0, s1>>>(deg, bsum, offcnt, cur, ntot, NI_MAX, E);
    // main: dual projection (xl1 + xr2 share user_x A tiles)
    mma_gemm32_dual<<<(Nu + 127) / 128, 256, smemMM32>>>(user_x,
                                                         wp + WP_C1WL, conv1_bl, xl1,
                                                         wp + WP_C2WR, conv2_br, xr2, Nu);
    item_lin_kernel<<<(Ni * 32 + 255) / 256, 256>>>(fund_x, item_lin_w, item_lin_b, item_x, Ni);
    // side
    scatter_kernel<<<(E + 255) / 256, 256, 0, s1>>>(edge_src, edge_dst, edge_attr,
                                                    cur1, cur2, oth1, oth2, ea1, E);
    // main
    mma_gemm<32><<<(Ni + 127) / 128, 256, smemMM32>>>(item_x, wp + WP_C1WR, conv1_br, xr1, Ni, 0);

    // join
    cudaEventRecord(eJoin, s1);
    cudaStreamWaitEvent(0, eJoin, 0);

    // conv1: user -> item
    gat_conv_kernel<<<(Ni + 7) / 8, 256>>>(xl1, xr1, oc1, oth1, ea1, conv1_we,
                                           conv1_att, conv1_bias, item2, Ni, 1);
    // conv2: item -> user
    mma_gemm<128><<<(Ni + 127) / 128, 256, smemMM128>>>(item2, wp + WP_C2WL, conv2_bl, xl2, Ni, 0);
    gat_conv_kernel<<<(Nu + 7) / 8, 256>>>(xl2, xr2, oc2, oth2, nullptr, nullptr,
                                           conv2_att, conv2_bias, user_out, Nu, 0);
    // final MLP (fused, no hid round trip)
    mlp_fused<<<(Nu + 127) / 128, 256, smemFused>>>(user_out, wp + WP_PW1, proj_b1,
                                                    wp + WP_PW2, proj_b2, z, Nu);
}